// round 9
// baseline (speedup 1.0000x reference)
#include <cuda_runtime.h>
#include <cuda_fp16.h>
#include <cstdint>

// ---------------------------------------------------------------------------
// AffinityHead — mma.sync fp16x3 split GEMM core, SW128-swizzled smem,
// 512-thread CTA, 32x32 warp tiles. Per-atom tail optimized: vectorized
// octet builds (LDS.128/STS.128), warp0-only reduction overlapped with the
// next atom's M-tile build, 2 barriers/atom.
// ---------------------------------------------------------------------------

__device__ __forceinline__ float silu_f(float v) { return v / (1.f + __expf(-v)); }

// ------------------------- scratch (static, no allocs) ---------------------
__device__ float g_tok[4 * 128 * 128];     // [n][j][h]
__device__ float g_S1[4 * 64 * 27];
__device__ float g_S0[4 * 32 * 27];
__device__ float g_p[4 * 256];
__device__ float g_pf[4 * 128];
__device__ float g_atoms[4 * 1024 * 128];  // [n][i][k]
__device__ float g_atom_e[4 * 1024];

// ------------------------------ PTX helpers --------------------------------
__device__ __forceinline__ uint32_t smem_to_u32(const void* p) {
    uint32_t a;
    asm("{ .reg .u64 t; cvta.to.shared.u64 t, %1; cvt.u32.u64 %0, t; }" : "=r"(a) : "l"(p));
    return a;
}

__device__ __forceinline__ void ldsm_x4(uint32_t* r, uint32_t addr) {
    asm volatile("ldmatrix.sync.aligned.m8n8.x4.shared.b16 {%0,%1,%2,%3}, [%4];"
                 : "=r"(r[0]), "=r"(r[1]), "=r"(r[2]), "=r"(r[3]) : "r"(addr));
}

__device__ __forceinline__ void mma_f16(float* d, const uint32_t* a, const uint32_t* b) {
    asm volatile(
        "mma.sync.aligned.m16n8k16.row.col.f32.f16.f16.f32 "
        "{%0,%1,%2,%3}, {%4,%5,%6,%7}, {%8,%9}, {%0,%1,%2,%3};"
        : "+f"(d[0]), "+f"(d[1]), "+f"(d[2]), "+f"(d[3])
        : "r"(a[0]), "r"(a[1]), "r"(a[2]), "r"(a[3]), "r"(b[0]), "r"(b[1]));
}

// SW128 blocked-atom swizzled byte offset for a [128 rows][128 halves] plane.
__device__ __forceinline__ uint32_t swz(int row, int k) {
    uint32_t off = (uint32_t)(((k >> 6) << 14) + ((row >> 3) << 10) +
                              ((row & 7) << 7) + ((k & 63) << 1));
    return off ^ (uint32_t)((row & 7) << 4);
}

// ------------------------------ k_tok --------------------------------------
__global__ void k_tok(const float* __restrict__ tf, const float* __restrict__ Wt,
                      const float* __restrict__ bt) {
    int row = blockIdx.x;
    int t = threadIdx.x;
    __shared__ float s[256];
    const float* x = tf + row * 256;
    for (int c = t; c < 256; c += 128) s[c] = silu_f(x[c]);
    __syncthreads();
    float acc = bt[t];
#pragma unroll 8
    for (int c = 0; c < 256; c++) acc += s[c] * Wt[c * 128 + t];
    g_tok[row * 128 + t] = acc;
}

// ------------------------------ k_S1 ----------------------------------------
__global__ void k_S1(const float* __restrict__ x) {
    int nc = blockIdx.x;
    int t = threadIdx.x;
    __shared__ float v[512];
    for (int i = t; i < 512; i += 128) v[i] = silu_f(x[nc * 512 + i]);
    __syncthreads();
    if (t < 27) {
        int kd = t / 9, kh = (t / 3) % 3, kw = t % 3;
        float s = 0.f;
        for (int d = 0; d < 6; d++)
            for (int h = 0; h < 6; h++)
                for (int w = 0; w < 6; w++)
                    s += v[(d + kd) * 64 + (h + kh) * 8 + (w + kw)];
        g_S1[nc * 27 + t] = s;
    }
}

// ------------------------------ k_S0 ----------------------------------------
__global__ void k_S0(const float* __restrict__ x) {
    int nc = blockIdx.x;
    int t = threadIdx.x;
    __shared__ float v[4096];
    __shared__ float rbuf[8];
    for (int i = t; i < 4096; i += 256) v[i] = silu_f(x[nc * 4096 + i]);
    __syncthreads();
    for (int k = 0; k < 27; k++) {
        int kd = k / 9, kh = (k / 3) % 3, kw = k % 3;
        float s = 0.f;
        for (int p = t; p < 2744; p += 256) {
            int d = p / 196;
            int r = p % 196;
            int hh = r / 14, ww = r % 14;
            s += v[(d + kd) * 256 + (hh + kh) * 16 + (ww + kw)];
        }
        for (int off = 16; off > 0; off >>= 1) s += __shfl_down_sync(0xffffffffu, s, off);
        if ((t & 31) == 0) rbuf[t >> 5] = s;
        __syncthreads();
        if (t == 0) {
            float tot = 0.f;
            for (int w = 0; w < 8; w++) tot += rbuf[w];
            g_S0[nc * 27 + k] = tot;
        }
        __syncthreads();
    }
}

// ------------------------------ k_pconv (warp-per-output) -------------------
__global__ void k_pconv(const float* __restrict__ Wc0, const float* __restrict__ bc0,
                        const float* __restrict__ Wc1, const float* __restrict__ bc1) {
    int b = blockIdx.x, t = threadIdx.x;   // 64 blocks x 256 threads
    int n = b >> 4, og = b & 15;
    __shared__ float s1[1728];
    __shared__ float s0[864];
    for (int i = t; i < 1728; i += 256) s1[i] = g_S1[n * 1728 + i];
    for (int i = t; i < 864; i += 256) s0[i] = g_S0[n * 864 + i];
    __syncthreads();
    int w = t >> 5, lane = t & 31;
    int o = og * 8 + w;
    float a0 = 0.f;
    for (int x = lane; x < 1728; x += 32) a0 += s1[x] * Wc0[o * 1728 + x];
    float a1 = 0.f;
    for (int x = lane; x < 864; x += 32) a1 += s0[x] * Wc1[o * 864 + x];
#pragma unroll
    for (int off = 16; off > 0; off >>= 1) {
        a0 += __shfl_down_sync(0xffffffffu, a0, off);
        a1 += __shfl_down_sync(0xffffffffu, a1, off);
    }
    if (lane == 0) {
        g_p[n * 256 + o] = a0 * (1.f / 216.f) + bc0[o];
        g_p[n * 256 + 128 + o] = a1 * (1.f / 2744.f) + bc1[o];
    }
}

// ------------------------------ k_pf ----------------------------------------
__global__ void k_pf(const float* __restrict__ Wp, const float* __restrict__ bp,
                     const float* __restrict__ Wcat, const float* __restrict__ bcat,
                     const float* __restrict__ Wgate, const float* __restrict__ bgate) {
    int n = blockIdx.x, t = threadIdx.x;
    __shared__ float sp[256];
    __shared__ float pin[384];
    for (int c = t; c < 256; c += 128) sp[c] = silu_f(g_p[n * 256 + c]);
    float ts = 0.f;
    for (int j = 0; j < 128; j++) ts += g_tok[(n * 128 + j) * 128 + t];
    __syncthreads();
    float pk = bp[t];
#pragma unroll 4
    for (int c = 0; c < 256; c++) pk += sp[c] * Wp[c * 128 + t];
    pin[t] = pk;
    pin[128 + t] = ts;
    pin[256 + t] = ts * (1.f / 128.f);
    __syncthreads();
    float c1 = bcat[t], g1 = bgate[t];
#pragma unroll 4
    for (int c = 0; c < 384; c++) {
        float z = pin[c];
        c1 += z * Wcat[c * 128 + t];
        g1 += z * Wgate[c * 128 + t];
    }
    g_pf[n * 128 + t] = c1 / (1.f + __expf(-g1));
}

// ------------------------------ k_atoms -------------------------------------
__global__ void k_atoms(const float* __restrict__ la, const float* __restrict__ Wa,
                        const float* __restrict__ ba) {
    int r0 = blockIdx.x * 8;
    int t = threadIdx.x;
    __shared__ float s[8][64];
    for (int i = t; i < 512; i += 128) s[i >> 6][i & 63] = la[r0 * 64 + i];
    __syncthreads();
    float b = ba[t];
    float acc[8];
#pragma unroll
    for (int r = 0; r < 8; r++) acc[r] = b;
    for (int c = 0; c < 64; c++) {
        float w = Wa[c * 128 + t];
#pragma unroll
        for (int r = 0; r < 8; r++) acc[r] += s[r][c] * w;
    }
#pragma unroll
    for (int r = 0; r < 8; r++) g_atoms[(r0 + r) * 128 + t] = acc[r];
}

// ------------------------------ k_inter -------------------------------------
#define SA_HI 0
#define SA_LO 32768
#define SM_HI 65536
#define SM_LO 98304
#define SWT 131072            // W^T fp32 [128][132] : 67584
#define SCV 198656            // wpe|wpg|bi : 1536
#define SPE 200192            // peb/pgb [4][128] each : 4096
#define SRED 204288           // 64
#define SSAV 204352           // 512
#define SMEM_TC_BYTES 204928

#define SCALE_A 16.f
#define SCALE_B 256.f
#define SCALE_INV (1.f / 4096.f)

// Build one octet (8 k-values at one h) of M = diag(sav)*W into hi/lo planes.
__device__ __forceinline__ void build_oct(char* smc, const float* __restrict__ WfT,
                                          const float* __restrict__ sav, int p) {
    const int h = p >> 4, k0 = (p & 15) << 3;
    const float4* wp = (const float4*)(WfT + h * 132 + k0);
    const float4 w0 = wp[0], w1 = wp[1];
    const float4* ap = (const float4*)(sav + k0);
    const float4 a0 = ap[0], a1 = ap[1];
    float v[8];
    v[0] = a0.x * w0.x; v[1] = a0.y * w0.y; v[2] = a0.z * w0.z; v[3] = a0.w * w0.w;
    v[4] = a1.x * w1.x; v[5] = a1.y * w1.y; v[6] = a1.z * w1.z; v[7] = a1.w * w1.w;
    uint32_t hi[4], lo[4];
#pragma unroll
    for (int q = 0; q < 4; q++) {
        __half2 hh = __float22half2_rn(make_float2(v[2 * q], v[2 * q + 1]));
        __half2 ll = __float22half2_rn(make_float2(v[2 * q] - __low2float(hh),
                                                   v[2 * q + 1] - __high2float(hh)));
        hi[q] = *(uint32_t*)&hh;
        lo[q] = *(uint32_t*)&ll;
    }
    const uint32_t o = swz(h, k0);
    *(uint4*)(smc + SM_HI + o) = make_uint4(hi[0], hi[1], hi[2], hi[3]);
    *(uint4*)(smc + SM_LO + o) = make_uint4(lo[0], lo[1], lo[2], lo[3]);
}

__global__ void __launch_bounds__(512, 1)
k_inter(const float* __restrict__ Wi, const float* __restrict__ bi,
        const float* __restrict__ wpe, const float* __restrict__ bpe,
        const float* __restrict__ wpg, const float* __restrict__ bpg) {
    extern __shared__ char smc[];
    const uint32_t sb = smem_to_u32(smc);
    float* WfT = (float*)(smc + SWT);
    float* cv = (float*)(smc + SCV);
    float* peb = (float*)(smc + SPE);        // [4][128]
    float* pgb = peb + 512;                  // [4][128]
    float* sav = (float*)(smc + SSAV);       // [128], pre-scaled by SCALE_B

    const int t = threadIdx.x;
    const int wid = t >> 5;
    const int lane = t & 31;

    const int n = blockIdx.x / 37;
    const int grp = blockIdx.x % 37;
    const int i0 = grp * 28;
    const int cnt = min(28, 1024 - i0);
    const float* atomBase = g_atoms + (n * 1024 + i0) * 128;
    const float bpe0 = bpe[0], bpg0 = bpg[0];

    // ---- phase 1: stage W^T, constants, sav(0) ----
    for (int idx = t; idx < 16384; idx += 512) {
        int k = idx >> 7, h = idx & 127;
        WfT[h * 132 + k] = Wi[idx];
    }
    if (t < 128) {
        cv[t] = wpe[t];
        cv[128 + t] = wpg[t];
        cv[256 + t] = bi[t];
        sav[t] = atomBase[t] * SCALE_B;
    }
    __syncthreads();

    // ---- phase 2: A planes (octet form) + M(0) planes ----
    const float* tokn = g_tok + n * 16384;
    for (int p = t; p < 2048; p += 512) {
        int j = p >> 4, k0 = (p & 15) << 3;
        const float4* xp = (const float4*)(tokn + j * 128 + k0);
        float4 x0 = xp[0], x1 = xp[1];
        float v[8];
        v[0] = x0.x * SCALE_A; v[1] = x0.y * SCALE_A;
        v[2] = x0.z * SCALE_A; v[3] = x0.w * SCALE_A;
        v[4] = x1.x * SCALE_A; v[5] = x1.y * SCALE_A;
        v[6] = x1.z * SCALE_A; v[7] = x1.w * SCALE_A;
        uint32_t hi[4], lo[4];
#pragma unroll
        for (int q = 0; q < 4; q++) {
            __half2 hh = __float22half2_rn(make_float2(v[2 * q], v[2 * q + 1]));
            __half2 ll = __float22half2_rn(make_float2(v[2 * q] - __low2float(hh),
                                                       v[2 * q + 1] - __high2float(hh)));
            hi[q] = *(uint32_t*)&hh;
            lo[q] = *(uint32_t*)&ll;
        }
        uint32_t o = swz(j, k0);
        *(uint4*)(smc + SA_HI + o) = make_uint4(hi[0], hi[1], hi[2], hi[3]);
        *(uint4*)(smc + SA_LO + o) = make_uint4(lo[0], lo[1], lo[2], lo[3]);
    }
    for (int p = t; p < 2048; p += 512) build_oct(smc, WfT, sav, p);
    __syncthreads();

    // ---- ldsm lane bases (swizzled). 16 warps: 4 j-tiles x 4 h-groups ----
    const int j0 = (wid & 3) * 32;
    const int h0 = (wid >> 2) * 32;
    const int aRowG = j0 + (lane & 15);
    const uint32_t kbA = (uint32_t)(((lane >> 4) << 3) << 1);  // 0 or 16 B
    const uint32_t aXor = (uint32_t)((aRowG & 7) << 4);
    const uint32_t aBase = sb + (uint32_t)(((aRowG >> 3) << 10) + ((aRowG & 7) << 7));
    const int bRowG = h0 + ((lane >> 4) << 3) + (lane & 7);
    const uint32_t kbB = (uint32_t)((((lane >> 3) & 1) << 3) << 1);
    const uint32_t bXor = (uint32_t)((bRowG & 7) << 4);
    const uint32_t bBase = sb + (uint32_t)(((bRowG >> 3) << 10) + ((bRowG & 7) << 7));
    uint32_t alow[4], blow[4];
#pragma unroll
    for (int c = 0; c < 4; c++) {
        alow[c] = (((uint32_t)c << 5) + kbA) ^ aXor;
        blow[c] = (((uint32_t)c << 5) + kbB) ^ bXor;
    }

    for (int a = 0; a < cnt; a++) {
        // prefetch sav(a+1): safe — build of M(a) finished before last sync,
        // build of M(a+1) starts after the next sync.
        if (t >= 128 && t < 256 && a + 1 < cnt)
            sav[t - 128] = atomBase[(a + 1) * 128 + (t - 128)] * SCALE_B;

        float acc[2][4][4];
#pragma unroll
        for (int mt = 0; mt < 2; mt++)
#pragma unroll
            for (int nt = 0; nt < 4; nt++)
#pragma unroll
                for (int e = 0; e < 4; e++) acc[mt][nt][e] = 0.f;

#pragma unroll
        for (int ks = 0; ks < 8; ks++) {
            const uint32_t pan = (uint32_t)((ks >> 2) << 14);
            const uint32_t ao = pan + alow[ks & 3];
            const uint32_t bo = pan + blow[ks & 3];
            uint32_t aH[2][4], aL[2][4], bH[2][4], bL[2][4];
            ldsm_x4(aH[0], aBase + SA_HI + ao);
            ldsm_x4(aH[1], aBase + SA_HI + 2048 + ao);
            ldsm_x4(aL[0], aBase + SA_LO + ao);
            ldsm_x4(aL[1], aBase + SA_LO + 2048 + ao);
            ldsm_x4(bH[0], bBase + SM_HI + bo);
            ldsm_x4(bH[1], bBase + SM_HI + 2048 + bo);
            ldsm_x4(bL[0], bBase + SM_LO + bo);
            ldsm_x4(bL[1], bBase + SM_LO + 2048 + bo);
#pragma unroll
            for (int mt = 0; mt < 2; mt++) {
#pragma unroll
                for (int ng = 0; ng < 2; ng++) {
                    mma_f16(acc[mt][2 * ng], aH[mt], bH[ng]);
                    mma_f16(acc[mt][2 * ng + 1], aH[mt], bH[ng] + 2);
                    mma_f16(acc[mt][2 * ng], aH[mt], bL[ng]);
                    mma_f16(acc[mt][2 * ng + 1], aH[mt], bL[ng] + 2);
                    mma_f16(acc[mt][2 * ng], aL[mt], bH[ng]);
                    mma_f16(acc[mt][2 * ng + 1], aL[mt], bH[ng] + 2);
                }
            }
        }

        // ---- epilogue: unscale + lrelu + pe/pg dots (32 rows x 32 cols) ----
        float pe[4] = {0.f, 0.f, 0.f, 0.f}, pg[4] = {0.f, 0.f, 0.f, 0.f};
#pragma unroll
        for (int nt = 0; nt < 4; nt++) {
#pragma unroll
            for (int c = 0; c < 2; c++) {
                const int h = h0 + 8 * nt + 2 * (lane & 3) + c;
                const float wpeh = cv[h];
                const float wpgh = cv[128 + h];
                const float bih = cv[256 + h];
#pragma unroll
                for (int mt = 0; mt < 2; mt++) {
#pragma unroll
                    for (int hf = 0; hf < 2; hf++) {
                        float v = acc[mt][nt][hf * 2 + c] * SCALE_INV + bih;
                        v = (v > 0.f) ? v : 0.01f * v;
                        pe[mt * 2 + hf] += v * wpeh;
                        pg[mt * 2 + hf] += v * wpgh;
                    }
                }
            }
        }
#pragma unroll
        for (int rs = 0; rs < 4; rs++) {
#pragma unroll
            for (int off = 1; off < 4; off <<= 1) {
                pe[rs] += __shfl_xor_sync(0xffffffffu, pe[rs], off);
                pg[rs] += __shfl_xor_sync(0xffffffffu, pg[rs], off);
            }
        }
        if ((lane & 3) == 0) {
            const int wx = wid >> 2;  // h-group 0..3
#pragma unroll
            for (int mt = 0; mt < 2; mt++)
#pragma unroll
                for (int hf = 0; hf < 2; hf++) {
                    int j = j0 + 16 * mt + 8 * hf + (lane >> 2);
                    peb[wx * 128 + j] = pe[mt * 2 + hf];
                    pgb[wx * 128 + j] = pg[mt * 2 + hf];
                }
        }
        __syncthreads();

        // ---- overlapped window: warp 0 reduces; warps 1-15 build M(a+1) ----
        if (wid == 0) {
            float tot = 0.f;
#pragma unroll
            for (int q = 0; q < 4; q++) {
                int j = lane + q * 32;
                float spe = peb[j] + peb[128 + j] + peb[256 + j] + peb[384 + j] + bpe0;
                float spg = pgb[j] + pgb[128 + j] + pgb[256 + j] + pgb[384 + j] + bpg0;
                tot += spe / (1.f + __expf(-spg));
            }
#pragma unroll
            for (int off = 16; off > 0; off >>= 1)
                tot += __shfl_xor_sync(0xffffffffu, tot, off);
            if (lane == 0) g_atom_e[n * 1024 + i0 + a] = tot;
        } else if (a + 1 < cnt) {
            for (int p = t - 32; p < 2048; p += 480) build_oct(smc, WfT, sav, p);
        }
        __syncthreads();
    }
}

// ------------------------------ k_final -------------------------------------
__global__ void k_final(const float* __restrict__ lgr, const int* __restrict__ lb,
                        const float* __restrict__ Wgr, const float* __restrict__ bgr,
                        const float* __restrict__ Wb1, const float* __restrict__ bb1,
                        const float* __restrict__ Wb2, const float* __restrict__ bb2,
                        float* __restrict__ out) {
    int n = blockIdx.x >> 6, g = blockIdx.x & 63, t = threadIdx.x;
    __shared__ float z[256];
    __shared__ float lg[64];
    __shared__ float red[8];
    if (t < 64) lg[t] = lgr[(n * 64 + g) * 64 + t];
    z[t] = g_pf[n * 128 + t];
    __syncthreads();
    float gf = bgr[t];
#pragma unroll 4
    for (int c = 0; c < 64; c++) gf += lg[c] * Wgr[c * 128 + t];
    z[128 + t] = gf;
    __syncthreads();
    float h = bb1[t];
#pragma unroll 4
    for (int c = 0; c < 256; c++) h += z[c] * Wb1[c * 128 + t];
    h = (h > 0.f) ? h : 0.01f * h;
    float part = h * Wb2[t];
    float seg = 0.f;
    for (int a = t; a < 1024; a += 128) {
        if (lb[a] == g) seg += g_atom_e[n * 1024 + a];
    }
#pragma unroll
    for (int off = 16; off > 0; off >>= 1) {
        part += __shfl_down_sync(0xffffffffu, part, off);
        seg += __shfl_down_sync(0xffffffffu, seg, off);
    }
    int wid = t >> 5;
    if ((t & 31) == 0) {
        red[wid] = part;
        red[4 + wid] = seg;
    }
    __syncthreads();
    if (t == 0) {
        float bias = red[0] + red[1] + red[2] + red[3] + bb2[0];
        float segs = red[4] + red[5] + red[6] + red[7];
        out[n * 64 + g] = segs + bias;
    }
}

// ------------------------------ launch --------------------------------------
extern "C" void kernel_launch(void* const* d_in, const int* in_sizes, int n_in,
                              void* d_out, int out_size) {
    const float* ms0 = (const float*)d_in[0];
    const float* ms1 = (const float*)d_in[1];
    const float* tf = (const float*)d_in[2];
    const float* lat = (const float*)d_in[3];
    const float* lgr = (const float*)d_in[4];
    const int* lb = (const int*)d_in[5];
    const float* Wt = (const float*)d_in[6];
    const float* bt = (const float*)d_in[7];
    const float* Wc0 = (const float*)d_in[8];
    const float* bc0 = (const float*)d_in[9];
    const float* Wc1 = (const float*)d_in[10];
    const float* bc1 = (const float*)d_in[11];
    const float* Wp = (const float*)d_in[12];
    const float* bp = (const float*)d_in[13];
    const float* Wcat = (const float*)d_in[14];
    const float* bcat = (const float*)d_in[15];
    const float* Wgate = (const float*)d_in[16];
    const float* bgate = (const float*)d_in[17];
    const float* Wa = (const float*)d_in[18];
    const float* ba = (const float*)d_in[19];
    const float* Wgr = (const float*)d_in[20];
    const float* bgr = (const float*)d_in[21];
    const float* Wb1 = (const float*)d_in[22];
    const float* bb1 = (const float*)d_in[23];
    const float* Wb2 = (const float*)d_in[24];
    const float* bb2 = (const float*)d_in[25];
    const float* Wi = (const float*)d_in[26];
    const float* bi = (const float*)d_in[27];
    const float* wpe = (const float*)d_in[28];
    const float* bpe = (const float*)d_in[29];
    const float* wpg = (const float*)d_in[30];
    const float* bpg = (const float*)d_in[31];
    float* out = (float*)d_out;

    // k_inter is the 4th launch (ncu -s window lands on it).
    k_tok<<<512, 128>>>(tf, Wt, bt);
    k_atoms<<<512, 128>>>(lat, Wa, ba);
    k_S1<<<256, 128>>>(ms1);

    cudaFuncSetAttribute(k_inter, cudaFuncAttributeMaxDynamicSharedMemorySize,
                         SMEM_TC_BYTES);
    k_inter<<<148, 512, SMEM_TC_BYTES>>>(Wi, bi, wpe, bpe, wpg, bpg);

    k_S0<<<128, 256>>>(ms0);
    k_pconv<<<64, 256>>>(Wc0, bc0, Wc1, bc1);
    k_pf<<<4, 128>>>(Wp, bp, Wcat, bcat, Wgate, bgate);
    k_final<<<256, 128>>>(lgr, lb, Wgr, bgr, Wb1, bb1, Wb2, bb2, out);
}

// round 10
// speedup vs baseline: 1.0198x; 1.0198x over previous
#include <cuda_runtime.h>
#include <cuda_fp16.h>
#include <cstdint>

// ---------------------------------------------------------------------------
// AffinityHead — mma.sync fp16x3 split GEMM core (unchanged from R9 best) +
// fused/parallelized small kernels: 5 launches total.
//   k_tokatoms : tok rows (blocks 0-511) + atom rows (blocks 512-1023)
//   k_ms       : S1 sums (blocks 0-255) + S0 sums (blocks 256-383), warp-per-k
//   k_pconv    : warp-per-output, conv0/conv1 split across blocks
//   k_inter    : per-atom 128x128x128 fp16x3 tensor-core GEMM (4th launch)
//   k_final    : pf (recomputed per block) + bias MLP + segment sum
// ---------------------------------------------------------------------------

__device__ __forceinline__ float silu_f(float v) { return v / (1.f + __expf(-v)); }

// ------------------------- scratch (static, no allocs) ---------------------
__device__ float g_tok[4 * 128 * 128];     // [n][j][h]
__device__ float g_S1[4 * 64 * 27];
__device__ float g_S0[4 * 32 * 27];
__device__ float g_p[4 * 256];
__device__ float g_atoms[4 * 1024 * 128];  // [n][i][k]
__device__ float g_atom_e[4 * 1024];

// ------------------------------ PTX helpers --------------------------------
__device__ __forceinline__ uint32_t smem_to_u32(const void* p) {
    uint32_t a;
    asm("{ .reg .u64 t; cvta.to.shared.u64 t, %1; cvt.u32.u64 %0, t; }" : "=r"(a) : "l"(p));
    return a;
}

__device__ __forceinline__ void ldsm_x4(uint32_t* r, uint32_t addr) {
    asm volatile("ldmatrix.sync.aligned.m8n8.x4.shared.b16 {%0,%1,%2,%3}, [%4];"
                 : "=r"(r[0]), "=r"(r[1]), "=r"(r[2]), "=r"(r[3]) : "r"(addr));
}

__device__ __forceinline__ void mma_f16(float* d, const uint32_t* a, const uint32_t* b) {
    asm volatile(
        "mma.sync.aligned.m16n8k16.row.col.f32.f16.f16.f32 "
        "{%0,%1,%2,%3}, {%4,%5,%6,%7}, {%8,%9}, {%0,%1,%2,%3};"
        : "+f"(d[0]), "+f"(d[1]), "+f"(d[2]), "+f"(d[3])
        : "r"(a[0]), "r"(a[1]), "r"(a[2]), "r"(a[3]), "r"(b[0]), "r"(b[1]));
}

// SW128 blocked-atom swizzled byte offset for a [128 rows][128 halves] plane.
__device__ __forceinline__ uint32_t swz(int row, int k) {
    uint32_t off = (uint32_t)(((k >> 6) << 14) + ((row >> 3) << 10) +
                              ((row & 7) << 7) + ((k & 63) << 1));
    return off ^ (uint32_t)((row & 7) << 4);
}

// ------------------------------ k_tokatoms ----------------------------------
__global__ void k_tokatoms(const float* __restrict__ tf, const float* __restrict__ Wt,
                           const float* __restrict__ bt, const float* __restrict__ la,
                           const float* __restrict__ Wa, const float* __restrict__ ba) {
    __shared__ float s[512];
    const int t = threadIdx.x;
    if (blockIdx.x < 512) {
        // tok row = blockIdx.x
        const int row = blockIdx.x;
        const float* x = tf + row * 256;
        for (int c = t; c < 256; c += 128) s[c] = silu_f(x[c]);
        __syncthreads();
        float acc = bt[t];
#pragma unroll 8
        for (int c = 0; c < 256; c++) acc += s[c] * Wt[c * 128 + t];
        g_tok[row * 128 + t] = acc;
    } else {
        // atoms rows r0..r0+7
        const int r0 = (blockIdx.x - 512) * 8;
        for (int i = t; i < 512; i += 128) s[i] = la[r0 * 64 + i];
        __syncthreads();
        float b = ba[t];
        float acc[8];
#pragma unroll
        for (int r = 0; r < 8; r++) acc[r] = b;
        for (int c = 0; c < 64; c++) {
            float w = Wa[c * 128 + t];
#pragma unroll
            for (int r = 0; r < 8; r++) acc[r] += s[(r << 6) + c] * w;
        }
#pragma unroll
        for (int r = 0; r < 8; r++) g_atoms[(r0 + r) * 128 + t] = acc[r];
    }
}

// ------------------------------ k_ms (S1 + S0) ------------------------------
__global__ void k_ms(const float* __restrict__ ms1, const float* __restrict__ ms0) {
    __shared__ float v[4096];
    const int t = threadIdx.x;
    const int w = t >> 5, lane = t & 31;
    const int b = blockIdx.x;
    if (b < 256) {
        // S1: one (n,c) channel of ms_feat_1 [8x8x8], 27 shifted 6^3 sums
        for (int i = t; i < 512; i += 256) v[i] = silu_f(ms1[b * 512 + i]);
        __syncthreads();
        for (int k = w; k < 27; k += 8) {
            int kd = k / 9, kh = (k / 3) % 3, kw = k % 3;
            float s = 0.f;
            for (int i = lane; i < 216; i += 32) {
                int d = i / 36, r = i % 36, hh = r / 6, ww = r % 6;
                s += v[(d + kd) * 64 + (hh + kh) * 8 + (ww + kw)];
            }
#pragma unroll
            for (int off = 16; off > 0; off >>= 1)
                s += __shfl_down_sync(0xffffffffu, s, off);
            if (lane == 0) g_S1[b * 27 + k] = s;
        }
    } else {
        // S0: one (n,c) channel of ms_feat_0 [16x16x16], 27 shifted 14^3 sums
        const int nc = b - 256;
        for (int i = t; i < 4096; i += 256) v[i] = silu_f(ms0[nc * 4096 + i]);
        __syncthreads();
        for (int k = w; k < 27; k += 8) {
            int kd = k / 9, kh = (k / 3) % 3, kw = k % 3;
            float s = 0.f;
            for (int i = lane; i < 2744; i += 32) {
                int d = i / 196, r = i % 196, hh = r / 14, ww = r % 14;
                s += v[(d + kd) * 256 + (hh + kh) * 16 + (ww + kw)];
            }
#pragma unroll
            for (int off = 16; off > 0; off >>= 1)
                s += __shfl_down_sync(0xffffffffu, s, off);
            if (lane == 0) g_S0[nc * 27 + k] = s;
        }
    }
}

// ------------------------------ k_pconv (warp-per-output) -------------------
__global__ void k_pconv(const float* __restrict__ Wc0, const float* __restrict__ bc0,
                        const float* __restrict__ Wc1, const float* __restrict__ bc1) {
    __shared__ float s[1728];
    const int t = threadIdx.x, w = t >> 5, lane = t & 31;
    int b = blockIdx.x;   // 128 blocks x 256 threads
    if (b < 64) {
        int n = b >> 4, o = (b & 15) * 8 + w;
        for (int i = t; i < 1728; i += 256) s[i] = g_S1[n * 1728 + i];
        __syncthreads();
        float a = 0.f;
        for (int x = lane; x < 1728; x += 32) a += s[x] * Wc0[o * 1728 + x];
#pragma unroll
        for (int off = 16; off > 0; off >>= 1)
            a += __shfl_down_sync(0xffffffffu, a, off);
        if (lane == 0) g_p[n * 256 + o] = a * (1.f / 216.f) + bc0[o];
    } else {
        b -= 64;
        int n = b >> 4, o = (b & 15) * 8 + w;
        for (int i = t; i < 864; i += 256) s[i] = g_S0[n * 864 + i];
        __syncthreads();
        float a = 0.f;
        for (int x = lane; x < 864; x += 32) a += s[x] * Wc1[o * 864 + x];
#pragma unroll
        for (int off = 16; off > 0; off >>= 1)
            a += __shfl_down_sync(0xffffffffu, a, off);
        if (lane == 0) g_p[n * 256 + 128 + o] = a * (1.f / 2744.f) + bc1[o];
    }
}

// ------------------------------ k_inter (unchanged from R9) -----------------
#define SA_HI 0
#define SA_LO 32768
#define SM_HI 65536
#define SM_LO 98304
#define SWT 131072            // W^T fp32 [128][132] : 67584
#define SCV 198656            // wpe|wpg|bi : 1536
#define SPE 200192            // peb/pgb [4][128] each : 4096
#define SSAV 204352           // 512
#define SMEM_TC_BYTES 204928

#define SCALE_A 16.f
#define SCALE_B 256.f
#define SCALE_INV (1.f / 4096.f)

__device__ __forceinline__ void build_oct(char* smc, const float* __restrict__ WfT,
                                          const float* __restrict__ sav, int p) {
    const int h = p >> 4, k0 = (p & 15) << 3;
    const float4* wp = (const float4*)(WfT + h * 132 + k0);
    const float4 w0 = wp[0], w1 = wp[1];
    const float4* ap = (const float4*)(sav + k0);
    const float4 a0 = ap[0], a1 = ap[1];
    float v[8];
    v[0] = a0.x * w0.x; v[1] = a0.y * w0.y; v[2] = a0.z * w0.z; v[3] = a0.w * w0.w;
    v[4] = a1.x * w1.x; v[5] = a1.y * w1.y; v[6] = a1.z * w1.z; v[7] = a1.w * w1.w;
    uint32_t hi[4], lo[4];
#pragma unroll
    for (int q = 0; q < 4; q++) {
        __half2 hh = __float22half2_rn(make_float2(v[2 * q], v[2 * q + 1]));
        __half2 ll = __float22half2_rn(make_float2(v[2 * q] - __low2float(hh),
                                                   v[2 * q + 1] - __high2float(hh)));
        hi[q] = *(uint32_t*)&hh;
        lo[q] = *(uint32_t*)&ll;
    }
    const uint32_t o = swz(h, k0);
    *(uint4*)(smc + SM_HI + o) = make_uint4(hi[0], hi[1], hi[2], hi[3]);
    *(uint4*)(smc + SM_LO + o) = make_uint4(lo[0], lo[1], lo[2], lo[3]);
}

__global__ void __launch_bounds__(512, 1)
k_inter(const float* __restrict__ Wi, const float* __restrict__ bi,
        const float* __restrict__ wpe, const float* __restrict__ bpe,
        const float* __restrict__ wpg, const float* __restrict__ bpg) {
    extern __shared__ char smc[];
    const uint32_t sb = smem_to_u32(smc);
    float* WfT = (float*)(smc + SWT);
    float* cv = (float*)(smc + SCV);
    float* peb = (float*)(smc + SPE);        // [4][128]
    float* pgb = peb + 512;                  // [4][128]
    float* sav = (float*)(smc + SSAV);       // [128], pre-scaled by SCALE_B

    const int t = threadIdx.x;
    const int wid = t >> 5;
    const int lane = t & 31;

    const int n = blockIdx.x / 37;
    const int grp = blockIdx.x % 37;
    const int i0 = grp * 28;
    const int cnt = min(28, 1024 - i0);
    const float* atomBase = g_atoms + (n * 1024 + i0) * 128;
    const float bpe0 = bpe[0], bpg0 = bpg[0];

    for (int idx = t; idx < 16384; idx += 512) {
        int k = idx >> 7, h = idx & 127;
        WfT[h * 132 + k] = Wi[idx];
    }
    if (t < 128) {
        cv[t] = wpe[t];
        cv[128 + t] = wpg[t];
        cv[256 + t] = bi[t];
        sav[t] = atomBase[t] * SCALE_B;
    }
    __syncthreads();

    const float* tokn = g_tok + n * 16384;
    for (int p = t; p < 2048; p += 512) {
        int j = p >> 4, k0 = (p & 15) << 3;
        const float4* xp = (const float4*)(tokn + j * 128 + k0);
        float4 x0 = xp[0], x1 = xp[1];
        float v[8];
        v[0] = x0.x * SCALE_A; v[1] = x0.y * SCALE_A;
        v[2] = x0.z * SCALE_A; v[3] = x0.w * SCALE_A;
        v[4] = x1.x * SCALE_A; v[5] = x1.y * SCALE_A;
        v[6] = x1.z * SCALE_A; v[7] = x1.w * SCALE_A;
        uint32_t hi[4], lo[4];
#pragma unroll
        for (int q = 0; q < 4; q++) {
            __half2 hh = __float22half2_rn(make_float2(v[2 * q], v[2 * q + 1]));
            __half2 ll = __float22half2_rn(make_float2(v[2 * q] - __low2float(hh),
                                                       v[2 * q + 1] - __high2float(hh)));
            hi[q] = *(uint32_t*)&hh;
            lo[q] = *(uint32_t*)&ll;
        }
        uint32_t o = swz(j, k0);
        *(uint4*)(smc + SA_HI + o) = make_uint4(hi[0], hi[1], hi[2], hi[3]);
        *(uint4*)(smc + SA_LO + o) = make_uint4(lo[0], lo[1], lo[2], lo[3]);
    }
    for (int p = t; p < 2048; p += 512) build_oct(smc, WfT, sav, p);
    __syncthreads();

    const int j0 = (wid & 3) * 32;
    const int h0 = (wid >> 2) * 32;
    const int aRowG = j0 + (lane & 15);
    const uint32_t kbA = (uint32_t)(((lane >> 4) << 3) << 1);
    const uint32_t aXor = (uint32_t)((aRowG & 7) << 4);
    const uint32_t aBase = sb + (uint32_t)(((aRowG >> 3) << 10) + ((aRowG & 7) << 7));
    const int bRowG = h0 + ((lane >> 4) << 3) + (lane & 7);
    const uint32_t kbB = (uint32_t)((((lane >> 3) & 1) << 3) << 1);
    const uint32_t bXor = (uint32_t)((bRowG & 7) << 4);
    const uint32_t bBase = sb + (uint32_t)(((bRowG >> 3) << 10) + ((bRowG & 7) << 7));
    uint32_t alow[4], blow[4];
#pragma unroll
    for (int c = 0; c < 4; c++) {
        alow[c] = (((uint32_t)c << 5) + kbA) ^ aXor;
        blow[c] = (((uint32_t)c << 5) + kbB) ^ bXor;
    }

    for (int a = 0; a < cnt; a++) {
        if (t >= 128 && t < 256 && a + 1 < cnt)
            sav[t - 128] = atomBase[(a + 1) * 128 + (t - 128)] * SCALE_B;

        float acc[2][4][4];
#pragma unroll
        for (int mt = 0; mt < 2; mt++)
#pragma unroll
            for (int nt = 0; nt < 4; nt++)
#pragma unroll
                for (int e = 0; e < 4; e++) acc[mt][nt][e] = 0.f;

#pragma unroll
        for (int ks = 0; ks < 8; ks++) {
            const uint32_t pan = (uint32_t)((ks >> 2) << 14);
            const uint32_t ao = pan + alow[ks & 3];
            const uint32_t bo = pan + blow[ks & 3];
            uint32_t aH[2][4], aL[2][4], bH[2][4], bL[2][4];
            ldsm_x4(aH[0], aBase + SA_HI + ao);
            ldsm_x4(aH[1], aBase + SA_HI + 2048 + ao);
            ldsm_x4(aL[0], aBase + SA_LO + ao);
            ldsm_x4(aL[1], aBase + SA_LO + 2048 + ao);
            ldsm_x4(bH[0], bBase + SM_HI + bo);
            ldsm_x4(bH[1], bBase + SM_HI + 2048 + bo);
            ldsm_x4(bL[0], bBase + SM_LO + bo);
            ldsm_x4(bL[1], bBase + SM_LO + 2048 + bo);
#pragma unroll
            for (int mt = 0; mt < 2; mt++) {
#pragma unroll
                for (int ng = 0; ng < 2; ng++) {
                    mma_f16(acc[mt][2 * ng], aH[mt], bH[ng]);
                    mma_f16(acc[mt][2 * ng + 1], aH[mt], bH[ng] + 2);
                    mma_f16(acc[mt][2 * ng], aH[mt], bL[ng]);
                    mma_f16(acc[mt][2 * ng + 1], aH[mt], bL[ng] + 2);
                    mma_f16(acc[mt][2 * ng], aL[mt], bH[ng]);
                    mma_f16(acc[mt][2 * ng + 1], aL[mt], bH[ng] + 2);
                }
            }
        }

        float pe[4] = {0.f, 0.f, 0.f, 0.f}, pg[4] = {0.f, 0.f, 0.f, 0.f};
#pragma unroll
        for (int nt = 0; nt < 4; nt++) {
#pragma unroll
            for (int c = 0; c < 2; c++) {
                const int h = h0 + 8 * nt + 2 * (lane & 3) + c;
                const float wpeh = cv[h];
                const float wpgh = cv[128 + h];
                const float bih = cv[256 + h];
#pragma unroll
                for (int mt = 0; mt < 2; mt++) {
#pragma unroll
                    for (int hf = 0; hf < 2; hf++) {
                        float v = acc[mt][nt][hf * 2 + c] * SCALE_INV + bih;
                        v = (v > 0.f) ? v : 0.01f * v;
                        pe[mt * 2 + hf] += v * wpeh;
                        pg[mt * 2 + hf] += v * wpgh;
                    }
                }
            }
        }
#pragma unroll
        for (int rs = 0; rs < 4; rs++) {
#pragma unroll
            for (int off = 1; off < 4; off <<= 1) {
                pe[rs] += __shfl_xor_sync(0xffffffffu, pe[rs], off);
                pg[rs] += __shfl_xor_sync(0xffffffffu, pg[rs], off);
            }
        }
        if ((lane & 3) == 0) {
            const int wx = wid >> 2;
#pragma unroll
            for (int mt = 0; mt < 2; mt++)
#pragma unroll
                for (int hf = 0; hf < 2; hf++) {
                    int j = j0 + 16 * mt + 8 * hf + (lane >> 2);
                    peb[wx * 128 + j] = pe[mt * 2 + hf];
                    pgb[wx * 128 + j] = pg[mt * 2 + hf];
                }
        }
        __syncthreads();

        if (wid == 0) {
            float tot = 0.f;
#pragma unroll
            for (int q = 0; q < 4; q++) {
                int j = lane + q * 32;
                float spe = peb[j] + peb[128 + j] + peb[256 + j] + peb[384 + j] + bpe0;
                float spg = pgb[j] + pgb[128 + j] + pgb[256 + j] + pgb[384 + j] + bpg0;
                tot += spe / (1.f + __expf(-spg));
            }
#pragma unroll
            for (int off = 16; off > 0; off >>= 1)
                tot += __shfl_xor_sync(0xffffffffu, tot, off);
            if (lane == 0) g_atom_e[n * 1024 + i0 + a] = tot;
        } else if (a + 1 < cnt) {
            for (int p = t - 32; p < 2048; p += 480) build_oct(smc, WfT, sav, p);
        }
        __syncthreads();
    }
}

// ------------------------------ k_final (pf fused) --------------------------
__global__ void k_final(const float* __restrict__ lgr, const int* __restrict__ lb,
                        const float* __restrict__ Wp, const float* __restrict__ bp,
                        const float* __restrict__ Wcat, const float* __restrict__ bcat,
                        const float* __restrict__ Wgate, const float* __restrict__ bgate,
                        const float* __restrict__ Wgr, const float* __restrict__ bgr,
                        const float* __restrict__ Wb1, const float* __restrict__ bb1,
                        const float* __restrict__ Wb2, const float* __restrict__ bb2,
                        float* __restrict__ out) {
    int n = blockIdx.x >> 6, g = blockIdx.x & 63, t = threadIdx.x;
    __shared__ float sp[256];
    __shared__ float pin[384];
    __shared__ float z[256];
    __shared__ float lg[64];
    __shared__ float red[8];

    // pf recompute (cheap): silu(g_p), token agg, pocket MLP, cat/gate
    for (int c = t; c < 256; c += 128) sp[c] = silu_f(g_p[n * 256 + c]);
    if (t < 64) lg[t] = lgr[(n * 64 + g) * 64 + t];
    float ts = 0.f;
    for (int j = 0; j < 128; j++) ts += g_tok[(n * 128 + j) * 128 + t];
    __syncthreads();
    float pk = bp[t];
#pragma unroll 4
    for (int c = 0; c < 256; c++) pk += sp[c] * Wp[c * 128 + t];
    pin[t] = pk;
    pin[128 + t] = ts;
    pin[256 + t] = ts * (1.f / 128.f);
    __syncthreads();
    float c1 = bcat[t], g1 = bgate[t];
#pragma unroll 4
    for (int c = 0; c < 384; c++) {
        float zz = pin[c];
        c1 += zz * Wcat[c * 128 + t];
        g1 += zz * Wgate[c * 128 + t];
    }
    z[t] = c1 / (1.f + __expf(-g1));   // pf

    // graph projection
    float gf = bgr[t];
#pragma unroll 4
    for (int c = 0; c < 64; c++) gf += lg[c] * Wgr[c * 128 + t];
    z[128 + t] = gf;
    __syncthreads();

    float h = bb1[t];
#pragma unroll 4
    for (int c = 0; c < 256; c++) h += z[c] * Wb1[c * 128 + t];
    h = (h > 0.f) ? h : 0.01f * h;
    float part = h * Wb2[t];
    float seg = 0.f;
    for (int a = t; a < 1024; a += 128) {
        if (lb[a] == g) seg += g_atom_e[n * 1024 + a];
    }
#pragma unroll
    for (int off = 16; off > 0; off >>= 1) {
        part += __shfl_down_sync(0xffffffffu, part, off);
        seg += __shfl_down_sync(0xffffffffu, seg, off);
    }
    int wid = t >> 5;
    if ((t & 31) == 0) {
        red[wid] = part;
        red[4 + wid] = seg;
    }
    __syncthreads();
    if (t == 0) {
        float bias = red[0] + red[1] + red[2] + red[3] + bb2[0];
        float segs = red[4] + red[5] + red[6] + red[7];
        out[n * 64 + g] = segs + bias;
    }
}

// ------------------------------ launch --------------------------------------
extern "C" void kernel_launch(void* const* d_in, const int* in_sizes, int n_in,
                              void* d_out, int out_size) {
    const float* ms0 = (const float*)d_in[0];
    const float* ms1 = (const float*)d_in[1];
    const float* tf = (const float*)d_in[2];
    const float* lat = (const float*)d_in[3];
    const float* lgr = (const float*)d_in[4];
    const int* lb = (const int*)d_in[5];
    const float* Wt = (const float*)d_in[6];
    const float* bt = (const float*)d_in[7];
    const float* Wc0 = (const float*)d_in[8];
    const float* bc0 = (const float*)d_in[9];
    const float* Wc1 = (const float*)d_in[10];
    const float* bc1 = (const float*)d_in[11];
    const float* Wp = (const float*)d_in[12];
    const float* bp = (const float*)d_in[13];
    const float* Wcat = (const float*)d_in[14];
    const float* bcat = (const float*)d_in[15];
    const float* Wgate = (const float*)d_in[16];
    const float* bgate = (const float*)d_in[17];
    const float* Wa = (const float*)d_in[18];
    const float* ba = (const float*)d_in[19];
    const float* Wgr = (const float*)d_in[20];
    const float* bgr = (const float*)d_in[21];
    const float* Wb1 = (const float*)d_in[22];
    const float* bb1 = (const float*)d_in[23];
    const float* Wb2 = (const float*)d_in[24];
    const float* bb2 = (const float*)d_in[25];
    const float* Wi = (const float*)d_in[26];
    const float* bi = (const float*)d_in[27];
    const float* wpe = (const float*)d_in[28];
    const float* bpe = (const float*)d_in[29];
    const float* wpg = (const float*)d_in[30];
    const float* bpg = (const float*)d_in[31];
    float* out = (float*)d_out;

    k_tokatoms<<<1024, 128>>>(tf, Wt, bt, lat, Wa, ba);
    k_ms<<<384, 256>>>(ms1, ms0);
    k_pconv<<<128, 256>>>(Wc0, bc0, Wc1, bc1);

    cudaFuncSetAttribute(k_inter, cudaFuncAttributeMaxDynamicSharedMemorySize,
                         SMEM_TC_BYTES);
    k_inter<<<148, 512, SMEM_TC_BYTES>>>(Wi, bi, wpe, bpe, wpg, bpg);

    k_final<<<256, 128>>>(lgr, lb, Wp, bp, Wcat, bcat, Wgate, bgate,
                          Wgr, bgr, Wb1, bb1, Wb2, bb2, out);
}

// round 12
// speedup vs baseline: 1.0811x; 1.0601x over previous
#include <cuda_runtime.h>
#include <cuda_fp16.h>
#include <cstdint>

// ---------------------------------------------------------------------------
// AffinityHead — mma.sync fp16x3 split GEMM core.
// R12: same as R11 (B in [k][h] via ldmatrix.trans, double-buffered M,
// builds from L2 inside the mainloop) with the swizzle-carry bug fixed:
// the h+16 octet gets its own precomputed swizzled base instead of +32
// applied to a post-XOR address.
// ---------------------------------------------------------------------------

__device__ __forceinline__ float silu_f(float v) { return v / (1.f + __expf(-v)); }

// ------------------------- scratch (static, no allocs) ---------------------
__device__ float g_tok[4 * 128 * 128];     // [n][j][h]
__device__ float g_S1[4 * 64 * 27];
__device__ float g_S0[4 * 32 * 27];
__device__ float g_p[4 * 256];
__device__ float g_atoms[4 * 1024 * 128];  // [n][i][k]
__device__ float g_atom_e[4 * 1024];

// ------------------------------ PTX helpers --------------------------------
__device__ __forceinline__ uint32_t smem_to_u32(const void* p) {
    uint32_t a;
    asm("{ .reg .u64 t; cvta.to.shared.u64 t, %1; cvt.u32.u64 %0, t; }" : "=r"(a) : "l"(p));
    return a;
}

__device__ __forceinline__ void ldsm_x4(uint32_t* r, uint32_t addr) {
    asm volatile("ldmatrix.sync.aligned.m8n8.x4.shared.b16 {%0,%1,%2,%3}, [%4];"
                 : "=r"(r[0]), "=r"(r[1]), "=r"(r[2]), "=r"(r[3]) : "r"(addr));
}

__device__ __forceinline__ void ldsm_x4_t(uint32_t* r, uint32_t addr) {
    asm volatile("ldmatrix.sync.aligned.m8n8.x4.trans.shared.b16 {%0,%1,%2,%3}, [%4];"
                 : "=r"(r[0]), "=r"(r[1]), "=r"(r[2]), "=r"(r[3]) : "r"(addr));
}

__device__ __forceinline__ void mma_f16(float* d, const uint32_t* a, const uint32_t* b) {
    asm volatile(
        "mma.sync.aligned.m16n8k16.row.col.f32.f16.f16.f32 "
        "{%0,%1,%2,%3}, {%4,%5,%6,%7}, {%8,%9}, {%0,%1,%2,%3};"
        : "+f"(d[0]), "+f"(d[1]), "+f"(d[2]), "+f"(d[3])
        : "r"(a[0]), "r"(a[1]), "r"(a[2]), "r"(a[3]), "r"(b[0]), "r"(b[1]));
}

// SW128 blocked-atom swizzled byte offset for a [128 rows][128 halves] plane.
__device__ __forceinline__ uint32_t swz(int row, int k) {
    uint32_t off = (uint32_t)(((k >> 6) << 14) + ((row >> 3) << 10) +
                              ((row & 7) << 7) + ((k & 63) << 1));
    return off ^ (uint32_t)((row & 7) << 4);
}

// ------------------------------ k_tokatoms ----------------------------------
__global__ void k_tokatoms(const float* __restrict__ tf, const float* __restrict__ Wt,
                           const float* __restrict__ bt, const float* __restrict__ la,
                           const float* __restrict__ Wa, const float* __restrict__ ba) {
    __shared__ float s[512];
    const int t = threadIdx.x;
    if (blockIdx.x < 512) {
        const int row = blockIdx.x;
        const float* x = tf + row * 256;
        for (int c = t; c < 256; c += 128) s[c] = silu_f(x[c]);
        __syncthreads();
        float acc = bt[t];
#pragma unroll 8
        for (int c = 0; c < 256; c++) acc += s[c] * Wt[c * 128 + t];
        g_tok[row * 128 + t] = acc;
    } else {
        const int r0 = (blockIdx.x - 512) * 8;
        for (int i = t; i < 512; i += 128) s[i] = la[r0 * 64 + i];
        __syncthreads();
        float b = ba[t];
        float acc[8];
#pragma unroll
        for (int r = 0; r < 8; r++) acc[r] = b;
        for (int c = 0; c < 64; c++) {
            float w = Wa[c * 128 + t];
#pragma unroll
            for (int r = 0; r < 8; r++) acc[r] += s[(r << 6) + c] * w;
        }
#pragma unroll
        for (int r = 0; r < 8; r++) g_atoms[(r0 + r) * 128 + t] = acc[r];
    }
}

// ------------------------------ k_ms (S1 + S0) ------------------------------
__global__ void k_ms(const float* __restrict__ ms1, const float* __restrict__ ms0) {
    __shared__ float v[4096];
    const int t = threadIdx.x;
    const int w = t >> 5, lane = t & 31;
    const int b = blockIdx.x;
    if (b < 256) {
        for (int i = t; i < 512; i += 256) v[i] = silu_f(ms1[b * 512 + i]);
        __syncthreads();
        for (int k = w; k < 27; k += 8) {
            int kd = k / 9, kh = (k / 3) % 3, kw = k % 3;
            float s = 0.f;
            for (int i = lane; i < 216; i += 32) {
                int d = i / 36, r = i % 36, hh = r / 6, ww = r % 6;
                s += v[(d + kd) * 64 + (hh + kh) * 8 + (ww + kw)];
            }
#pragma unroll
            for (int off = 16; off > 0; off >>= 1)
                s += __shfl_down_sync(0xffffffffu, s, off);
            if (lane == 0) g_S1[b * 27 + k] = s;
        }
    } else {
        const int nc = b - 256;
        for (int i = t; i < 4096; i += 256) v[i] = silu_f(ms0[nc * 4096 + i]);
        __syncthreads();
        for (int k = w; k < 27; k += 8) {
            int kd = k / 9, kh = (k / 3) % 3, kw = k % 3;
            float s = 0.f;
            for (int i = lane; i < 2744; i += 32) {
                int d = i / 196, r = i % 196, hh = r / 14, ww = r % 14;
                s += v[(d + kd) * 256 + (hh + kh) * 16 + (ww + kw)];
            }
#pragma unroll
            for (int off = 16; off > 0; off >>= 1)
                s += __shfl_down_sync(0xffffffffu, s, off);
            if (lane == 0) g_S0[nc * 27 + k] = s;
        }
    }
}

// ------------------------------ k_pconv (warp-per-output) -------------------
__global__ void k_pconv(const float* __restrict__ Wc0, const float* __restrict__ bc0,
                        const float* __restrict__ Wc1, const float* __restrict__ bc1) {
    __shared__ float s[1728];
    const int t = threadIdx.x, w = t >> 5, lane = t & 31;
    int b = blockIdx.x;   // 128 blocks x 256 threads
    if (b < 64) {
        int n = b >> 4, o = (b & 15) * 8 + w;
        for (int i = t; i < 1728; i += 256) s[i] = g_S1[n * 1728 + i];
        __syncthreads();
        float a = 0.f;
        for (int x = lane; x < 1728; x += 32) a += s[x] * Wc0[o * 1728 + x];
#pragma unroll
        for (int off = 16; off > 0; off >>= 1)
            a += __shfl_down_sync(0xffffffffu, a, off);
        if (lane == 0) g_p[n * 256 + o] = a * (1.f / 216.f) + bc0[o];
    } else {
        b -= 64;
        int n = b >> 4, o = (b & 15) * 8 + w;
        for (int i = t; i < 864; i += 256) s[i] = g_S0[n * 864 + i];
        __syncthreads();
        float a = 0.f;
        for (int x = lane; x < 864; x += 32) a += s[x] * Wc1[o * 864 + x];
#pragma unroll
        for (int off = 16; off > 0; off >>= 1)
            a += __shfl_down_sync(0xffffffffu, a, off);
        if (lane == 0) g_p[n * 256 + 128 + o] = a * (1.f / 2744.f) + bc1[o];
    }
}

// ------------------------------ k_inter -------------------------------------
// smem: A hi/lo (32768 each) | M buf0 hi/lo | M buf1 hi/lo | cv | peb/pgb | sav
#define SA_HI 0
#define SA_LO 32768
#define SMB 65536
#define MBUF_STRIDE 65536     // per buffer: hi at +0, lo at +32768
#define SCV 196608            // wpe|wpg|bi : 1536
#define SPE 198144            // peb/pgb [4][128] each : 4096
#define SSAV 202240           // [2][128] : 1024
#define SMEM_TC_BYTES 203264

#define SCALE_A 16.f
#define SCALE_B 256.f
#define SCALE_INV (1.f / 4096.f)

// Build one octet (8 h-values at one k) of M = diag(sav)*W into [k][h] planes.
// Reads Wi straight from global (L2-resident, 32B coalesced per lane).
__device__ __forceinline__ void build_oct_t(char* mb, const float* __restrict__ Wi,
                                            const float* __restrict__ sav, int p) {
    const int k = p >> 4, h0 = (p & 15) << 3;
    const float s = sav[k];
    const float4* wp = (const float4*)(Wi + k * 128 + h0);
    const float4 w0 = wp[0], w1 = wp[1];
    float v[8];
    v[0] = s * w0.x; v[1] = s * w0.y; v[2] = s * w0.z; v[3] = s * w0.w;
    v[4] = s * w1.x; v[5] = s * w1.y; v[6] = s * w1.z; v[7] = s * w1.w;
    uint32_t hi[4], lo[4];
#pragma unroll
    for (int q = 0; q < 4; q++) {
        __half2 hh = __float22half2_rn(make_float2(v[2 * q], v[2 * q + 1]));
        __half2 ll = __float22half2_rn(make_float2(v[2 * q] - __low2float(hh),
                                                   v[2 * q + 1] - __high2float(hh)));
        hi[q] = *(uint32_t*)&hh;
        lo[q] = *(uint32_t*)&ll;
    }
    const uint32_t o = swz(k, h0);
    *(uint4*)(mb + o) = make_uint4(hi[0], hi[1], hi[2], hi[3]);
    *(uint4*)(mb + 32768 + o) = make_uint4(lo[0], lo[1], lo[2], lo[3]);
}

__global__ void __launch_bounds__(512, 1)
k_inter(const float* __restrict__ Wi, const float* __restrict__ bi,
        const float* __restrict__ wpe, const float* __restrict__ bpe,
        const float* __restrict__ wpg, const float* __restrict__ bpg) {
    extern __shared__ char smc[];
    const uint32_t sb = smem_to_u32(smc);
    float* cv = (float*)(smc + SCV);
    float* peb = (float*)(smc + SPE);        // [4][128]
    float* pgb = peb + 512;                  // [4][128]
    float* savbuf = (float*)(smc + SSAV);    // [2][128], pre-scaled by SCALE_B

    const int t = threadIdx.x;
    const int wid = t >> 5;
    const int lane = t & 31;

    const int n = blockIdx.x / 37;
    const int grp = blockIdx.x % 37;
    const int i0 = grp * 28;
    const int cnt = min(28, 1024 - i0);
    const float* atomBase = g_atoms + (n * 1024 + i0) * 128;
    const float bpe0 = bpe[0], bpg0 = bpg[0];

    // ---- prologue: constants + sav(0), sav(1) ----
    if (t < 128) {
        cv[t] = wpe[t];
        cv[128 + t] = wpg[t];
        cv[256 + t] = bi[t];
        savbuf[t] = atomBase[t] * SCALE_B;
    } else if (t < 256) {
        savbuf[128 + (t - 128)] = atomBase[128 + (t - 128)] * SCALE_B;
    }
    __syncthreads();

    // ---- A planes (scaled tok, [j][k]) + M(0) planes ([k][h]) ----
    const float* tokn = g_tok + n * 16384;
    for (int p = t; p < 2048; p += 512) {
        int j = p >> 4, k0 = (p & 15) << 3;
        const float4* xp = (const float4*)(tokn + j * 128 + k0);
        float4 x0 = xp[0], x1 = xp[1];
        float v[8];
        v[0] = x0.x * SCALE_A; v[1] = x0.y * SCALE_A;
        v[2] = x0.z * SCALE_A; v[3] = x0.w * SCALE_A;
        v[4] = x1.x * SCALE_A; v[5] = x1.y * SCALE_A;
        v[6] = x1.z * SCALE_A; v[7] = x1.w * SCALE_A;
        uint32_t hi[4], lo[4];
#pragma unroll
        for (int q = 0; q < 4; q++) {
            __half2 hh = __float22half2_rn(make_float2(v[2 * q], v[2 * q + 1]));
            __half2 ll = __float22half2_rn(make_float2(v[2 * q] - __low2float(hh),
                                                       v[2 * q + 1] - __high2float(hh)));
            hi[q] = *(uint32_t*)&hh;
            lo[q] = *(uint32_t*)&ll;
        }
        uint32_t o = swz(j, k0);
        *(uint4*)(smc + SA_HI + o) = make_uint4(hi[0], hi[1], hi[2], hi[3]);
        *(uint4*)(smc + SA_LO + o) = make_uint4(lo[0], lo[1], lo[2], lo[3]);
    }
    for (int p = t; p < 2048; p += 512) build_oct_t(smc + SMB, Wi, savbuf, p);
    __syncthreads();

    // ---- lane bases. 16 warps: 4 j-tiles x 4 h-groups (32x32 tiles) ----
    const int j0 = (wid & 3) * 32;
    const int h0 = (wid >> 2) * 32;
    // A ([j][k] plane, normal ldsm)
    const int aRowG = j0 + (lane & 15);
    const uint32_t kbA = (uint32_t)(((lane >> 4) << 3) << 1);
    const uint32_t aXor = (uint32_t)((aRowG & 7) << 4);
    const uint32_t aBase = sb + (uint32_t)(((aRowG >> 3) << 10) + ((aRowG & 7) << 7));
    uint32_t alow[4];
#pragma unroll
    for (int c = 0; c < 4; c++) alow[c] = (((uint32_t)c << 5) + kbA) ^ aXor;
    // B ([k][h] plane, trans ldsm): two precomputed swizzled bases per lane
    // (h octet at h0.. and h0+16..). Runtime strides (+ks*2048, +32768 for the
    // lo plane) live in bits >= 11, disjoint from the XOR bits 4-6.
    const int bk = (lane & 7) + (((lane >> 3) & 1) << 3);
    const int bh = h0 + ((lane >> 4) << 3);
    const uint32_t bB0 = swz(bk, bh);
    const uint32_t bB1 = swz(bk, bh + 16);

    for (int a = 0; a < cnt; a++) {
        const uint32_t mB = sb + (uint32_t)(SMB + (a & 1) * MBUF_STRIDE);
        char* mbN = smc + SMB + ((a + 1) & 1) * MBUF_STRIDE;
        const float* savN = savbuf + ((a + 1) & 1) * 128;
        const bool doBuild = (a + 1 < cnt);

        float acc[2][4][4];
#pragma unroll
        for (int mt = 0; mt < 2; mt++)
#pragma unroll
            for (int nt = 0; nt < 4; nt++)
#pragma unroll
                for (int e = 0; e < 4; e++) acc[mt][nt][e] = 0.f;

#pragma unroll
        for (int ks = 0; ks < 8; ks++) {
            const uint32_t pan = (uint32_t)((ks >> 2) << 14);
            const uint32_t ao = pan + alow[ks & 3];
            const uint32_t kstep = (uint32_t)(ks * 2048);
            uint32_t aH[2][4], aL[2][4], bH[2][4], bL[2][4];
            ldsm_x4(aH[0], aBase + SA_HI + ao);
            ldsm_x4(aH[1], aBase + SA_HI + 2048 + ao);
            ldsm_x4(aL[0], aBase + SA_LO + ao);
            ldsm_x4(aL[1], aBase + SA_LO + 2048 + ao);
            ldsm_x4_t(bH[0], mB + bB0 + kstep);            // h0..h0+15
            ldsm_x4_t(bH[1], mB + bB1 + kstep);            // h0+16..h0+31
            ldsm_x4_t(bL[0], mB + 32768 + bB0 + kstep);
            ldsm_x4_t(bL[1], mB + 32768 + bB1 + kstep);
#pragma unroll
            for (int mt = 0; mt < 2; mt++) {
#pragma unroll
                for (int ng = 0; ng < 2; ng++) {
                    mma_f16(acc[mt][2 * ng], aH[mt], bH[ng]);
                    mma_f16(acc[mt][2 * ng + 1], aH[mt], bH[ng] + 2);
                    mma_f16(acc[mt][2 * ng], aH[mt], bL[ng]);
                    mma_f16(acc[mt][2 * ng + 1], aH[mt], bL[ng] + 2);
                    mma_f16(acc[mt][2 * ng], aL[mt], bH[ng]);
                    mma_f16(acc[mt][2 * ng + 1], aL[mt], bH[ng] + 2);
                }
            }
            // pipelined build of M(a+1) into the other buffer (4 octets/thread)
            if (doBuild && (ks & 1) == 0)
                build_oct_t(mbN, Wi, savN, t + ((ks >> 1) << 9));
        }

        // ---- epilogue: unscale + lrelu + pe/pg dots (32 rows x 32 cols) ----
        float pe[4] = {0.f, 0.f, 0.f, 0.f}, pg[4] = {0.f, 0.f, 0.f, 0.f};
#pragma unroll
        for (int nt = 0; nt < 4; nt++) {
#pragma unroll
            for (int c = 0; c < 2; c++) {
                const int h = h0 + 8 * nt + 2 * (lane & 3) + c;
                const float wpeh = cv[h];
                const float wpgh = cv[128 + h];
                const float bih = cv[256 + h];
#pragma unroll
                for (int mt = 0; mt < 2; mt++) {
#pragma unroll
                    for (int hf = 0; hf < 2; hf++) {
                        float v = acc[mt][nt][hf * 2 + c] * SCALE_INV + bih;
                        v = (v > 0.f) ? v : 0.01f * v;
                        pe[mt * 2 + hf] += v * wpeh;
                        pg[mt * 2 + hf] += v * wpgh;
                    }
                }
            }
        }
#pragma unroll
        for (int rs = 0; rs < 4; rs++) {
#pragma unroll
            for (int off = 1; off < 4; off <<= 1) {
                pe[rs] += __shfl_xor_sync(0xffffffffu, pe[rs], off);
                pg[rs] += __shfl_xor_sync(0xffffffffu, pg[rs], off);
            }
        }
        if ((lane & 3) == 0) {
            const int wx = wid >> 2;
#pragma unroll
            for (int mt = 0; mt < 2; mt++)
#pragma unroll
                for (int hf = 0; hf < 2; hf++) {
                    int j = j0 + 16 * mt + 8 * hf + (lane >> 2);
                    peb[wx * 128 + j] = pe[mt * 2 + hf];
                    pgb[wx * 128 + j] = pg[mt * 2 + hf];
                }
        }
        __syncthreads();

        // ---- window: warp0 reduces; warps 1-4 prefetch sav(a+2) ----
        if (wid == 0) {
            float tot = 0.f;
#pragma unroll
            for (int q = 0; q < 4; q++) {
                int j = lane + q * 32;
                float spe = peb[j] + peb[128 + j] + peb[256 + j] + peb[384 + j] + bpe0;
                float spg = pgb[j] + pgb[128 + j] + pgb[256 + j] + pgb[384 + j] + bpg0;
                tot += spe / (1.f + __expf(-spg));
            }
#pragma unroll
            for (int off = 16; off > 0; off >>= 1)
                tot += __shfl_xor_sync(0xffffffffu, tot, off);
            if (lane == 0) g_atom_e[n * 1024 + i0 + a] = tot;
        } else if (wid <= 4 && a + 2 < cnt) {
            // slot (a&1) held sav(a), no longer needed -> load sav(a+2)
            savbuf[(a & 1) * 128 + (t - 32)] = atomBase[(a + 2) * 128 + (t - 32)] * SCALE_B;
        }
        __syncthreads();
    }
}

// ------------------------------ k_final (pf fused) --------------------------
__global__ void k_final(const float* __restrict__ lgr, const int* __restrict__ lb,
                        const float* __restrict__ Wp, const float* __restrict__ bp,
                        const float* __restrict__ Wcat, const float* __restrict__ bcat,
                        const float* __restrict__ Wgate, const float* __restrict__ bgate,
                        const float* __restrict__ Wgr, const float* __restrict__ bgr,
                        const float* __restrict__ Wb1, const float* __restrict__ bb1,
                        const float* __restrict__ Wb2, const float* __restrict__ bb2,
                        float* __restrict__ out) {
    int n = blockIdx.x >> 6, g = blockIdx.x & 63, t = threadIdx.x;
    __shared__ float sp[256];
    __shared__ float pin[384];
    __shared__ float z[256];
    __shared__ float lg[64];
    __shared__ float red[8];

    for (int c = t; c < 256; c += 128) sp[c] = silu_f(g_p[n * 256 + c]);
    if (t < 64) lg[t] = lgr[(n * 64 + g) * 64 + t];
    float ts = 0.f;
    for (int j = 0; j < 128; j++) ts += g_tok[(n * 128 + j) * 128 + t];
    __syncthreads();
    float pk = bp[t];
#pragma unroll 4
    for (int c = 0; c < 256; c++) pk += sp[c] * Wp[c * 128 + t];
    pin[t] = pk;
    pin[128 + t] = ts;
    pin[256 + t] = ts * (1.f / 128.f);
    __syncthreads();
    float c1 = bcat[t], g1 = bgate[t];
#pragma unroll 4
    for (int c = 0; c < 384; c++) {
        float zz = pin[c];
        c1 += zz * Wcat[c * 128 + t];
        g1 += zz * Wgate[c * 128 + t];
    }
    z[t] = c1 / (1.f + __expf(-g1));   // pf

    float gf = bgr[t];
#pragma unroll 4
    for (int c = 0; c < 64; c++) gf += lg[c] * Wgr[c * 128 + t];
    z[128 + t] = gf;
    __syncthreads();

    float h = bb1[t];
#pragma unroll 4
    for (int c = 0; c < 256; c++) h += z[c] * Wb1[c * 128 + t];
    h = (h > 0.f) ? h : 0.01f * h;
    float part = h * Wb2[t];
    float seg = 0.f;
    for (int a = t; a < 1024; a += 128) {
        if (lb[a] == g) seg += g_atom_e[n * 1024 + a];
    }
#pragma unroll
    for (int off = 16; off > 0; off >>= 1) {
        part += __shfl_down_sync(0xffffffffu, part, off);
        seg += __shfl_down_sync(0xffffffffu, seg, off);
    }
    int wid = t >> 5;
    if ((t & 31) == 0) {
        red[wid] = part;
        red[4 + wid] = seg;
    }
    __syncthreads();
    if (t == 0) {
        float bias = red[0] + red[1] + red[2] + red[3] + bb2[0];
        float segs = red[4] + red[5] + red[6] + red[7];
        out[n * 64 + g] = segs + bias;
    }
}

// ------------------------------ launch --------------------------------------
extern "C" void kernel_launch(void* const* d_in, const int* in_sizes, int n_in,
                              void* d_out, int out_size) {
    const float* ms0 = (const float*)d_in[0];
    const float* ms1 = (const float*)d_in[1];
    const float* tf = (const float*)d_in[2];
    const float* lat = (const float*)d_in[3];
    const float* lgr = (const float*)d_in[4];
    const int* lb = (const int*)d_in[5];
    const float* Wt = (const float*)d_in[6];
    const float* bt = (const float*)d_in[7];
    const float* Wc0 = (const float*)d_in[8];
    const float* bc0 = (const float*)d_in[9];
    const float* Wc1 = (const float*)d_in[10];
    const float* bc1 = (const float*)d_in[11];
    const float* Wp = (const float*)d_in[12];
    const float* bp = (const float*)d_in[13];
    const float* Wcat = (const float*)d_in[14];
    const float* bcat = (const float*)d_in[15];
    const float* Wgate = (const float*)d_in[16];
    const float* bgate = (const float*)d_in[17];
    const float* Wa = (const float*)d_in[18];
    const float* ba = (const float*)d_in[19];
    const float* Wgr = (const float*)d_in[20];
    const float* bgr = (const float*)d_in[21];
    const float* Wb1 = (const float*)d_in[22];
    const float* bb1 = (const float*)d_in[23];
    const float* Wb2 = (const float*)d_in[24];
    const float* bb2 = (const float*)d_in[25];
    const float* Wi = (const float*)d_in[26];
    const float* bi = (const float*)d_in[27];
    const float* wpe = (const float*)d_in[28];
    const float* bpe = (const float*)d_in[29];
    const float* wpg = (const float*)d_in[30];
    const float* bpg = (const float*)d_in[31];
    float* out = (float*)d_out;

    k_tokatoms<<<1024, 128>>>(tf, Wt, bt, lat, Wa, ba);
    k_ms<<<384, 256>>>(ms1, ms0);
    k_pconv<<<128, 256>>>(Wc0, bc0, Wc1, bc1);

    cudaFuncSetAttribute(k_inter, cudaFuncAttributeMaxDynamicSharedMemorySize,
                         SMEM_TC_BYTES);
    k_inter<<<148, 512, SMEM_TC_BYTES>>>(Wi, bi, wpe, bpe, wpg, bpg);

    k_final<<<256, 128>>>(lgr, lb, Wp, bp, Wcat, bcat, Wgate, bgate,
                          Wgr, bgr, Wb1, bb1, Wb2, bb2, out);
}

// round 13
// speedup vs baseline: 1.1109x; 1.0275x over previous
#include <cuda_runtime.h>
#include <cuda_fp16.h>
#include <cstdint>

// ---------------------------------------------------------------------------
// AffinityHead — mma.sync fp16x3 split GEMM core (k_inter unchanged from R12).
// R13: stream fork/join — k_ms/k_pconv run on a side stream concurrently with
// k_tokatoms/k_inter; k_final joins. k_ms/k_pconv reg-capped (32) so they can
// co-reside with k_inter's fat CTA.
// ---------------------------------------------------------------------------

__device__ __forceinline__ float silu_f(float v) { return v / (1.f + __expf(-v)); }

// ------------------------- scratch (static, no allocs) ---------------------
__device__ float g_tok[4 * 128 * 128];     // [n][j][h]
__device__ float g_S1[4 * 64 * 27];
__device__ float g_S0[4 * 32 * 27];
__device__ float g_p[4 * 256];
__device__ float g_atoms[4 * 1024 * 128];  // [n][i][k]
__device__ float g_atom_e[4 * 1024];

// ------------------------------ PTX helpers --------------------------------
__device__ __forceinline__ uint32_t smem_to_u32(const void* p) {
    uint32_t a;
    asm("{ .reg .u64 t; cvta.to.shared.u64 t, %1; cvt.u32.u64 %0, t; }" : "=r"(a) : "l"(p));
    return a;
}

__device__ __forceinline__ void ldsm_x4(uint32_t* r, uint32_t addr) {
    asm volatile("ldmatrix.sync.aligned.m8n8.x4.shared.b16 {%0,%1,%2,%3}, [%4];"
                 : "=r"(r[0]), "=r"(r[1]), "=r"(r[2]), "=r"(r[3]) : "r"(addr));
}

__device__ __forceinline__ void ldsm_x4_t(uint32_t* r, uint32_t addr) {
    asm volatile("ldmatrix.sync.aligned.m8n8.x4.trans.shared.b16 {%0,%1,%2,%3}, [%4];"
                 : "=r"(r[0]), "=r"(r[1]), "=r"(r[2]), "=r"(r[3]) : "r"(addr));
}

__device__ __forceinline__ void mma_f16(float* d, const uint32_t* a, const uint32_t* b) {
    asm volatile(
        "mma.sync.aligned.m16n8k16.row.col.f32.f16.f16.f32 "
        "{%0,%1,%2,%3}, {%4,%5,%6,%7}, {%8,%9}, {%0,%1,%2,%3};"
        : "+f"(d[0]), "+f"(d[1]), "+f"(d[2]), "+f"(d[3])
        : "r"(a[0]), "r"(a[1]), "r"(a[2]), "r"(a[3]), "r"(b[0]), "r"(b[1]));
}

// SW128 blocked-atom swizzled byte offset for a [128 rows][128 halves] plane.
__device__ __forceinline__ uint32_t swz(int row, int k) {
    uint32_t off = (uint32_t)(((k >> 6) << 14) + ((row >> 3) << 10) +
                              ((row & 7) << 7) + ((k & 63) << 1));
    return off ^ (uint32_t)((row & 7) << 4);
}

// ------------------------------ k_tokatoms ----------------------------------
__global__ void k_tokatoms(const float* __restrict__ tf, const float* __restrict__ Wt,
                           const float* __restrict__ bt, const float* __restrict__ la,
                           const float* __restrict__ Wa, const float* __restrict__ ba) {
    __shared__ float s[512];
    const int t = threadIdx.x;
    if (blockIdx.x < 512) {
        const int row = blockIdx.x;
        const float* x = tf + row * 256;
        for (int c = t; c < 256; c += 128) s[c] = silu_f(x[c]);
        __syncthreads();
        float acc = bt[t];
#pragma unroll 8
        for (int c = 0; c < 256; c++) acc += s[c] * Wt[c * 128 + t];
        g_tok[row * 128 + t] = acc;
    } else {
        const int r0 = (blockIdx.x - 512) * 8;
        for (int i = t; i < 512; i += 128) s[i] = la[r0 * 64 + i];
        __syncthreads();
        float b = ba[t];
        float acc[8];
#pragma unroll
        for (int r = 0; r < 8; r++) acc[r] = b;
        for (int c = 0; c < 64; c++) {
            float w = Wa[c * 128 + t];
#pragma unroll
            for (int r = 0; r < 8; r++) acc[r] += s[(r << 6) + c] * w;
        }
#pragma unroll
        for (int r = 0; r < 8; r++) g_atoms[(r0 + r) * 128 + t] = acc[r];
    }
}

// ------------------------------ k_ms (S1 + S0) ------------------------------
__global__ void __launch_bounds__(256, 8)
k_ms(const float* __restrict__ ms1, const float* __restrict__ ms0) {
    __shared__ float v[4096];
    const int t = threadIdx.x;
    const int w = t >> 5, lane = t & 31;
    const int b = blockIdx.x;
    if (b < 256) {
        for (int i = t; i < 512; i += 256) v[i] = silu_f(ms1[b * 512 + i]);
        __syncthreads();
        for (int k = w; k < 27; k += 8) {
            int kd = k / 9, kh = (k / 3) % 3, kw = k % 3;
            float s = 0.f;
            for (int i = lane; i < 216; i += 32) {
                int d = i / 36, r = i % 36, hh = r / 6, ww = r % 6;
                s += v[(d + kd) * 64 + (hh + kh) * 8 + (ww + kw)];
            }
#pragma unroll
            for (int off = 16; off > 0; off >>= 1)
                s += __shfl_down_sync(0xffffffffu, s, off);
            if (lane == 0) g_S1[b * 27 + k] = s;
        }
    } else {
        const int nc = b - 256;
        for (int i = t; i < 4096; i += 256) v[i] = silu_f(ms0[nc * 4096 + i]);
        __syncthreads();
        for (int k = w; k < 27; k += 8) {
            int kd = k / 9, kh = (k / 3) % 3, kw = k % 3;
            float s = 0.f;
            for (int i = lane; i < 2744; i += 32) {
                int d = i / 196, r = i % 196, hh = r / 14, ww = r % 14;
                s += v[(d + kd) * 256 + (hh + kh) * 16 + (ww + kw)];
            }
#pragma unroll
            for (int off = 16; off > 0; off >>= 1)
                s += __shfl_down_sync(0xffffffffu, s, off);
            if (lane == 0) g_S0[nc * 27 + k] = s;
        }
    }
}

// ------------------------------ k_pconv (warp-per-output) -------------------
__global__ void __launch_bounds__(256, 8)
k_pconv(const float* __restrict__ Wc0, const float* __restrict__ bc0,
        const float* __restrict__ Wc1, const float* __restrict__ bc1) {
    __shared__ float s[1728];
    const int t = threadIdx.x, w = t >> 5, lane = t & 31;
    int b = blockIdx.x;   // 128 blocks x 256 threads
    if (b < 64) {
        int n = b >> 4, o = (b & 15) * 8 + w;
        for (int i = t; i < 1728; i += 256) s[i] = g_S1[n * 1728 + i];
        __syncthreads();
        float a = 0.f;
        for (int x = lane; x < 1728; x += 32) a += s[x] * Wc0[o * 1728 + x];
#pragma unroll
        for (int off = 16; off > 0; off >>= 1)
            a += __shfl_down_sync(0xffffffffu, a, off);
        if (lane == 0) g_p[n * 256 + o] = a * (1.f / 216.f) + bc0[o];
    } else {
        b -= 64;
        int n = b >> 4, o = (b & 15) * 8 + w;
        for (int i = t; i < 864; i += 256) s[i] = g_S0[n * 864 + i];
        __syncthreads();
        float a = 0.f;
        for (int x = lane; x < 864; x += 32) a += s[x] * Wc1[o * 864 + x];
#pragma unroll
        for (int off = 16; off > 0; off >>= 1)
            a += __shfl_down_sync(0xffffffffu, a, off);
        if (lane == 0) g_p[n * 256 + 128 + o] = a * (1.f / 2744.f) + bc1[o];
    }
}

// ------------------------------ k_inter -------------------------------------
// smem: A hi/lo (32768 each) | M buf0 hi/lo | M buf1 hi/lo | cv | peb/pgb | sav
#define SA_HI 0
#define SA_LO 32768
#define SMB 65536
#define MBUF_STRIDE 65536     // per buffer: hi at +0, lo at +32768
#define SCV 196608            // wpe|wpg|bi : 1536
#define SPE 198144            // peb/pgb [4][128] each : 4096
#define SSAV 202240           // [2][128] : 1024
#define SMEM_TC_BYTES 203264

#define SCALE_A 16.f
#define SCALE_B 256.f
#define SCALE_INV (1.f / 4096.f)

// Build one octet (8 h-values at one k) of M = diag(sav)*W into [k][h] planes.
// Reads Wi straight from global (L2-resident, 32B coalesced per lane).
__device__ __forceinline__ void build_oct_t(char* mb, const float* __restrict__ Wi,
                                            const float* __restrict__ sav, int p) {
    const int k = p >> 4, h0 = (p & 15) << 3;
    const float s = sav[k];
    const float4* wp = (const float4*)(Wi + k * 128 + h0);
    const float4 w0 = wp[0], w1 = wp[1];
    float v[8];
    v[0] = s * w0.x; v[1] = s * w0.y; v[2] = s * w0.z; v[3] = s * w0.w;
    v[4] = s * w1.x; v[5] = s * w1.y; v[6] = s * w1.z; v[7] = s * w1.w;
    uint32_t hi[4], lo[4];
#pragma unroll
    for (int q = 0; q < 4; q++) {
        __half2 hh = __float22half2_rn(make_float2(v[2 * q], v[2 * q + 1]));
        __half2 ll = __float22half2_rn(make_float2(v[2 * q] - __low2float(hh),
                                                   v[2 * q + 1] - __high2float(hh)));
        hi[q] = *(uint32_t*)&hh;
        lo[q] = *(uint32_t*)&ll;
    }
    const uint32_t o = swz(k, h0);
    *(uint4*)(mb + o) = make_uint4(hi[0], hi[1], hi[2], hi[3]);
    *(uint4*)(mb + 32768 + o) = make_uint4(lo[0], lo[1], lo[2], lo[3]);
}

__global__ void __launch_bounds__(512, 1)
k_inter(const float* __restrict__ Wi, const float* __restrict__ bi,
        const float* __restrict__ wpe, const float* __restrict__ bpe,
        const float* __restrict__ wpg, const float* __restrict__ bpg) {
    extern __shared__ char smc[];
    const uint32_t sb = smem_to_u32(smc);
    float* cv = (float*)(smc + SCV);
    float* peb = (float*)(smc + SPE);        // [4][128]
    float* pgb = peb + 512;                  // [4][128]
    float* savbuf = (float*)(smc + SSAV);    // [2][128], pre-scaled by SCALE_B

    const int t = threadIdx.x;
    const int wid = t >> 5;
    const int lane = t & 31;

    const int n = blockIdx.x / 37;
    const int grp = blockIdx.x % 37;
    const int i0 = grp * 28;
    const int cnt = min(28, 1024 - i0);
    const float* atomBase = g_atoms + (n * 1024 + i0) * 128;
    const float bpe0 = bpe[0], bpg0 = bpg[0];

    // ---- prologue: constants + sav(0), sav(1) ----
    if (t < 128) {
        cv[t] = wpe[t];
        cv[128 + t] = wpg[t];
        cv[256 + t] = bi[t];
        savbuf[t] = atomBase[t] * SCALE_B;
    } else if (t < 256) {
        savbuf[128 + (t - 128)] = atomBase[128 + (t - 128)] * SCALE_B;
    }
    __syncthreads();

    // ---- A planes (scaled tok, [j][k]) + M(0) planes ([k][h]) ----
    const float* tokn = g_tok + n * 16384;
    for (int p = t; p < 2048; p += 512) {
        int j = p >> 4, k0 = (p & 15) << 3;
        const float4* xp = (const float4*)(tokn + j * 128 + k0);
        float4 x0 = xp[0], x1 = xp[1];
        float v[8];
        v[0] = x0.x * SCALE_A; v[1] = x0.y * SCALE_A;
        v[2] = x0.z * SCALE_A; v[3] = x0.w * SCALE_A;
        v[4] = x1.x * SCALE_A; v[5] = x1.y * SCALE_A;
        v[6] = x1.z * SCALE_A; v[7] = x1.w * SCALE_A;
        uint32_t hi[4], lo[4];
#pragma unroll
        for (int q = 0; q < 4; q++) {
            __half2 hh = __float22half2_rn(make_float2(v[2 * q], v[2 * q + 1]));
            __half2 ll = __float22half2_rn(make_float2(v[2 * q] - __low2float(hh),
                                                       v[2 * q + 1] - __high2float(hh)));
            hi[q] = *(uint32_t*)&hh;
            lo[q] = *(uint32_t*)&ll;
        }
        uint32_t o = swz(j, k0);
        *(uint4*)(smc + SA_HI + o) = make_uint4(hi[0], hi[1], hi[2], hi[3]);
        *(uint4*)(smc + SA_LO + o) = make_uint4(lo[0], lo[1], lo[2], lo[3]);
    }
    for (int p = t; p < 2048; p += 512) build_oct_t(smc + SMB, Wi, savbuf, p);
    __syncthreads();

    // ---- lane bases. 16 warps: 4 j-tiles x 4 h-groups (32x32 tiles) ----
    const int j0 = (wid & 3) * 32;
    const int h0 = (wid >> 2) * 32;
    // A ([j][k] plane, normal ldsm)
    const int aRowG = j0 + (lane & 15);
    const uint32_t kbA = (uint32_t)(((lane >> 4) << 3) << 1);
    const uint32_t aXor = (uint32_t)((aRowG & 7) << 4);
    const uint32_t aBase = sb + (uint32_t)(((aRowG >> 3) << 10) + ((aRowG & 7) << 7));
    uint32_t alow[4];
#pragma unroll
    for (int c = 0; c < 4; c++) alow[c] = (((uint32_t)c << 5) + kbA) ^ aXor;
    // B ([k][h] plane, trans ldsm): two precomputed swizzled bases per lane
    // (h octet at h0.. and h0+16..). Runtime strides (+ks*2048, +32768 for the
    // lo plane) live in bits >= 11, disjoint from the XOR bits 4-6.
    const int bk = (lane & 7) + (((lane >> 3) & 1) << 3);
    const int bh = h0 + ((lane >> 4) << 3);
    const uint32_t bB0 = swz(bk, bh);
    const uint32_t bB1 = swz(bk, bh + 16);

    for (int a = 0; a < cnt; a++) {
        const uint32_t mB = sb + (uint32_t)(SMB + (a & 1) * MBUF_STRIDE);
        char* mbN = smc + SMB + ((a + 1) & 1) * MBUF_STRIDE;
        const float* savN = savbuf + ((a + 1) & 1) * 128;
        const bool doBuild = (a + 1 < cnt);

        float acc[2][4][4];
#pragma unroll
        for (int mt = 0; mt < 2; mt++)
#pragma unroll
            for (int nt = 0; nt < 4; nt++)
#pragma unroll
                for (int e = 0; e < 4; e++) acc[mt][nt][e] = 0.f;

#pragma unroll
        for (int ks = 0; ks < 8; ks++) {
            const uint32_t pan = (uint32_t)((ks >> 2) << 14);
            const uint32_t ao = pan + alow[ks & 3];
            const uint32_t kstep = (uint32_t)(ks * 2048);
            uint32_t aH[2][4], aL[2][4], bH[2][4], bL[2][4];
            ldsm_x4(aH[0], aBase + SA_HI + ao);
            ldsm_x4(aH[1], aBase + SA_HI + 2048 + ao);
            ldsm_x4(aL[0], aBase + SA_LO + ao);
            ldsm_x4(aL[1], aBase + SA_LO + 2048 + ao);
            ldsm_x4_t(bH[0], mB + bB0 + kstep);            // h0..h0+15
            ldsm_x4_t(bH[1], mB + bB1 + kstep);            // h0+16..h0+31
            ldsm_x4_t(bL[0], mB + 32768 + bB0 + kstep);
            ldsm_x4_t(bL[1], mB + 32768 + bB1 + kstep);
#pragma unroll
            for (int mt = 0; mt < 2; mt++) {
#pragma unroll
                for (int ng = 0; ng < 2; ng++) {
                    mma_f16(acc[mt][2 * ng], aH[mt], bH[ng]);
                    mma_f16(acc[mt][2 * ng + 1], aH[mt], bH[ng] + 2);
                    mma_f16(acc[mt][2 * ng], aH[mt], bL[ng]);
                    mma_f16(acc[mt][2 * ng + 1], aH[mt], bL[ng] + 2);
                    mma_f16(acc[mt][2 * ng], aL[mt], bH[ng]);
                    mma_f16(acc[mt][2 * ng + 1], aL[mt], bH[ng] + 2);
                }
            }
            // pipelined build of M(a+1) into the other buffer (4 octets/thread)
            if (doBuild && (ks & 1) == 0)
                build_oct_t(mbN, Wi, savN, t + ((ks >> 1) << 9));
        }

        // ---- epilogue: unscale + lrelu + pe/pg dots (32 rows x 32 cols) ----
        float pe[4] = {0.f, 0.f, 0.f, 0.f}, pg[4] = {0.f, 0.f, 0.f, 0.f};
#pragma unroll
        for (int nt = 0; nt < 4; nt++) {
#pragma unroll
            for (int c = 0; c < 2; c++) {
                const int h = h0 + 8 * nt + 2 * (lane & 3) + c;
                const float wpeh = cv[h];
                const float wpgh = cv[128 + h];
                const float bih = cv[256 + h];
#pragma unroll
                for (int mt = 0; mt < 2; mt++) {
#pragma unroll
                    for (int hf = 0; hf < 2; hf++) {
                        float v = acc[mt][nt][hf * 2 + c] * SCALE_INV + bih;
                        v = (v > 0.f) ? v : 0.01f * v;
                        pe[mt * 2 + hf] += v * wpeh;
                        pg[mt * 2 + hf] += v * wpgh;
                    }
                }
            }
        }
#pragma unroll
        for (int rs = 0; rs < 4; rs++) {
#pragma unroll
            for (int off = 1; off < 4; off <<= 1) {
                pe[rs] += __shfl_xor_sync(0xffffffffu, pe[rs], off);
                pg[rs] += __shfl_xor_sync(0xffffffffu, pg[rs], off);
            }
        }
        if ((lane & 3) == 0) {
            const int wx = wid >> 2;
#pragma unroll
            for (int mt = 0; mt < 2; mt++)
#pragma unroll
                for (int hf = 0; hf < 2; hf++) {
                    int j = j0 + 16 * mt + 8 * hf + (lane >> 2);
                    peb[wx * 128 + j] = pe[mt * 2 + hf];
                    pgb[wx * 128 + j] = pg[mt * 2 + hf];
                }
        }
        __syncthreads();

        // ---- window: warp0 reduces; warps 1-4 prefetch sav(a+2) ----
        if (wid == 0) {
            float tot = 0.f;
#pragma unroll
            for (int q = 0; q < 4; q++) {
                int j = lane + q * 32;
                float spe = peb[j] + peb[128 + j] + peb[256 + j] + peb[384 + j] + bpe0;
                float spg = pgb[j] + pgb[128 + j] + pgb[256 + j] + pgb[384 + j] + bpg0;
                tot += spe / (1.f + __expf(-spg));
            }
#pragma unroll
            for (int off = 16; off > 0; off >>= 1)
                tot += __shfl_xor_sync(0xffffffffu, tot, off);
            if (lane == 0) g_atom_e[n * 1024 + i0 + a] = tot;
        } else if (wid <= 4 && a + 2 < cnt) {
            // slot (a&1) held sav(a), no longer needed -> load sav(a+2)
            savbuf[(a & 1) * 128 + (t - 32)] = atomBase[(a + 2) * 128 + (t - 32)] * SCALE_B;
        }
        __syncthreads();
    }
}

// ------------------------------ k_final (pf fused) --------------------------
__global__ void k_final(const float* __restrict__ lgr, const int* __restrict__ lb,
                        const float* __restrict__ Wp, const float* __restrict__ bp,
                        const float* __restrict__ Wcat, const float* __restrict__ bcat,
                        const float* __restrict__ Wgate, const float* __restrict__ bgate,
                        const float* __restrict__ Wgr, const float* __restrict__ bgr,
                        const float* __restrict__ Wb1, const float* __restrict__ bb1,
                        const float* __restrict__ Wb2, const float* __restrict__ bb2,
                        float* __restrict__ out) {
    int n = blockIdx.x >> 6, g = blockIdx.x & 63, t = threadIdx.x;
    __shared__ float sp[256];
    __shared__ float pin[384];
    __shared__ float z[256];
    __shared__ float lg[64];
    __shared__ float red[8];

    for (int c = t; c < 256; c += 128) sp[c] = silu_f(g_p[n * 256 + c]);
    if (t < 64) lg[t] = lgr[(n * 64 + g) * 64 + t];
    float ts = 0.f;
    for (int j = 0; j < 128; j++) ts += g_tok[(n * 128 + j) * 128 + t];
    __syncthreads();
    float pk = bp[t];
#pragma unroll 4
    for (int c = 0; c < 256; c++) pk += sp[c] * Wp[c * 128 + t];
    pin[t] = pk;
    pin[128 + t] = ts;
    pin[256 + t] = ts * (1.f / 128.f);
    __syncthreads();
    float c1 = bcat[t], g1 = bgate[t];
#pragma unroll 4
    for (int c = 0; c < 384; c++) {
        float zz = pin[c];
        c1 += zz * Wcat[c * 128 + t];
        g1 += zz * Wgate[c * 128 + t];
    }
    z[t] = c1 / (1.f + __expf(-g1));   // pf

    float gf = bgr[t];
#pragma unroll 4
    for (int c = 0; c < 64; c++) gf += lg[c] * Wgr[c * 128 + t];
    z[128 + t] = gf;
    __syncthreads();

    float h = bb1[t];
#pragma unroll 4
    for (int c = 0; c < 256; c++) h += z[c] * Wb1[c * 128 + t];
    h = (h > 0.f) ? h : 0.01f * h;
    float part = h * Wb2[t];
    float seg = 0.f;
    for (int a = t; a < 1024; a += 128) {
        if (lb[a] == g) seg += g_atom_e[n * 1024 + a];
    }
#pragma unroll
    for (int off = 16; off > 0; off >>= 1) {
        part += __shfl_down_sync(0xffffffffu, part, off);
        seg += __shfl_down_sync(0xffffffffu, seg, off);
    }
    int wid = t >> 5;
    if ((t & 31) == 0) {
        red[wid] = part;
        red[4 + wid] = seg;
    }
    __syncthreads();
    if (t == 0) {
        float bias = red[0] + red[1] + red[2] + red[3] + bb2[0];
        float segs = red[4] + red[5] + red[6] + red[7];
        out[n * 64 + g] = segs + bias;
    }
}

// ------------------------------ launch --------------------------------------
extern "C" void kernel_launch(void* const* d_in, const int* in_sizes, int n_in,
                              void* d_out, int out_size) {
    const float* ms0 = (const float*)d_in[0];
    const float* ms1 = (const float*)d_in[1];
    const float* tf = (const float*)d_in[2];
    const float* lat = (const float*)d_in[3];
    const float* lgr = (const float*)d_in[4];
    const int* lb = (const int*)d_in[5];
    const float* Wt = (const float*)d_in[6];
    const float* bt = (const float*)d_in[7];
    const float* Wc0 = (const float*)d_in[8];
    const float* bc0 = (const float*)d_in[9];
    const float* Wc1 = (const float*)d_in[10];
    const float* bc1 = (const float*)d_in[11];
    const float* Wp = (const float*)d_in[12];
    const float* bp = (const float*)d_in[13];
    const float* Wcat = (const float*)d_in[14];
    const float* bcat = (const float*)d_in[15];
    const float* Wgate = (const float*)d_in[16];
    const float* bgate = (const float*)d_in[17];
    const float* Wa = (const float*)d_in[18];
    const float* ba = (const float*)d_in[19];
    const float* Wgr = (const float*)d_in[20];
    const float* bgr = (const float*)d_in[21];
    const float* Wb1 = (const float*)d_in[22];
    const float* bb1 = (const float*)d_in[23];
    const float* Wb2 = (const float*)d_in[24];
    const float* bb2 = (const float*)d_in[25];
    const float* Wi = (const float*)d_in[26];
    const float* bi = (const float*)d_in[27];
    const float* wpe = (const float*)d_in[28];
    const float* bpe = (const float*)d_in[29];
    const float* wpg = (const float*)d_in[30];
    const float* bpg = (const float*)d_in[31];
    float* out = (float*)d_out;

    // One-time side-stream/event creation (first call is the non-captured
    // correctness run; captured calls reuse the same handles -> identical work).
    static cudaStream_t s2 = nullptr;
    static cudaEvent_t evFork = nullptr, evJoin = nullptr;
    if (s2 == nullptr) {
        cudaStreamCreateWithFlags(&s2, cudaStreamNonBlocking);
        cudaEventCreateWithFlags(&evFork, cudaEventDisableTiming);
        cudaEventCreateWithFlags(&evJoin, cudaEventDisableTiming);
        cudaFuncSetAttribute(k_inter, cudaFuncAttributeMaxDynamicSharedMemorySize,
                             SMEM_TC_BYTES);
    }

    // Fork: side stream runs the pocket branch concurrently with tok/atoms+GEMM.
    cudaEventRecord(evFork, 0);
    cudaStreamWaitEvent(s2, evFork, 0);
    k_ms<<<384, 256, 0, s2>>>(ms1, ms0);
    k_pconv<<<128, 256, 0, s2>>>(Wc0, bc0, Wc1, bc1);

    k_tokatoms<<<1024, 128>>>(tf, Wt, bt, lat, Wa, ba);
    k_inter<<<148, 512, SMEM_TC_BYTES>>>(Wi, bi, wpe, bpe, wpg, bpg);

    // Join, then the output head.
    cudaEventRecord(evJoin, s2);
    cudaStreamWaitEvent(0, evJoin, 0);
    k_final<<<256, 128>>>(lgr, lb, Wp, bp, Wcat, bcat, Wgate, bgate,
                          Wgr, bgr, Wb1, bb1, Wb2, bb2, out);
}

// round 14
// speedup vs baseline: 1.1239x; 1.0117x over previous
#include <cuda_runtime.h>
#include <cuda_fp16.h>
#include <cstdint>

// ---------------------------------------------------------------------------
// AffinityHead — mma.sync fp16x3 split GEMM core.
// R14: k_inter tail surgery — (1) M-build LDGs issued before the HMMA block
// and consumed after it (latency hidden in-warp), (2) per-atom reduction
// parallelized across all 16 warps with the final 16-sum off the critical
// path. Stream fork/join for the pocket branch kept from R13.
// ---------------------------------------------------------------------------

__device__ __forceinline__ float silu_f(float v) { return v / (1.f + __expf(-v)); }

// ------------------------- scratch (static, no allocs) ---------------------
__device__ float g_tok[4 * 128 * 128];     // [n][j][h]
__device__ float g_S1[4 * 64 * 27];
__device__ float g_S0[4 * 32 * 27];
__device__ float g_p[4 * 256];
__device__ float g_atoms[4 * 1024 * 128];  // [n][i][k]
__device__ float g_atom_e[4 * 1024];

// ------------------------------ PTX helpers --------------------------------
__device__ __forceinline__ uint32_t smem_to_u32(const void* p) {
    uint32_t a;
    asm("{ .reg .u64 t; cvta.to.shared.u64 t, %1; cvt.u32.u64 %0, t; }" : "=r"(a) : "l"(p));
    return a;
}

__device__ __forceinline__ void ldsm_x4(uint32_t* r, uint32_t addr) {
    asm volatile("ldmatrix.sync.aligned.m8n8.x4.shared.b16 {%0,%1,%2,%3}, [%4];"
                 : "=r"(r[0]), "=r"(r[1]), "=r"(r[2]), "=r"(r[3]) : "r"(addr));
}

__device__ __forceinline__ void ldsm_x4_t(uint32_t* r, uint32_t addr) {
    asm volatile("ldmatrix.sync.aligned.m8n8.x4.trans.shared.b16 {%0,%1,%2,%3}, [%4];"
                 : "=r"(r[0]), "=r"(r[1]), "=r"(r[2]), "=r"(r[3]) : "r"(addr));
}

__device__ __forceinline__ void mma_f16(float* d, const uint32_t* a, const uint32_t* b) {
    asm volatile(
        "mma.sync.aligned.m16n8k16.row.col.f32.f16.f16.f32 "
        "{%0,%1,%2,%3}, {%4,%5,%6,%7}, {%8,%9}, {%0,%1,%2,%3};"
        : "+f"(d[0]), "+f"(d[1]), "+f"(d[2]), "+f"(d[3])
        : "r"(a[0]), "r"(a[1]), "r"(a[2]), "r"(a[3]), "r"(b[0]), "r"(b[1]));
}

// SW128 blocked-atom swizzled byte offset for a [128 rows][128 halves] plane.
__device__ __forceinline__ uint32_t swz(int row, int k) {
    uint32_t off = (uint32_t)(((k >> 6) << 14) + ((row >> 3) << 10) +
                              ((row & 7) << 7) + ((k & 63) << 1));
    return off ^ (uint32_t)((row & 7) << 4);
}

// ------------------------------ k_tokatoms ----------------------------------
__global__ void k_tokatoms(const float* __restrict__ tf, const float* __restrict__ Wt,
                           const float* __restrict__ bt, const float* __restrict__ la,
                           const float* __restrict__ Wa, const float* __restrict__ ba) {
    __shared__ float s[512];
    const int t = threadIdx.x;
    if (blockIdx.x < 512) {
        const int row = blockIdx.x;
        const float* x = tf + row * 256;
        for (int c = t; c < 256; c += 128) s[c] = silu_f(x[c]);
        __syncthreads();
        float acc = bt[t];
#pragma unroll 8
        for (int c = 0; c < 256; c++) acc += s[c] * Wt[c * 128 + t];
        g_tok[row * 128 + t] = acc;
    } else {
        const int r0 = (blockIdx.x - 512) * 8;
        for (int i = t; i < 512; i += 128) s[i] = la[r0 * 64 + i];
        __syncthreads();
        float b = ba[t];
        float acc[8];
#pragma unroll
        for (int r = 0; r < 8; r++) acc[r] = b;
        for (int c = 0; c < 64; c++) {
            float w = Wa[c * 128 + t];
#pragma unroll
            for (int r = 0; r < 8; r++) acc[r] += s[(r << 6) + c] * w;
        }
#pragma unroll
        for (int r = 0; r < 8; r++) g_atoms[(r0 + r) * 128 + t] = acc[r];
    }
}

// ------------------------------ k_ms (S1 + S0) ------------------------------
__global__ void __launch_bounds__(256, 8)
k_ms(const float* __restrict__ ms1, const float* __restrict__ ms0) {
    __shared__ float v[4096];
    const int t = threadIdx.x;
    const int w = t >> 5, lane = t & 31;
    const int b = blockIdx.x;
    if (b < 256) {
        for (int i = t; i < 512; i += 256) v[i] = silu_f(ms1[b * 512 + i]);
        __syncthreads();
        for (int k = w; k < 27; k += 8) {
            int kd = k / 9, kh = (k / 3) % 3, kw = k % 3;
            float s = 0.f;
            for (int i = lane; i < 216; i += 32) {
                int d = i / 36, r = i % 36, hh = r / 6, ww = r % 6;
                s += v[(d + kd) * 64 + (hh + kh) * 8 + (ww + kw)];
            }
#pragma unroll
            for (int off = 16; off > 0; off >>= 1)
                s += __shfl_down_sync(0xffffffffu, s, off);
            if (lane == 0) g_S1[b * 27 + k] = s;
        }
    } else {
        const int nc = b - 256;
        for (int i = t; i < 4096; i += 256) v[i] = silu_f(ms0[nc * 4096 + i]);
        __syncthreads();
        for (int k = w; k < 27; k += 8) {
            int kd = k / 9, kh = (k / 3) % 3, kw = k % 3;
            float s = 0.f;
            for (int i = lane; i < 2744; i += 32) {
                int d = i / 196, r = i % 196, hh = r / 14, ww = r % 14;
                s += v[(d + kd) * 256 + (hh + kh) * 16 + (ww + kw)];
            }
#pragma unroll
            for (int off = 16; off > 0; off >>= 1)
                s += __shfl_down_sync(0xffffffffu, s, off);
            if (lane == 0) g_S0[nc * 27 + k] = s;
        }
    }
}

// ------------------------------ k_pconv (warp-per-output) -------------------
__global__ void __launch_bounds__(256, 8)
k_pconv(const float* __restrict__ Wc0, const float* __restrict__ bc0,
        const float* __restrict__ Wc1, const float* __restrict__ bc1) {
    __shared__ float s[1728];
    const int t = threadIdx.x, w = t >> 5, lane = t & 31;
    int b = blockIdx.x;   // 128 blocks x 256 threads
    if (b < 64) {
        int n = b >> 4, o = (b & 15) * 8 + w;
        for (int i = t; i < 1728; i += 256) s[i] = g_S1[n * 1728 + i];
        __syncthreads();
        float a = 0.f;
        for (int x = lane; x < 1728; x += 32) a += s[x] * Wc0[o * 1728 + x];
#pragma unroll
        for (int off = 16; off > 0; off >>= 1)
            a += __shfl_down_sync(0xffffffffu, a, off);
        if (lane == 0) g_p[n * 256 + o] = a * (1.f / 216.f) + bc0[o];
    } else {
        b -= 64;
        int n = b >> 4, o = (b & 15) * 8 + w;
        for (int i = t; i < 864; i += 256) s[i] = g_S0[n * 864 + i];
        __syncthreads();
        float a = 0.f;
        for (int x = lane; x < 864; x += 32) a += s[x] * Wc1[o * 864 + x];
#pragma unroll
        for (int off = 16; off > 0; off >>= 1)
            a += __shfl_down_sync(0xffffffffu, a, off);
        if (lane == 0) g_p[n * 256 + 128 + o] = a * (1.f / 2744.f) + bc1[o];
    }
}

// ------------------------------ k_inter -------------------------------------
// smem: A hi/lo (32768 each) | M buf0 hi/lo | M buf1 hi/lo | cv | peb/pgb | red | sav
#define SA_HI 0
#define SA_LO 32768
#define SMB 65536
#define MBUF_STRIDE 65536     // per buffer: hi at +0, lo at +32768
#define SCV 196608            // wpe|wpg|bi : 1536
#define SPE 198144            // peb/pgb [4][128] each : 4096
#define SRED 202240           // [16] : 64
#define SSAV 202304           // [2][128] : 1024
#define SMEM_TC_BYTES 203328

#define SCALE_A 16.f
#define SCALE_B 256.f
#define SCALE_INV (1.f / 4096.f)

// Full octet build (prologue only).
__device__ __forceinline__ void build_oct_t(char* mb, const float* __restrict__ Wi,
                                            const float* __restrict__ sav, int p) {
    const int k = p >> 4, h0 = (p & 15) << 3;
    const float s = sav[k];
    const float4* wp = (const float4*)(Wi + k * 128 + h0);
    const float4 w0 = wp[0], w1 = wp[1];
    float v[8];
    v[0] = s * w0.x; v[1] = s * w0.y; v[2] = s * w0.z; v[3] = s * w0.w;
    v[4] = s * w1.x; v[5] = s * w1.y; v[6] = s * w1.z; v[7] = s * w1.w;
    uint32_t hi[4], lo[4];
#pragma unroll
    for (int q = 0; q < 4; q++) {
        __half2 hh = __float22half2_rn(make_float2(v[2 * q], v[2 * q + 1]));
        __half2 ll = __float22half2_rn(make_float2(v[2 * q] - __low2float(hh),
                                                   v[2 * q + 1] - __high2float(hh)));
        hi[q] = *(uint32_t*)&hh;
        lo[q] = *(uint32_t*)&ll;
    }
    const uint32_t o = swz(k, h0);
    *(uint4*)(mb + o) = make_uint4(hi[0], hi[1], hi[2], hi[3]);
    *(uint4*)(mb + 32768 + o) = make_uint4(lo[0], lo[1], lo[2], lo[3]);
}

__global__ void __launch_bounds__(512, 1)
k_inter(const float* __restrict__ Wi, const float* __restrict__ bi,
        const float* __restrict__ wpe, const float* __restrict__ bpe,
        const float* __restrict__ wpg, const float* __restrict__ bpg) {
    extern __shared__ char smc[];
    const uint32_t sb = smem_to_u32(smc);
    float* cv = (float*)(smc + SCV);
    float* peb = (float*)(smc + SPE);        // [4][128]
    float* pgb = peb + 512;                  // [4][128]
    float* red = (float*)(smc + SRED);       // [16]
    float* savbuf = (float*)(smc + SSAV);    // [2][128], pre-scaled by SCALE_B

    const int t = threadIdx.x;
    const int wid = t >> 5;
    const int lane = t & 31;

    const int n = blockIdx.x / 37;
    const int grp = blockIdx.x % 37;
    const int i0 = grp * 28;
    const int cnt = min(28, 1024 - i0);
    const float* atomBase = g_atoms + (n * 1024 + i0) * 128;
    const float bpe0 = bpe[0], bpg0 = bpg[0];

    // ---- prologue: constants + sav(0), sav(1) ----
    if (t < 128) {
        cv[t] = wpe[t];
        cv[128 + t] = wpg[t];
        cv[256 + t] = bi[t];
        savbuf[t] = atomBase[t] * SCALE_B;
    } else if (t < 256) {
        savbuf[128 + (t - 128)] = atomBase[128 + (t - 128)] * SCALE_B;
    }
    __syncthreads();

    // ---- A planes (scaled tok, [j][k]) + M(0) planes ([k][h]) ----
    const float* tokn = g_tok + n * 16384;
    for (int p = t; p < 2048; p += 512) {
        int j = p >> 4, k0 = (p & 15) << 3;
        const float4* xp = (const float4*)(tokn + j * 128 + k0);
        float4 x0 = xp[0], x1 = xp[1];
        float v[8];
        v[0] = x0.x * SCALE_A; v[1] = x0.y * SCALE_A;
        v[2] = x0.z * SCALE_A; v[3] = x0.w * SCALE_A;
        v[4] = x1.x * SCALE_A; v[5] = x1.y * SCALE_A;
        v[6] = x1.z * SCALE_A; v[7] = x1.w * SCALE_A;
        uint32_t hi[4], lo[4];
#pragma unroll
        for (int q = 0; q < 4; q++) {
            __half2 hh = __float22half2_rn(make_float2(v[2 * q], v[2 * q + 1]));
            __half2 ll = __float22half2_rn(make_float2(v[2 * q] - __low2float(hh),
                                                       v[2 * q + 1] - __high2float(hh)));
            hi[q] = *(uint32_t*)&hh;
            lo[q] = *(uint32_t*)&ll;
        }
        uint32_t o = swz(j, k0);
        *(uint4*)(smc + SA_HI + o) = make_uint4(hi[0], hi[1], hi[2], hi[3]);
        *(uint4*)(smc + SA_LO + o) = make_uint4(lo[0], lo[1], lo[2], lo[3]);
    }
    for (int p = t; p < 2048; p += 512) build_oct_t(smc + SMB, Wi, savbuf, p);
    __syncthreads();

    // ---- lane bases. 16 warps: 4 j-tiles x 4 h-groups (32x32 tiles) ----
    const int j0 = (wid & 3) * 32;
    const int h0 = (wid >> 2) * 32;
    // A ([j][k] plane, normal ldsm)
    const int aRowG = j0 + (lane & 15);
    const uint32_t kbA = (uint32_t)(((lane >> 4) << 3) << 1);
    const uint32_t aXor = (uint32_t)((aRowG & 7) << 4);
    const uint32_t aBase = sb + (uint32_t)(((aRowG >> 3) << 10) + ((aRowG & 7) << 7));
    uint32_t alow[4];
#pragma unroll
    for (int c = 0; c < 4; c++) alow[c] = (((uint32_t)c << 5) + kbA) ^ aXor;
    // B ([k][h] plane, trans ldsm): two precomputed swizzled bases per lane.
    const int bk = (lane & 7) + (((lane >> 3) & 1) << 3);
    const int bh = h0 + ((lane >> 4) << 3);
    const uint32_t bB0 = swz(bk, bh);
    const uint32_t bB1 = swz(bk, bh + 16);

    // build octet indices for this thread (p = t + u*512, u=0..3)
    for (int a = 0; a < cnt; a++) {
        const uint32_t mB = sb + (uint32_t)(SMB + (a & 1) * MBUF_STRIDE);
        char* mbN = smc + SMB + ((a + 1) & 1) * MBUF_STRIDE;
        const float* savN = savbuf + ((a + 1) & 1) * 128;
        const bool doBuild = (a + 1 < cnt);

        float acc[2][4][4];
#pragma unroll
        for (int mt = 0; mt < 2; mt++)
#pragma unroll
            for (int nt = 0; nt < 4; nt++)
#pragma unroll
                for (int e = 0; e < 4; e++) acc[mt][nt][e] = 0.f;

#pragma unroll
        for (int ks = 0; ks < 8; ks++) {
            // -- split build, phase 1: issue LDGs (covered by the mma block) --
            float4 bw0, bw1;
            float bsv = 0.f;
            uint32_t boSw = 0;
            if (doBuild && (ks & 1) == 0) {
                const int p = t + ((ks >> 1) << 9);
                const int bkk = p >> 4, bhx = (p & 15) << 3;
                bsv = savN[bkk];
                const float4* wp = (const float4*)(Wi + bkk * 128 + bhx);
                bw0 = wp[0];
                bw1 = wp[1];
                boSw = swz(bkk, bhx);
            }

            const uint32_t pan = (uint32_t)((ks >> 2) << 14);
            const uint32_t ao = pan + alow[ks & 3];
            const uint32_t kstep = (uint32_t)(ks * 2048);
            uint32_t aH[2][4], aL[2][4], bH[2][4], bL[2][4];
            ldsm_x4(aH[0], aBase + SA_HI + ao);
            ldsm_x4(aH[1], aBase + SA_HI + 2048 + ao);
            ldsm_x4(aL[0], aBase + SA_LO + ao);
            ldsm_x4(aL[1], aBase + SA_LO + 2048 + ao);
            ldsm_x4_t(bH[0], mB + bB0 + kstep);            // h0..h0+15
            ldsm_x4_t(bH[1], mB + bB1 + kstep);            // h0+16..h0+31
            ldsm_x4_t(bL[0], mB + 32768 + bB0 + kstep);
            ldsm_x4_t(bL[1], mB + 32768 + bB1 + kstep);
#pragma unroll
            for (int mt = 0; mt < 2; mt++) {
#pragma unroll
                for (int ng = 0; ng < 2; ng++) {
                    mma_f16(acc[mt][2 * ng], aH[mt], bH[ng]);
                    mma_f16(acc[mt][2 * ng + 1], aH[mt], bH[ng] + 2);
                    mma_f16(acc[mt][2 * ng], aH[mt], bL[ng]);
                    mma_f16(acc[mt][2 * ng + 1], aH[mt], bL[ng] + 2);
                    mma_f16(acc[mt][2 * ng], aL[mt], bH[ng]);
                    mma_f16(acc[mt][2 * ng + 1], aL[mt], bH[ng] + 2);
                }
            }

            // -- split build, phase 2: convert + STS (LDGs have landed) --
            if (doBuild && (ks & 1) == 0) {
                float v[8];
                v[0] = bsv * bw0.x; v[1] = bsv * bw0.y;
                v[2] = bsv * bw0.z; v[3] = bsv * bw0.w;
                v[4] = bsv * bw1.x; v[5] = bsv * bw1.y;
                v[6] = bsv * bw1.z; v[7] = bsv * bw1.w;
                uint32_t hi[4], lo[4];
#pragma unroll
                for (int q = 0; q < 4; q++) {
                    __half2 hh = __float22half2_rn(make_float2(v[2 * q], v[2 * q + 1]));
                    __half2 ll = __float22half2_rn(
                        make_float2(v[2 * q] - __low2float(hh),
                                    v[2 * q + 1] - __high2float(hh)));
                    hi[q] = *(uint32_t*)&hh;
                    lo[q] = *(uint32_t*)&ll;
                }
                *(uint4*)(mbN + boSw) = make_uint4(hi[0], hi[1], hi[2], hi[3]);
                *(uint4*)(mbN + 32768 + boSw) = make_uint4(lo[0], lo[1], lo[2], lo[3]);
            }
        }

        // ---- epilogue: unscale + lrelu + pe/pg dots (32 rows x 32 cols) ----
        float pe[4] = {0.f, 0.f, 0.f, 0.f}, pg[4] = {0.f, 0.f, 0.f, 0.f};
#pragma unroll
        for (int nt = 0; nt < 4; nt++) {
#pragma unroll
            for (int c = 0; c < 2; c++) {
                const int h = h0 + 8 * nt + 2 * (lane & 3) + c;
                const float wpeh = cv[h];
                const float wpgh = cv[128 + h];
                const float bih = cv[256 + h];
#pragma unroll
                for (int mt = 0; mt < 2; mt++) {
#pragma unroll
                    for (int hf = 0; hf < 2; hf++) {
                        float v = acc[mt][nt][hf * 2 + c] * SCALE_INV + bih;
                        v = (v > 0.f) ? v : 0.01f * v;
                        pe[mt * 2 + hf] += v * wpeh;
                        pg[mt * 2 + hf] += v * wpgh;
                    }
                }
            }
        }
#pragma unroll
        for (int rs = 0; rs < 4; rs++) {
#pragma unroll
            for (int off = 1; off < 4; off <<= 1) {
                pe[rs] += __shfl_xor_sync(0xffffffffu, pe[rs], off);
                pg[rs] += __shfl_xor_sync(0xffffffffu, pg[rs], off);
            }
        }
        if ((lane & 3) == 0) {
            const int wx = wid >> 2;
#pragma unroll
            for (int mt = 0; mt < 2; mt++)
#pragma unroll
                for (int hf = 0; hf < 2; hf++) {
                    int j = j0 + 16 * mt + 8 * hf + (lane >> 2);
                    peb[wx * 128 + j] = pe[mt * 2 + hf];
                    pgb[wx * 128 + j] = pg[mt * 2 + hf];
                }
        }
        __syncthreads();

        // ---- window: all warps reduce 8 j's each; lanes 24-31 prefetch sav ----
        if (lane < 8) {
            const int j = (wid << 3) + lane;
            float spe = peb[j] + peb[128 + j] + peb[256 + j] + peb[384 + j] + bpe0;
            float spg = pgb[j] + pgb[128 + j] + pgb[256 + j] + pgb[384 + j] + bpg0;
            float sj = spe / (1.f + __expf(-spg));
#pragma unroll
            for (int off = 4; off > 0; off >>= 1)
                sj += __shfl_down_sync(0x000000ffu, sj, off);
            if (lane == 0) red[wid] = sj;
        } else if (lane >= 24 && a + 2 < cnt) {
            const int idx = (wid << 3) + (lane - 24);
            savbuf[(a & 1) * 128 + idx] = atomBase[(a + 2) * 128 + idx] * SCALE_B;
        }
        __syncthreads();

        // final 16-sum off the critical path (warp 0 only; others proceed)
        if (wid == 0) {
            float v = (lane < 16) ? red[lane] : 0.f;
#pragma unroll
            for (int off = 8; off > 0; off >>= 1)
                v += __shfl_down_sync(0xffffffffu, v, off);
            if (lane == 0) g_atom_e[n * 1024 + i0 + a] = v;
        }
    }
}

// ------------------------------ k_final (pf fused) --------------------------
__global__ void k_final(const float* __restrict__ lgr, const int* __restrict__ lb,
                        const float* __restrict__ Wp, const float* __restrict__ bp,
                        const float* __restrict__ Wcat, const float* __restrict__ bcat,
                        const float* __restrict__ Wgate, const float* __restrict__ bgate,
                        const float* __restrict__ Wgr, const float* __restrict__ bgr,
                        const float* __restrict__ Wb1, const float* __restrict__ bb1,
                        const float* __restrict__ Wb2, const float* __restrict__ bb2,
                        float* __restrict__ out) {
    int n = blockIdx.x >> 6, g = blockIdx.x & 63, t = threadIdx.x;
    __shared__ float sp[256];
    __shared__ float pin[384];
    __shared__ float z[256];
    __shared__ float lg[64];
    __shared__ float red[8];

    for (int c = t; c < 256; c += 128) sp[c] = silu_f(g_p[n * 256 + c]);
    if (t < 64) lg[t] = lgr[(n * 64 + g) * 64 + t];
    float ts = 0.f;
    for (int j = 0; j < 128; j++) ts += g_tok[(n * 128 + j) * 128 + t];
    __syncthreads();
    float pk = bp[t];
#pragma unroll 4
    for (int c = 0; c < 256; c++) pk += sp[c] * Wp[c * 128 + t];
    pin[t] = pk;
    pin[128 + t] = ts;
    pin[256 + t] = ts * (1.f / 128.f);
    __syncthreads();
    float c1 = bcat[t], g1 = bgate[t];
#pragma unroll 4
    for (int c = 0; c < 384; c++) {
        float zz = pin[c];
        c1 += zz * Wcat[c * 128 + t];
        g1 += zz * Wgate[c * 128 + t];
    }
    z[t] = c1 / (1.f + __expf(-g1));   // pf

    float gf = bgr[t];
#pragma unroll 4
    for (int c = 0; c < 64; c++) gf += lg[c] * Wgr[c * 128 + t];
    z[128 + t] = gf;
    __syncthreads();

    float h = bb1[t];
#pragma unroll 4
    for (int c = 0; c < 256; c++) h += z[c] * Wb1[c * 128 + t];
    h = (h > 0.f) ? h : 0.01f * h;
    float part = h * Wb2[t];
    float seg = 0.f;
    for (int a = t; a < 1024; a += 128) {
        if (lb[a] == g) seg += g_atom_e[n * 1024 + a];
    }
#pragma unroll
    for (int off = 16; off > 0; off >>= 1) {
        part += __shfl_down_sync(0xffffffffu, part, off);
        seg += __shfl_down_sync(0xffffffffu, seg, off);
    }
    int wid = t >> 5;
    if ((t & 31) == 0) {
        red[wid] = part;
        red[4 + wid] = seg;
    }
    __syncthreads();
    if (t == 0) {
        float bias = red[0] + red[1] + red[2] + red[3] + bb2[0];
        float segs = red[4] + red[5] + red[6] + red[7];
        out[n * 64 + g] = segs + bias;
    }
}

// ------------------------------ launch --------------------------------------
extern "C" void kernel_launch(void* const* d_in, const int* in_sizes, int n_in,
                              void* d_out, int out_size) {
    const float* ms0 = (const float*)d_in[0];
    const float* ms1 = (const float*)d_in[1];
    const float* tf = (const float*)d_in[2];
    const float* lat = (const float*)d_in[3];
    const float* lgr = (const float*)d_in[4];
    const int* lb = (const int*)d_in[5];
    const float* Wt = (const float*)d_in[6];
    const float* bt = (const float*)d_in[7];
    const float* Wc0 = (const float*)d_in[8];
    const float* bc0 = (const float*)d_in[9];
    const float* Wc1 = (const float*)d_in[10];
    const float* bc1 = (const float*)d_in[11];
    const float* Wp = (const float*)d_in[12];
    const float* bp = (const float*)d_in[13];
    const float* Wcat = (const float*)d_in[14];
    const float* bcat = (const float*)d_in[15];
    const float* Wgate = (const float*)d_in[16];
    const float* bgate = (const float*)d_in[17];
    const float* Wa = (const float*)d_in[18];
    const float* ba = (const float*)d_in[19];
    const float* Wgr = (const float*)d_in[20];
    const float* bgr = (const float*)d_in[21];
    const float* Wb1 = (const float*)d_in[22];
    const float* bb1 = (const float*)d_in[23];
    const float* Wb2 = (const float*)d_in[24];
    const float* bb2 = (const float*)d_in[25];
    const float* Wi = (const float*)d_in[26];
    const float* bi = (const float*)d_in[27];
    const float* wpe = (const float*)d_in[28];
    const float* bpe = (const float*)d_in[29];
    const float* wpg = (const float*)d_in[30];
    const float* bpg = (const float*)d_in[31];
    float* out = (float*)d_out;

    static cudaStream_t s2 = nullptr;
    static cudaEvent_t evFork = nullptr, evJoin = nullptr;
    if (s2 == nullptr) {
        cudaStreamCreateWithFlags(&s2, cudaStreamNonBlocking);
        cudaEventCreateWithFlags(&evFork, cudaEventDisableTiming);
        cudaEventCreateWithFlags(&evJoin, cudaEventDisableTiming);
        cudaFuncSetAttribute(k_inter, cudaFuncAttributeMaxDynamicSharedMemorySize,
                             SMEM_TC_BYTES);
    }

    cudaEventRecord(evFork, 0);
    cudaStreamWaitEvent(s2, evFork, 0);
    k_ms<<<384, 256, 0, s2>>>(ms1, ms0);
    k_pconv<<<128, 256, 0, s2>>>(Wc0, bc0, Wc1, bc1);

    k_tokatoms<<<1024, 128>>>(tf, Wt, bt, lat, Wa, ba);
    k_inter<<<148, 512, SMEM_TC_BYTES>>>(Wi, bi, wpe, bpe, wpg, bpg);

    cudaEventRecord(evJoin, s2);
    cudaStreamWaitEvent(0, evJoin, 0);
    k_final<<<256, 128>>>(lgr, lb, Wp, bp, Wcat, bcat, Wgate, bgate,
                          Wgr, bgr, Wb1, bb1, Wb2, bb2, out);
}

// round 15
// speedup vs baseline: 1.1403x; 1.0146x over previous
#include <cuda_runtime.h>
#include <cuda_fp16.h>
#include <cstdint>

// ---------------------------------------------------------------------------
// AffinityHead — mma.sync fp16x3 split GEMM core.
// R15: R13 build placement (consume-immediately, low regs) + pipelined
// cross-warp reduction with double-buffered peb/pgb/red -> ONE barrier per
// atom. Stream fork/join for the pocket branch kept.
// ---------------------------------------------------------------------------

__device__ __forceinline__ float silu_f(float v) { return v / (1.f + __expf(-v)); }

// ------------------------- scratch (static, no allocs) ---------------------
__device__ float g_tok[4 * 128 * 128];     // [n][j][h]
__device__ float g_S1[4 * 64 * 27];
__device__ float g_S0[4 * 32 * 27];
__device__ float g_p[4 * 256];
__device__ float g_atoms[4 * 1024 * 128];  // [n][i][k]
__device__ float g_atom_e[4 * 1024];

// ------------------------------ PTX helpers --------------------------------
__device__ __forceinline__ uint32_t smem_to_u32(const void* p) {
    uint32_t a;
    asm("{ .reg .u64 t; cvta.to.shared.u64 t, %1; cvt.u32.u64 %0, t; }" : "=r"(a) : "l"(p));
    return a;
}

__device__ __forceinline__ void ldsm_x4(uint32_t* r, uint32_t addr) {
    asm volatile("ldmatrix.sync.aligned.m8n8.x4.shared.b16 {%0,%1,%2,%3}, [%4];"
                 : "=r"(r[0]), "=r"(r[1]), "=r"(r[2]), "=r"(r[3]) : "r"(addr));
}

__device__ __forceinline__ void ldsm_x4_t(uint32_t* r, uint32_t addr) {
    asm volatile("ldmatrix.sync.aligned.m8n8.x4.trans.shared.b16 {%0,%1,%2,%3}, [%4];"
                 : "=r"(r[0]), "=r"(r[1]), "=r"(r[2]), "=r"(r[3]) : "r"(addr));
}

__device__ __forceinline__ void mma_f16(float* d, const uint32_t* a, const uint32_t* b) {
    asm volatile(
        "mma.sync.aligned.m16n8k16.row.col.f32.f16.f16.f32 "
        "{%0,%1,%2,%3}, {%4,%5,%6,%7}, {%8,%9}, {%0,%1,%2,%3};"
        : "+f"(d[0]), "+f"(d[1]), "+f"(d[2]), "+f"(d[3])
        : "r"(a[0]), "r"(a[1]), "r"(a[2]), "r"(a[3]), "r"(b[0]), "r"(b[1]));
}

// SW128 blocked-atom swizzled byte offset for a [128 rows][128 halves] plane.
__device__ __forceinline__ uint32_t swz(int row, int k) {
    uint32_t off = (uint32_t)(((k >> 6) << 14) + ((row >> 3) << 10) +
                              ((row & 7) << 7) + ((k & 63) << 1));
    return off ^ (uint32_t)((row & 7) << 4);
}

// ------------------------------ k_tokatoms ----------------------------------
__global__ void k_tokatoms(const float* __restrict__ tf, const float* __restrict__ Wt,
                           const float* __restrict__ bt, const float* __restrict__ la,
                           const float* __restrict__ Wa, const float* __restrict__ ba) {
    __shared__ float s[512];
    const int t = threadIdx.x;
    if (blockIdx.x < 512) {
        const int row = blockIdx.x;
        const float* x = tf + row * 256;
        for (int c = t; c < 256; c += 128) s[c] = silu_f(x[c]);
        __syncthreads();
        float acc = bt[t];
#pragma unroll 8
        for (int c = 0; c < 256; c++) acc += s[c] * Wt[c * 128 + t];
        g_tok[row * 128 + t] = acc;
    } else {
        const int r0 = (blockIdx.x - 512) * 8;
        for (int i = t; i < 512; i += 128) s[i] = la[r0 * 64 + i];
        __syncthreads();
        float b = ba[t];
        float acc[8];
#pragma unroll
        for (int r = 0; r < 8; r++) acc[r] = b;
        for (int c = 0; c < 64; c++) {
            float w = Wa[c * 128 + t];
#pragma unroll
            for (int r = 0; r < 8; r++) acc[r] += s[(r << 6) + c] * w;
        }
#pragma unroll
        for (int r = 0; r < 8; r++) g_atoms[(r0 + r) * 128 + t] = acc[r];
    }
}

// ------------------------------ k_ms (S1 + S0) ------------------------------
__global__ void __launch_bounds__(256, 8)
k_ms(const float* __restrict__ ms1, const float* __restrict__ ms0) {
    __shared__ float v[4096];
    const int t = threadIdx.x;
    const int w = t >> 5, lane = t & 31;
    const int b = blockIdx.x;
    if (b < 256) {
        for (int i = t; i < 512; i += 256) v[i] = silu_f(ms1[b * 512 + i]);
        __syncthreads();
        for (int k = w; k < 27; k += 8) {
            int kd = k / 9, kh = (k / 3) % 3, kw = k % 3;
            float s = 0.f;
            for (int i = lane; i < 216; i += 32) {
                int d = i / 36, r = i % 36, hh = r / 6, ww = r % 6;
                s += v[(d + kd) * 64 + (hh + kh) * 8 + (ww + kw)];
            }
#pragma unroll
            for (int off = 16; off > 0; off >>= 1)
                s += __shfl_down_sync(0xffffffffu, s, off);
            if (lane == 0) g_S1[b * 27 + k] = s;
        }
    } else {
        const int nc = b - 256;
        for (int i = t; i < 4096; i += 256) v[i] = silu_f(ms0[nc * 4096 + i]);
        __syncthreads();
        for (int k = w; k < 27; k += 8) {
            int kd = k / 9, kh = (k / 3) % 3, kw = k % 3;
            float s = 0.f;
            for (int i = lane; i < 2744; i += 32) {
                int d = i / 196, r = i % 196, hh = r / 14, ww = r % 14;
                s += v[(d + kd) * 256 + (hh + kh) * 16 + (ww + kw)];
            }
#pragma unroll
            for (int off = 16; off > 0; off >>= 1)
                s += __shfl_down_sync(0xffffffffu, s, off);
            if (lane == 0) g_S0[nc * 27 + k] = s;
        }
    }
}

// ------------------------------ k_pconv (warp-per-output) -------------------
__global__ void __launch_bounds__(256, 8)
k_pconv(const float* __restrict__ Wc0, const float* __restrict__ bc0,
        const float* __restrict__ Wc1, const float* __restrict__ bc1) {
    __shared__ float s[1728];
    const int t = threadIdx.x, w = t >> 5, lane = t & 31;
    int b = blockIdx.x;   // 128 blocks x 256 threads
    if (b < 64) {
        int n = b >> 4, o = (b & 15) * 8 + w;
        for (int i = t; i < 1728; i += 256) s[i] = g_S1[n * 1728 + i];
        __syncthreads();
        float a = 0.f;
        for (int x = lane; x < 1728; x += 32) a += s[x] * Wc0[o * 1728 + x];
#pragma unroll
        for (int off = 16; off > 0; off >>= 1)
            a += __shfl_down_sync(0xffffffffu, a, off);
        if (lane == 0) g_p[n * 256 + o] = a * (1.f / 216.f) + bc0[o];
    } else {
        b -= 64;
        int n = b >> 4, o = (b & 15) * 8 + w;
        for (int i = t; i < 864; i += 256) s[i] = g_S0[n * 864 + i];
        __syncthreads();
        float a = 0.f;
        for (int x = lane; x < 864; x += 32) a += s[x] * Wc1[o * 864 + x];
#pragma unroll
        for (int off = 16; off > 0; off >>= 1)
            a += __shfl_down_sync(0xffffffffu, a, off);
        if (lane == 0) g_p[n * 256 + 128 + o] = a * (1.f / 2744.f) + bc1[o];
    }
}

// ------------------------------ k_inter -------------------------------------
// smem: A hi/lo | M buf0 hi/lo | M buf1 hi/lo | cv | pe/pg x2 | red x2 | sav x2
#define SA_HI 0
#define SA_LO 32768
#define SMB 65536
#define MBUF_STRIDE 65536     // per buffer: hi at +0, lo at +32768
#define SCV 196608            // wpe|wpg|bi : 1536
#define SPE 198144            // 2 x (peb[4][128] | pgb[4][128]) : 8192
#define SRED 206336           // [2][16] : 128
#define SSAV 206464           // [2][128] : 1024
#define SMEM_TC_BYTES 207488

#define SCALE_A 16.f
#define SCALE_B 256.f
#define SCALE_INV (1.f / 4096.f)

// Build one octet (8 h-values at one k) of M = diag(sav)*W into [k][h] planes.
// Reads Wi straight from global (L2-resident, 32B coalesced per lane).
__device__ __forceinline__ void build_oct_t(char* mb, const float* __restrict__ Wi,
                                            const float* __restrict__ sav, int p) {
    const int k = p >> 4, h0 = (p & 15) << 3;
    const float s = sav[k];
    const float4* wp = (const float4*)(Wi + k * 128 + h0);
    const float4 w0 = wp[0], w1 = wp[1];
    float v[8];
    v[0] = s * w0.x; v[1] = s * w0.y; v[2] = s * w0.z; v[3] = s * w0.w;
    v[4] = s * w1.x; v[5] = s * w1.y; v[6] = s * w1.z; v[7] = s * w1.w;
    uint32_t hi[4], lo[4];
#pragma unroll
    for (int q = 0; q < 4; q++) {
        __half2 hh = __float22half2_rn(make_float2(v[2 * q], v[2 * q + 1]));
        __half2 ll = __float22half2_rn(make_float2(v[2 * q] - __low2float(hh),
                                                   v[2 * q + 1] - __high2float(hh)));
        hi[q] = *(uint32_t*)&hh;
        lo[q] = *(uint32_t*)&ll;
    }
    const uint32_t o = swz(k, h0);
    *(uint4*)(mb + o) = make_uint4(hi[0], hi[1], hi[2], hi[3]);
    *(uint4*)(mb + 32768 + o) = make_uint4(lo[0], lo[1], lo[2], lo[3]);
}

__global__ void __launch_bounds__(512, 1)
k_inter(const float* __restrict__ Wi, const float* __restrict__ bi,
        const float* __restrict__ wpe, const float* __restrict__ bpe,
        const float* __restrict__ wpg, const float* __restrict__ bpg) {
    extern __shared__ char smc[];
    const uint32_t sb = smem_to_u32(smc);
    float* cv = (float*)(smc + SCV);
    float* redb = (float*)(smc + SRED);      // [2][16]
    float* savbuf = (float*)(smc + SSAV);    // [2][128], pre-scaled by SCALE_B

    const int t = threadIdx.x;
    const int wid = t >> 5;
    const int lane = t & 31;

    const int n = blockIdx.x / 37;
    const int grp = blockIdx.x % 37;
    const int i0 = grp * 28;
    const int cnt = min(28, 1024 - i0);
    const float* atomBase = g_atoms + (n * 1024 + i0) * 128;
    const float bpe0 = bpe[0], bpg0 = bpg[0];

    // ---- prologue: constants + sav(0), sav(1) ----
    if (t < 128) {
        cv[t] = wpe[t];
        cv[128 + t] = wpg[t];
        cv[256 + t] = bi[t];
        savbuf[t] = atomBase[t] * SCALE_B;
    } else if (t < 256) {
        savbuf[128 + (t - 128)] = atomBase[128 + (t - 128)] * SCALE_B;
    }
    __syncthreads();

    // ---- A planes (scaled tok, [j][k]) + M(0) planes ([k][h]) ----
    const float* tokn = g_tok + n * 16384;
    for (int p = t; p < 2048; p += 512) {
        int j = p >> 4, k0 = (p & 15) << 3;
        const float4* xp = (const float4*)(tokn + j * 128 + k0);
        float4 x0 = xp[0], x1 = xp[1];
        float v[8];
        v[0] = x0.x * SCALE_A; v[1] = x0.y * SCALE_A;
        v[2] = x0.z * SCALE_A; v[3] = x0.w * SCALE_A;
        v[4] = x1.x * SCALE_A; v[5] = x1.y * SCALE_A;
        v[6] = x1.z * SCALE_A; v[7] = x1.w * SCALE_A;
        uint32_t hi[4], lo[4];
#pragma unroll
        for (int q = 0; q < 4; q++) {
            __half2 hh = __float22half2_rn(make_float2(v[2 * q], v[2 * q + 1]));
            __half2 ll = __float22half2_rn(make_float2(v[2 * q] - __low2float(hh),
                                                       v[2 * q + 1] - __high2float(hh)));
            hi[q] = *(uint32_t*)&hh;
            lo[q] = *(uint32_t*)&ll;
        }
        uint32_t o = swz(j, k0);
        *(uint4*)(smc + SA_HI + o) = make_uint4(hi[0], hi[1], hi[2], hi[3]);
        *(uint4*)(smc + SA_LO + o) = make_uint4(lo[0], lo[1], lo[2], lo[3]);
    }
    for (int p = t; p < 2048; p += 512) build_oct_t(smc + SMB, Wi, savbuf, p);
    __syncthreads();

    // ---- lane bases. 16 warps: 4 j-tiles x 4 h-groups (32x32 tiles) ----
    const int j0 = (wid & 3) * 32;
    const int h0 = (wid >> 2) * 32;
    const int aRowG = j0 + (lane & 15);
    const uint32_t kbA = (uint32_t)(((lane >> 4) << 3) << 1);
    const uint32_t aXor = (uint32_t)((aRowG & 7) << 4);
    const uint32_t aBase = sb + (uint32_t)(((aRowG >> 3) << 10) + ((aRowG & 7) << 7));
    uint32_t alow[4];
#pragma unroll
    for (int c = 0; c < 4; c++) alow[c] = (((uint32_t)c << 5) + kbA) ^ aXor;
    const int bk = (lane & 7) + (((lane >> 3) & 1) << 3);
    const int bh = h0 + ((lane >> 4) << 3);
    const uint32_t bB0 = swz(bk, bh);
    const uint32_t bB1 = swz(bk, bh + 16);

    for (int a = 0; a < cnt; a++) {
        // ---- pipelined reductions (reads sync'd by end-of-prev-iter barrier) --
        if (a >= 2 && wid == 0) {
            float v = (lane < 16) ? redb[((a - 2) & 1) * 16 + lane] : 0.f;
#pragma unroll
            for (int off = 8; off > 0; off >>= 1)
                v += __shfl_down_sync(0xffffffffu, v, off);
            if (lane == 0) g_atom_e[n * 1024 + i0 + a - 2] = v;
        }
        if (a >= 1 && lane < 8) {
            const int bsel = (a - 1) & 1;
            const float* pebR = (const float*)(smc + SPE + bsel * 4096);
            const float* pgbR = pebR + 512;
            const int j = (wid << 3) + lane;
            float spe = pebR[j] + pebR[128 + j] + pebR[256 + j] + pebR[384 + j] + bpe0;
            float spg = pgbR[j] + pgbR[128 + j] + pgbR[256 + j] + pgbR[384 + j] + bpg0;
            float sj = spe / (1.f + __expf(-spg));
#pragma unroll
            for (int off = 4; off > 0; off >>= 1)
                sj += __shfl_down_sync(0x000000ffu, sj, off);
            if (lane == 0) redb[bsel * 16 + wid] = sj;
        }

        const uint32_t mB = sb + (uint32_t)(SMB + (a & 1) * MBUF_STRIDE);
        char* mbN = smc + SMB + ((a + 1) & 1) * MBUF_STRIDE;
        const float* savN = savbuf + ((a + 1) & 1) * 128;
        const bool doBuild = (a + 1 < cnt);

        float acc[2][4][4];
#pragma unroll
        for (int mt = 0; mt < 2; mt++)
#pragma unroll
            for (int nt = 0; nt < 4; nt++)
#pragma unroll
                for (int e = 0; e < 4; e++) acc[mt][nt][e] = 0.f;

#pragma unroll
        for (int ks = 0; ks < 8; ks++) {
            const uint32_t pan = (uint32_t)((ks >> 2) << 14);
            const uint32_t ao = pan + alow[ks & 3];
            const uint32_t kstep = (uint32_t)(ks * 2048);
            uint32_t aH[2][4], aL[2][4], bH[2][4], bL[2][4];
            ldsm_x4(aH[0], aBase + SA_HI + ao);
            ldsm_x4(aH[1], aBase + SA_HI + 2048 + ao);
            ldsm_x4(aL[0], aBase + SA_LO + ao);
            ldsm_x4(aL[1], aBase + SA_LO + 2048 + ao);
            ldsm_x4_t(bH[0], mB + bB0 + kstep);            // h0..h0+15
            ldsm_x4_t(bH[1], mB + bB1 + kstep);            // h0+16..h0+31
            ldsm_x4_t(bL[0], mB + 32768 + bB0 + kstep);
            ldsm_x4_t(bL[1], mB + 32768 + bB1 + kstep);
#pragma unroll
            for (int mt = 0; mt < 2; mt++) {
#pragma unroll
                for (int ng = 0; ng < 2; ng++) {
                    mma_f16(acc[mt][2 * ng], aH[mt], bH[ng]);
                    mma_f16(acc[mt][2 * ng + 1], aH[mt], bH[ng] + 2);
                    mma_f16(acc[mt][2 * ng], aH[mt], bL[ng]);
                    mma_f16(acc[mt][2 * ng + 1], aH[mt], bL[ng] + 2);
                    mma_f16(acc[mt][2 * ng], aL[mt], bH[ng]);
                    mma_f16(acc[mt][2 * ng + 1], aL[mt], bH[ng] + 2);
                }
            }
            // pipelined build of M(a+1) into the other buffer (4 octets/thread)
            if (doBuild && (ks & 1) == 0)
                build_oct_t(mbN, Wi, savN, t + ((ks >> 1) << 9));
        }

        // ---- epilogue: unscale + lrelu + pe/pg dots (32 rows x 32 cols) ----
        float* pebB = (float*)(smc + SPE + (a & 1) * 4096);
        float* pgbB = pebB + 512;
        float pe[4] = {0.f, 0.f, 0.f, 0.f}, pg[4] = {0.f, 0.f, 0.f, 0.f};
#pragma unroll
        for (int nt = 0; nt < 4; nt++) {
#pragma unroll
            for (int c = 0; c < 2; c++) {
                const int h = h0 + 8 * nt + 2 * (lane & 3) + c;
                const float wpeh = cv[h];
                const float wpgh = cv[128 + h];
                const float bih = cv[256 + h];
#pragma unroll
                for (int mt = 0; mt < 2; mt++) {
#pragma unroll
                    for (int hf = 0; hf < 2; hf++) {
                        float v = acc[mt][nt][hf * 2 + c] * SCALE_INV + bih;
                        v = (v > 0.f) ? v : 0.01f * v;
                        pe[mt * 2 + hf] += v * wpeh;
                        pg[mt * 2 + hf] += v * wpgh;
                    }
                }
            }
        }
#pragma unroll
        for (int rs = 0; rs < 4; rs++) {
#pragma unroll
            for (int off = 1; off < 4; off <<= 1) {
                pe[rs] += __shfl_xor_sync(0xffffffffu, pe[rs], off);
                pg[rs] += __shfl_xor_sync(0xffffffffu, pg[rs], off);
            }
        }
        if ((lane & 3) == 0) {
            const int wx = wid >> 2;
#pragma unroll
            for (int mt = 0; mt < 2; mt++)
#pragma unroll
                for (int hf = 0; hf < 2; hf++) {
                    int j = j0 + 16 * mt + 8 * hf + (lane >> 2);
                    pebB[wx * 128 + j] = pe[mt * 2 + hf];
                    pgbB[wx * 128 + j] = pg[mt * 2 + hf];
                }
        }
        // sav(a+2) prefetch (slot (a&1): its last readers ran in mainloop a-1)
        if (lane >= 24 && a + 2 < cnt) {
            const int idx = (wid << 3) + (lane - 24);
            savbuf[(a & 1) * 128 + idx] = atomBase[(a + 2) * 128 + idx] * SCALE_B;
        }
        __syncthreads();   // the ONLY barrier per atom
    }

    // ---- drain the reduction pipeline ----
    if (cnt >= 2 && wid == 0) {
        float v = (lane < 16) ? redb[((cnt - 2) & 1) * 16 + lane] : 0.f;
#pragma unroll
        for (int off = 8; off > 0; off >>= 1)
            v += __shfl_down_sync(0xffffffffu, v, off);
        if (lane == 0) g_atom_e[n * 1024 + i0 + cnt - 2] = v;
    }
    if (lane < 8) {
        const int bsel = (cnt - 1) & 1;
        const float* pebR = (const float*)(smc + SPE + bsel * 4096);
        const float* pgbR = pebR + 512;
        const int j = (wid << 3) + lane;
        float spe = pebR[j] + pebR[128 + j] + pebR[256 + j] + pebR[384 + j] + bpe0;
        float spg = pgbR[j] + pgbR[128 + j] + pgbR[256 + j] + pgbR[384 + j] + bpg0;
        float sj = spe / (1.f + __expf(-spg));
#pragma unroll
        for (int off = 4; off > 0; off >>= 1)
            sj += __shfl_down_sync(0x000000ffu, sj, off);
        if (lane == 0) redb[bsel * 16 + wid] = sj;
    }
    __syncthreads();
    if (wid == 0) {
        float v = (lane < 16) ? redb[((cnt - 1) & 1) * 16 + lane] : 0.f;
#pragma unroll
        for (int off = 8; off > 0; off >>= 1)
            v += __shfl_down_sync(0xffffffffu, v, off);
        if (lane == 0) g_atom_e[n * 1024 + i0 + cnt - 1] = v;
    }
}

// ------------------------------ k_final (pf fused) --------------------------
__global__ void k_final(const float* __restrict__ lgr, const int* __restrict__ lb,
                        const float* __restrict__ Wp, const float* __restrict__ bp,
                        const float* __restrict__ Wcat, const float* __restrict__ bcat,
                        const float* __restrict__ Wgate, const float* __restrict__ bgate,
                        const float* __restrict__ Wgr, const float* __restrict__ bgr,
                        const float* __restrict__ Wb1, const float* __restrict__ bb1,
                        const float* __restrict__ Wb2, const float* __restrict__ bb2,
                        float* __restrict__ out) {
    int n = blockIdx.x >> 6, g = blockIdx.x & 63, t = threadIdx.x;
    __shared__ float sp[256];
    __shared__ float pin[384];
    __shared__ float z[256];
    __shared__ float lg[64];
    __shared__ float red[8];

    for (int c = t; c < 256; c += 128) sp[c] = silu_f(g_p[n * 256 + c]);
    if (t < 64) lg[t] = lgr[(n * 64 + g) * 64 + t];
    float ts = 0.f;
    for (int j = 0; j < 128; j++) ts += g_tok[(n * 128 + j) * 128 + t];
    __syncthreads();
    float pk = bp[t];
#pragma unroll 4
    for (int c = 0; c < 256; c++) pk += sp[c] * Wp[c * 128 + t];
    pin[t] = pk;
    pin[128 + t] = ts;
    pin[256 + t] = ts * (1.f / 128.f);
    __syncthreads();
    float c1 = bcat[t], g1 = bgate[t];
#pragma unroll 4
    for (int c = 0; c < 384; c++) {
        float zz = pin[c];
        c1 += zz * Wcat[c * 128 + t];
        g1 += zz * Wgate[c * 128 + t];
    }
    z[t] = c1 / (1.f + __expf(-g1));   // pf

    float gf = bgr[t];
#pragma unroll 4
    for (int c = 0; c < 64; c++) gf += lg[c] * Wgr[c * 128 + t];
    z[128 + t] = gf;
    __syncthreads();

    float h = bb1[t];
#pragma unroll 4
    for (int c = 0; c < 256; c++) h += z[c] * Wb1[c * 128 + t];
    h = (h > 0.f) ? h : 0.01f * h;
    float part = h * Wb2[t];
    float seg = 0.f;
    for (int a = t; a < 1024; a += 128) {
        if (lb[a] == g) seg += g_atom_e[n * 1024 + a];
    }
#pragma unroll
    for (int off = 16; off > 0; off >>= 1) {
        part += __shfl_down_sync(0xffffffffu, part, off);
        seg += __shfl_down_sync(0xffffffffu, seg, off);
    }
    int wid = t >> 5;
    if ((t & 31) == 0) {
        red[wid] = part;
        red[4 + wid] = seg;
    }
    __syncthreads();
    if (t == 0) {
        float bias = red[0] + red[1] + red[2] + red[3] + bb2[0];
        float segs = red[4] + red[5] + red[6] + red[7];
        out[n * 64 + g] = segs + bias;
    }
}

// ------------------------------ launch --------------------------------------
extern "C" void kernel_launch(void* const* d_in, const int* in_sizes, int n_in,
                              void* d_out, int out_size) {
    const float* ms0 = (const float*)d_in[0];
    const float* ms1 = (const float*)d_in[1];
    const float* tf = (const float*)d_in[2];
    const float* lat = (const float*)d_in[3];
    const float* lgr = (const float*)d_in[4];
    const int* lb = (const int*)d_in[5];
    const float* Wt = (const float*)d_in[6];
    const float* bt = (const float*)d_in[7];
    const float* Wc0 = (const float*)d_in[8];
    const float* bc0 = (const float*)d_in[9];
    const float* Wc1 = (const float*)d_in[10];
    const float* bc1 = (const float*)d_in[11];
    const float* Wp = (const float*)d_in[12];
    const float* bp = (const float*)d_in[13];
    const float* Wcat = (const float*)d_in[14];
    const float* bcat = (const float*)d_in[15];
    const float* Wgate = (const float*)d_in[16];
    const float* bgate = (const float*)d_in[17];
    const float* Wa = (const float*)d_in[18];
    const float* ba = (const float*)d_in[19];
    const float* Wgr = (const float*)d_in[20];
    const float* bgr = (const float*)d_in[21];
    const float* Wb1 = (const float*)d_in[22];
    const float* bb1 = (const float*)d_in[23];
    const float* Wb2 = (const float*)d_in[24];
    const float* bb2 = (const float*)d_in[25];
    const float* Wi = (const float*)d_in[26];
    const float* bi = (const float*)d_in[27];
    const float* wpe = (const float*)d_in[28];
    const float* bpe = (const float*)d_in[29];
    const float* wpg = (const float*)d_in[30];
    const float* bpg = (const float*)d_in[31];
    float* out = (float*)d_out;

    static cudaStream_t s2 = nullptr;
    static cudaEvent_t evFork = nullptr, evJoin = nullptr;
    if (s2 == nullptr) {
        cudaStreamCreateWithFlags(&s2, cudaStreamNonBlocking);
        cudaEventCreateWithFlags(&evFork, cudaEventDisableTiming);
        cudaEventCreateWithFlags(&evJoin, cudaEventDisableTiming);
        cudaFuncSetAttribute(k_inter, cudaFuncAttributeMaxDynamicSharedMemorySize,
                             SMEM_TC_BYTES);
    }

    cudaEventRecord(evFork, 0);
    cudaStreamWaitEvent(s2, evFork, 0);
    k_ms<<<384, 256, 0, s2>>>(ms1, ms0);
    k_pconv<<<128, 256, 0, s2>>>(Wc0, bc0, Wc1, bc1);

    k_tokatoms<<<1024, 128>>>(tf, Wt, bt, lat, Wa, ba);
    k_inter<<<148, 512, SMEM_TC_BYTES>>>(Wi, bi, wpe, bpe, wpg, bpg);

    cudaEventRecord(evJoin, s2);
    cudaStreamWaitEvent(0, evJoin, 0);
    k_final<<<256, 128>>>(lgr, lb, Wp, bp, Wcat, bcat, Wgate, bgate,
                          Wgr, bgr, Wb1, bb1, Wb2, bb2, out);
}

// round 16
// speedup vs baseline: 1.3841x; 1.2137x over previous
#include <cuda_runtime.h>
#include <cuda_fp16.h>
#include <cstdint>

// ---------------------------------------------------------------------------
// AffinityHead — mma.sync fp16x3 split GEMM core (k_inter frozen from R15).
// R16: epilogue-kernel L2-traffic surgery:
//   - k_tokatoms: 8 tok rows per block (Wt reuse x8)
//   - k_pf: pf + hpf (= pf . Wb1_top) per image, on the side stream under
//     k_inter
//   - k_final: only gf, gf . Wb1_bot, lrelu, Wb2 dot, segment sum.
// ---------------------------------------------------------------------------

__device__ __forceinline__ float silu_f(float v) { return v / (1.f + __expf(-v)); }

// ------------------------- scratch (static, no allocs) ---------------------
__device__ float g_tok[4 * 128 * 128];     // [n][j][h]
__device__ float g_S1[4 * 64 * 27];
__device__ float g_S0[4 * 32 * 27];
__device__ float g_p[4 * 256];
__device__ float g_pf[4 * 128];
__device__ float g_hpf[4 * 128];           // pf . Wb1_top (pre-activation)
__device__ float g_atoms[4 * 1024 * 128];  // [n][i][k]
__device__ float g_atom_e[4 * 1024];

// ------------------------------ PTX helpers --------------------------------
__device__ __forceinline__ uint32_t smem_to_u32(const void* p) {
    uint32_t a;
    asm("{ .reg .u64 t; cvta.to.shared.u64 t, %1; cvt.u32.u64 %0, t; }" : "=r"(a) : "l"(p));
    return a;
}

__device__ __forceinline__ void ldsm_x4(uint32_t* r, uint32_t addr) {
    asm volatile("ldmatrix.sync.aligned.m8n8.x4.shared.b16 {%0,%1,%2,%3}, [%4];"
                 : "=r"(r[0]), "=r"(r[1]), "=r"(r[2]), "=r"(r[3]) : "r"(addr));
}

__device__ __forceinline__ void ldsm_x4_t(uint32_t* r, uint32_t addr) {
    asm volatile("ldmatrix.sync.aligned.m8n8.x4.trans.shared.b16 {%0,%1,%2,%3}, [%4];"
                 : "=r"(r[0]), "=r"(r[1]), "=r"(r[2]), "=r"(r[3]) : "r"(addr));
}

__device__ __forceinline__ void mma_f16(float* d, const uint32_t* a, const uint32_t* b) {
    asm volatile(
        "mma.sync.aligned.m16n8k16.row.col.f32.f16.f16.f32 "
        "{%0,%1,%2,%3}, {%4,%5,%6,%7}, {%8,%9}, {%0,%1,%2,%3};"
        : "+f"(d[0]), "+f"(d[1]), "+f"(d[2]), "+f"(d[3])
        : "r"(a[0]), "r"(a[1]), "r"(a[2]), "r"(a[3]), "r"(b[0]), "r"(b[1]));
}

// SW128 blocked-atom swizzled byte offset for a [128 rows][128 halves] plane.
__device__ __forceinline__ uint32_t swz(int row, int k) {
    uint32_t off = (uint32_t)(((k >> 6) << 14) + ((row >> 3) << 10) +
                              ((row & 7) << 7) + ((k & 63) << 1));
    return off ^ (uint32_t)((row & 7) << 4);
}

// ------------------------------ k_tokatoms ----------------------------------
// blocks 0-63: tok rows r0..r0+7 (8 rows, Wt reused across rows)
// blocks 64-575: atom rows (8 per block)
__global__ void k_tokatoms(const float* __restrict__ tf, const float* __restrict__ Wt,
                           const float* __restrict__ bt, const float* __restrict__ la,
                           const float* __restrict__ Wa, const float* __restrict__ ba) {
    __shared__ float s[2048];
    const int t = threadIdx.x;
    if (blockIdx.x < 64) {
        const int r0 = blockIdx.x * 8;
        for (int i = t; i < 2048; i += 128) s[i] = silu_f(tf[r0 * 256 + i]);
        __syncthreads();
        float b = bt[t];
        float acc[8];
#pragma unroll
        for (int r = 0; r < 8; r++) acc[r] = b;
        for (int c = 0; c < 256; c++) {
            float w = Wt[c * 128 + t];
#pragma unroll
            for (int r = 0; r < 8; r++) acc[r] += s[(r << 8) + c] * w;
        }
#pragma unroll
        for (int r = 0; r < 8; r++) g_tok[(r0 + r) * 128 + t] = acc[r];
    } else {
        const int r0 = (blockIdx.x - 64) * 8;
        for (int i = t; i < 512; i += 128) s[i] = la[r0 * 64 + i];
        __syncthreads();
        float b = ba[t];
        float acc[8];
#pragma unroll
        for (int r = 0; r < 8; r++) acc[r] = b;
        for (int c = 0; c < 64; c++) {
            float w = Wa[c * 128 + t];
#pragma unroll
            for (int r = 0; r < 8; r++) acc[r] += s[(r << 6) + c] * w;
        }
#pragma unroll
        for (int r = 0; r < 8; r++) g_atoms[(r0 + r) * 128 + t] = acc[r];
    }
}

// ------------------------------ k_ms (S1 + S0) ------------------------------
__global__ void __launch_bounds__(256, 8)
k_ms(const float* __restrict__ ms1, const float* __restrict__ ms0) {
    __shared__ float v[4096];
    const int t = threadIdx.x;
    const int w = t >> 5, lane = t & 31;
    const int b = blockIdx.x;
    if (b < 256) {
        for (int i = t; i < 512; i += 256) v[i] = silu_f(ms1[b * 512 + i]);
        __syncthreads();
        for (int k = w; k < 27; k += 8) {
            int kd = k / 9, kh = (k / 3) % 3, kw = k % 3;
            float s = 0.f;
            for (int i = lane; i < 216; i += 32) {
                int d = i / 36, r = i % 36, hh = r / 6, ww = r % 6;
                s += v[(d + kd) * 64 + (hh + kh) * 8 + (ww + kw)];
            }
#pragma unroll
            for (int off = 16; off > 0; off >>= 1)
                s += __shfl_down_sync(0xffffffffu, s, off);
            if (lane == 0) g_S1[b * 27 + k] = s;
        }
    } else {
        const int nc = b - 256;
        for (int i = t; i < 4096; i += 256) v[i] = silu_f(ms0[nc * 4096 + i]);
        __syncthreads();
        for (int k = w; k < 27; k += 8) {
            int kd = k / 9, kh = (k / 3) % 3, kw = k % 3;
            float s = 0.f;
            for (int i = lane; i < 2744; i += 32) {
                int d = i / 196, r = i % 196, hh = r / 14, ww = r % 14;
                s += v[(d + kd) * 256 + (hh + kh) * 16 + (ww + kw)];
            }
#pragma unroll
            for (int off = 16; off > 0; off >>= 1)
                s += __shfl_down_sync(0xffffffffu, s, off);
            if (lane == 0) g_S0[nc * 27 + k] = s;
        }
    }
}

// ------------------------------ k_pconv (warp-per-output) -------------------
__global__ void __launch_bounds__(256, 8)
k_pconv(const float* __restrict__ Wc0, const float* __restrict__ bc0,
        const float* __restrict__ Wc1, const float* __restrict__ bc1) {
    __shared__ float s[1728];
    const int t = threadIdx.x, w = t >> 5, lane = t & 31;
    int b = blockIdx.x;   // 128 blocks x 256 threads
    if (b < 64) {
        int n = b >> 4, o = (b & 15) * 8 + w;
        for (int i = t; i < 1728; i += 256) s[i] = g_S1[n * 1728 + i];
        __syncthreads();
        float a = 0.f;
        for (int x = lane; x < 1728; x += 32) a += s[x] * Wc0[o * 1728 + x];
#pragma unroll
        for (int off = 16; off > 0; off >>= 1)
            a += __shfl_down_sync(0xffffffffu, a, off);
        if (lane == 0) g_p[n * 256 + o] = a * (1.f / 216.f) + bc0[o];
    } else {
        b -= 64;
        int n = b >> 4, o = (b & 15) * 8 + w;
        for (int i = t; i < 864; i += 256) s[i] = g_S0[n * 864 + i];
        __syncthreads();
        float a = 0.f;
        for (int x = lane; x < 864; x += 32) a += s[x] * Wc1[o * 864 + x];
#pragma unroll
        for (int off = 16; off > 0; off >>= 1)
            a += __shfl_down_sync(0xffffffffu, a, off);
        if (lane == 0) g_p[n * 256 + 128 + o] = a * (1.f / 2744.f) + bc1[o];
    }
}

// ------------------------------ k_pf (per image, side stream) ---------------
__global__ void __launch_bounds__(128, 8)
k_pf(const float* __restrict__ Wp, const float* __restrict__ bp,
     const float* __restrict__ Wcat, const float* __restrict__ bcat,
     const float* __restrict__ Wgate, const float* __restrict__ bgate,
     const float* __restrict__ Wb1) {
    const int n = blockIdx.x, t = threadIdx.x;
    __shared__ float sp[256];
    __shared__ float pin[384];
    __shared__ float pfs[128];
    for (int c = t; c < 256; c += 128) sp[c] = silu_f(g_p[n * 256 + c]);
    float ts = 0.f;
    for (int j = 0; j < 128; j++) ts += g_tok[(n * 128 + j) * 128 + t];
    __syncthreads();
    float pk = bp[t];
#pragma unroll 4
    for (int c = 0; c < 256; c++) pk += sp[c] * Wp[c * 128 + t];
    pin[t] = pk;
    pin[128 + t] = ts;
    pin[256 + t] = ts * (1.f / 128.f);
    __syncthreads();
    float c1 = bcat[t], g1 = bgate[t];
#pragma unroll 4
    for (int c = 0; c < 384; c++) {
        float zz = pin[c];
        c1 += zz * Wcat[c * 128 + t];
        g1 += zz * Wgate[c * 128 + t];
    }
    float pf = c1 / (1.f + __expf(-g1));
    pfs[t] = pf;
    g_pf[n * 128 + t] = pf;
    __syncthreads();
    float hp = 0.f;
#pragma unroll 4
    for (int c = 0; c < 128; c++) hp += pfs[c] * Wb1[c * 128 + t];
    g_hpf[n * 128 + t] = hp;
}

// ------------------------------ k_inter (frozen R15) ------------------------
#define SA_HI 0
#define SA_LO 32768
#define SMB 65536
#define MBUF_STRIDE 65536     // per buffer: hi at +0, lo at +32768
#define SCV 196608            // wpe|wpg|bi : 1536
#define SPE 198144            // 2 x (peb[4][128] | pgb[4][128]) : 8192
#define SRED 206336           // [2][16] : 128
#define SSAV 206464           // [2][128] : 1024
#define SMEM_TC_BYTES 207488

#define SCALE_A 16.f
#define SCALE_B 256.f
#define SCALE_INV (1.f / 4096.f)

__device__ __forceinline__ void build_oct_t(char* mb, const float* __restrict__ Wi,
                                            const float* __restrict__ sav, int p) {
    const int k = p >> 4, h0 = (p & 15) << 3;
    const float s = sav[k];
    const float4* wp = (const float4*)(Wi + k * 128 + h0);
    const float4 w0 = wp[0], w1 = wp[1];
    float v[8];
    v[0] = s * w0.x; v[1] = s * w0.y; v[2] = s * w0.z; v[3] = s * w0.w;
    v[4] = s * w1.x; v[5] = s * w1.y; v[6] = s * w1.z; v[7] = s * w1.w;
    uint32_t hi[4], lo[4];
#pragma unroll
    for (int q = 0; q < 4; q++) {
        __half2 hh = __float22half2_rn(make_float2(v[2 * q], v[2 * q + 1]));
        __half2 ll = __float22half2_rn(make_float2(v[2 * q] - __low2float(hh),
                                                   v[2 * q + 1] - __high2float(hh)));
        hi[q] = *(uint32_t*)&hh;
        lo[q] = *(uint32_t*)&ll;
    }
    const uint32_t o = swz(k, h0);
    *(uint4*)(mb + o) = make_uint4(hi[0], hi[1], hi[2], hi[3]);
    *(uint4*)(mb + 32768 + o) = make_uint4(lo[0], lo[1], lo[2], lo[3]);
}

__global__ void __launch_bounds__(512, 1)
k_inter(const float* __restrict__ Wi, const float* __restrict__ bi,
        const float* __restrict__ wpe, const float* __restrict__ bpe,
        const float* __restrict__ wpg, const float* __restrict__ bpg) {
    extern __shared__ char smc[];
    const uint32_t sb = smem_to_u32(smc);
    float* cv = (float*)(smc + SCV);
    float* redb = (float*)(smc + SRED);      // [2][16]
    float* savbuf = (float*)(smc + SSAV);    // [2][128], pre-scaled by SCALE_B

    const int t = threadIdx.x;
    const int wid = t >> 5;
    const int lane = t & 31;

    const int n = blockIdx.x / 37;
    const int grp = blockIdx.x % 37;
    const int i0 = grp * 28;
    const int cnt = min(28, 1024 - i0);
    const float* atomBase = g_atoms + (n * 1024 + i0) * 128;
    const float bpe0 = bpe[0], bpg0 = bpg[0];

    if (t < 128) {
        cv[t] = wpe[t];
        cv[128 + t] = wpg[t];
        cv[256 + t] = bi[t];
        savbuf[t] = atomBase[t] * SCALE_B;
    } else if (t < 256) {
        savbuf[128 + (t - 128)] = atomBase[128 + (t - 128)] * SCALE_B;
    }
    __syncthreads();

    const float* tokn = g_tok + n * 16384;
    for (int p = t; p < 2048; p += 512) {
        int j = p >> 4, k0 = (p & 15) << 3;
        const float4* xp = (const float4*)(tokn + j * 128 + k0);
        float4 x0 = xp[0], x1 = xp[1];
        float v[8];
        v[0] = x0.x * SCALE_A; v[1] = x0.y * SCALE_A;
        v[2] = x0.z * SCALE_A; v[3] = x0.w * SCALE_A;
        v[4] = x1.x * SCALE_A; v[5] = x1.y * SCALE_A;
        v[6] = x1.z * SCALE_A; v[7] = x1.w * SCALE_A;
        uint32_t hi[4], lo[4];
#pragma unroll
        for (int q = 0; q < 4; q++) {
            __half2 hh = __float22half2_rn(make_float2(v[2 * q], v[2 * q + 1]));
            __half2 ll = __float22half2_rn(make_float2(v[2 * q] - __low2float(hh),
                                                       v[2 * q + 1] - __high2float(hh)));
            hi[q] = *(uint32_t*)&hh;
            lo[q] = *(uint32_t*)&ll;
        }
        uint32_t o = swz(j, k0);
        *(uint4*)(smc + SA_HI + o) = make_uint4(hi[0], hi[1], hi[2], hi[3]);
        *(uint4*)(smc + SA_LO + o) = make_uint4(lo[0], lo[1], lo[2], lo[3]);
    }
    for (int p = t; p < 2048; p += 512) build_oct_t(smc + SMB, Wi, savbuf, p);
    __syncthreads();

    const int j0 = (wid & 3) * 32;
    const int h0 = (wid >> 2) * 32;
    const int aRowG = j0 + (lane & 15);
    const uint32_t kbA = (uint32_t)(((lane >> 4) << 3) << 1);
    const uint32_t aXor = (uint32_t)((aRowG & 7) << 4);
    const uint32_t aBase = sb + (uint32_t)(((aRowG >> 3) << 10) + ((aRowG & 7) << 7));
    uint32_t alow[4];
#pragma unroll
    for (int c = 0; c < 4; c++) alow[c] = (((uint32_t)c << 5) + kbA) ^ aXor;
    const int bk = (lane & 7) + (((lane >> 3) & 1) << 3);
    const int bh = h0 + ((lane >> 4) << 3);
    const uint32_t bB0 = swz(bk, bh);
    const uint32_t bB1 = swz(bk, bh + 16);

    for (int a = 0; a < cnt; a++) {
        if (a >= 2 && wid == 0) {
            float v = (lane < 16) ? redb[((a - 2) & 1) * 16 + lane] : 0.f;
#pragma unroll
            for (int off = 8; off > 0; off >>= 1)
                v += __shfl_down_sync(0xffffffffu, v, off);
            if (lane == 0) g_atom_e[n * 1024 + i0 + a - 2] = v;
        }
        if (a >= 1 && lane < 8) {
            const int bsel = (a - 1) & 1;
            const float* pebR = (const float*)(smc + SPE + bsel * 4096);
            const float* pgbR = pebR + 512;
            const int j = (wid << 3) + lane;
            float spe = pebR[j] + pebR[128 + j] + pebR[256 + j] + pebR[384 + j] + bpe0;
            float spg = pgbR[j] + pgbR[128 + j] + pgbR[256 + j] + pgbR[384 + j] + bpg0;
            float sj = spe / (1.f + __expf(-spg));
#pragma unroll
            for (int off = 4; off > 0; off >>= 1)
                sj += __shfl_down_sync(0x000000ffu, sj, off);
            if (lane == 0) redb[bsel * 16 + wid] = sj;
        }

        const uint32_t mB = sb + (uint32_t)(SMB + (a & 1) * MBUF_STRIDE);
        char* mbN = smc + SMB + ((a + 1) & 1) * MBUF_STRIDE;
        const float* savN = savbuf + ((a + 1) & 1) * 128;
        const bool doBuild = (a + 1 < cnt);

        float acc[2][4][4];
#pragma unroll
        for (int mt = 0; mt < 2; mt++)
#pragma unroll
            for (int nt = 0; nt < 4; nt++)
#pragma unroll
                for (int e = 0; e < 4; e++) acc[mt][nt][e] = 0.f;

#pragma unroll
        for (int ks = 0; ks < 8; ks++) {
            const uint32_t pan = (uint32_t)((ks >> 2) << 14);
            const uint32_t ao = pan + alow[ks & 3];
            const uint32_t kstep = (uint32_t)(ks * 2048);
            uint32_t aH[2][4], aL[2][4], bH[2][4], bL[2][4];
            ldsm_x4(aH[0], aBase + SA_HI + ao);
            ldsm_x4(aH[1], aBase + SA_HI + 2048 + ao);
            ldsm_x4(aL[0], aBase + SA_LO + ao);
            ldsm_x4(aL[1], aBase + SA_LO + 2048 + ao);
            ldsm_x4_t(bH[0], mB + bB0 + kstep);
            ldsm_x4_t(bH[1], mB + bB1 + kstep);
            ldsm_x4_t(bL[0], mB + 32768 + bB0 + kstep);
            ldsm_x4_t(bL[1], mB + 32768 + bB1 + kstep);
#pragma unroll
            for (int mt = 0; mt < 2; mt++) {
#pragma unroll
                for (int ng = 0; ng < 2; ng++) {
                    mma_f16(acc[mt][2 * ng], aH[mt], bH[ng]);
                    mma_f16(acc[mt][2 * ng + 1], aH[mt], bH[ng] + 2);
                    mma_f16(acc[mt][2 * ng], aH[mt], bL[ng]);
                    mma_f16(acc[mt][2 * ng + 1], aH[mt], bL[ng] + 2);
                    mma_f16(acc[mt][2 * ng], aL[mt], bH[ng]);
                    mma_f16(acc[mt][2 * ng + 1], aL[mt], bH[ng] + 2);
                }
            }
            if (doBuild && (ks & 1) == 0)
                build_oct_t(mbN, Wi, savN, t + ((ks >> 1) << 9));
        }

        float* pebB = (float*)(smc + SPE + (a & 1) * 4096);
        float* pgbB = pebB + 512;
        float pe[4] = {0.f, 0.f, 0.f, 0.f}, pg[4] = {0.f, 0.f, 0.f, 0.f};
#pragma unroll
        for (int nt = 0; nt < 4; nt++) {
#pragma unroll
            for (int c = 0; c < 2; c++) {
                const int h = h0 + 8 * nt + 2 * (lane & 3) + c;
                const float wpeh = cv[h];
                const float wpgh = cv[128 + h];
                const float bih = cv[256 + h];
#pragma unroll
                for (int mt = 0; mt < 2; mt++) {
#pragma unroll
                    for (int hf = 0; hf < 2; hf++) {
                        float v = acc[mt][nt][hf * 2 + c] * SCALE_INV + bih;
                        v = (v > 0.f) ? v : 0.01f * v;
                        pe[mt * 2 + hf] += v * wpeh;
                        pg[mt * 2 + hf] += v * wpgh;
                    }
                }
            }
        }
#pragma unroll
        for (int rs = 0; rs < 4; rs++) {
#pragma unroll
            for (int off = 1; off < 4; off <<= 1) {
                pe[rs] += __shfl_xor_sync(0xffffffffu, pe[rs], off);
                pg[rs] += __shfl_xor_sync(0xffffffffu, pg[rs], off);
            }
        }
        if ((lane & 3) == 0) {
            const int wx = wid >> 2;
#pragma unroll
            for (int mt = 0; mt < 2; mt++)
#pragma unroll
                for (int hf = 0; hf < 2; hf++) {
                    int j = j0 + 16 * mt + 8 * hf + (lane >> 2);
                    pebB[wx * 128 + j] = pe[mt * 2 + hf];
                    pgbB[wx * 128 + j] = pg[mt * 2 + hf];
                }
        }
        if (lane >= 24 && a + 2 < cnt) {
            const int idx = (wid << 3) + (lane - 24);
            savbuf[(a & 1) * 128 + idx] = atomBase[(a + 2) * 128 + idx] * SCALE_B;
        }
        __syncthreads();   // the ONLY barrier per atom
    }

    // ---- drain the reduction pipeline ----
    if (cnt >= 2 && wid == 0) {
        float v = (lane < 16) ? redb[((cnt - 2) & 1) * 16 + lane] : 0.f;
#pragma unroll
        for (int off = 8; off > 0; off >>= 1)
            v += __shfl_down_sync(0xffffffffu, v, off);
        if (lane == 0) g_atom_e[n * 1024 + i0 + cnt - 2] = v;
    }
    if (lane < 8) {
        const int bsel = (cnt - 1) & 1;
        const float* pebR = (const float*)(smc + SPE + bsel * 4096);
        const float* pgbR = pebR + 512;
        const int j = (wid << 3) + lane;
        float spe = pebR[j] + pebR[128 + j] + pebR[256 + j] + pebR[384 + j] + bpe0;
        float spg = pgbR[j] + pgbR[128 + j] + pgbR[256 + j] + pgbR[384 + j] + bpg0;
        float sj = spe / (1.f + __expf(-spg));
#pragma unroll
        for (int off = 4; off > 0; off >>= 1)
            sj += __shfl_down_sync(0x000000ffu, sj, off);
        if (lane == 0) redb[bsel * 16 + wid] = sj;
    }
    __syncthreads();
    if (wid == 0) {
        float v = (lane < 16) ? redb[((cnt - 1) & 1) * 16 + lane] : 0.f;
#pragma unroll
        for (int off = 8; off > 0; off >>= 1)
            v += __shfl_down_sync(0xffffffffu, v, off);
        if (lane == 0) g_atom_e[n * 1024 + i0 + cnt - 1] = v;
    }
}

// ------------------------------ k_final (light) -----------------------------
__global__ void k_final(const float* __restrict__ lgr, const int* __restrict__ lb,
                        const float* __restrict__ Wgr, const float* __restrict__ bgr,
                        const float* __restrict__ Wb1, const float* __restrict__ bb1,
                        const float* __restrict__ Wb2, const float* __restrict__ bb2,
                        float* __restrict__ out) {
    int n = blockIdx.x >> 6, g = blockIdx.x & 63, t = threadIdx.x;
    __shared__ float lg[64];
    __shared__ float gfs[128];
    __shared__ float red[8];
    if (t < 64) lg[t] = lgr[(n * 64 + g) * 64 + t];
    __syncthreads();
    float gf = bgr[t];
#pragma unroll 4
    for (int c = 0; c < 64; c++) gf += lg[c] * Wgr[c * 128 + t];
    gfs[t] = gf;
    __syncthreads();
    float h = g_hpf[n * 128 + t] + bb1[t];
    const float* Wb1b = Wb1 + 128 * 128;   // bottom half: rows 128..255
#pragma unroll 4
    for (int c = 0; c < 128; c++) h += gfs[c] * Wb1b[c * 128 + t];
    h = (h > 0.f) ? h : 0.01f * h;
    float part = h * Wb2[t];
    float seg = 0.f;
    for (int a = t; a < 1024; a += 128) {
        if (lb[a] == g) seg += g_atom_e[n * 1024 + a];
    }
#pragma unroll
    for (int off = 16; off > 0; off >>= 1) {
        part += __shfl_down_sync(0xffffffffu, part, off);
        seg += __shfl_down_sync(0xffffffffu, seg, off);
    }
    int wid = t >> 5;
    if ((t & 31) == 0) {
        red[wid] = part;
        red[4 + wid] = seg;
    }
    __syncthreads();
    if (t == 0) {
        float bias = red[0] + red[1] + red[2] + red[3] + bb2[0];
        float segs = red[4] + red[5] + red[6] + red[7];
        out[n * 64 + g] = segs + bias;
    }
}

// ------------------------------ launch --------------------------------------
extern "C" void kernel_launch(void* const* d_in, const int* in_sizes, int n_in,
                              void* d_out, int out_size) {
    const float* ms0 = (const float*)d_in[0];
    const float* ms1 = (const float*)d_in[1];
    const float* tf = (const float*)d_in[2];
    const float* lat = (const float*)d_in[3];
    const float* lgr = (const float*)d_in[4];
    const int* lb = (const int*)d_in[5];
    const float* Wt = (const float*)d_in[6];
    const float* bt = (const float*)d_in[7];
    const float* Wc0 = (const float*)d_in[8];
    const float* bc0 = (const float*)d_in[9];
    const float* Wc1 = (const float*)d_in[10];
    const float* bc1 = (const float*)d_in[11];
    const float* Wp = (const float*)d_in[12];
    const float* bp = (const float*)d_in[13];
    const float* Wcat = (const float*)d_in[14];
    const float* bcat = (const float*)d_in[15];
    const float* Wgate = (const float*)d_in[16];
    const float* bgate = (const float*)d_in[17];
    const float* Wa = (const float*)d_in[18];
    const float* ba = (const float*)d_in[19];
    const float* Wgr = (const float*)d_in[20];
    const float* bgr = (const float*)d_in[21];
    const float* Wb1 = (const float*)d_in[22];
    const float* bb1 = (const float*)d_in[23];
    const float* Wb2 = (const float*)d_in[24];
    const float* bb2 = (const float*)d_in[25];
    const float* Wi = (const float*)d_in[26];
    const float* bi = (const float*)d_in[27];
    const float* wpe = (const float*)d_in[28];
    const float* bpe = (const float*)d_in[29];
    const float* wpg = (const float*)d_in[30];
    const float* bpg = (const float*)d_in[31];
    float* out = (float*)d_out;

    static cudaStream_t s2 = nullptr;
    static cudaEvent_t evFork = nullptr, evTok = nullptr, evJoin = nullptr;
    if (s2 == nullptr) {
        cudaStreamCreateWithFlags(&s2, cudaStreamNonBlocking);
        cudaEventCreateWithFlags(&evFork, cudaEventDisableTiming);
        cudaEventCreateWithFlags(&evTok, cudaEventDisableTiming);
        cudaEventCreateWithFlags(&evJoin, cudaEventDisableTiming);
        cudaFuncSetAttribute(k_inter, cudaFuncAttributeMaxDynamicSharedMemorySize,
                             SMEM_TC_BYTES);
    }

    // fork: side stream does pocket branch (independent of tok/atoms)
    cudaEventRecord(evFork, 0);
    cudaStreamWaitEvent(s2, evFork, 0);
    k_ms<<<384, 256, 0, s2>>>(ms1, ms0);
    k_pconv<<<128, 256, 0, s2>>>(Wc0, bc0, Wc1, bc1);

    // main: tok+atoms, then signal tok availability for k_pf
    k_tokatoms<<<576, 128>>>(tf, Wt, bt, lat, Wa, ba);
    cudaEventRecord(evTok, 0);
    cudaStreamWaitEvent(s2, evTok, 0);
    // side: pf + hpf runs under k_inter
    k_pf<<<4, 128, 0, s2>>>(Wp, bp, Wcat, bcat, Wgate, bgate, Wb1);

    k_inter<<<148, 512, SMEM_TC_BYTES>>>(Wi, bi, wpe, bpe, wpg, bpg);

    // join, then the light output head
    cudaEventRecord(evJoin, s2);
    cudaStreamWaitEvent(0, evJoin, 0);
    k_final<<<256, 128>>>(lgr, lb, Wgr, bgr, Wb1, bb1, Wb2, bb2, out);
}

// round 17
// speedup vs baseline: 1.6961x; 1.2254x over previous
#include <cuda_runtime.h>
#include <cuda_fp16.h>
#include <cstdint>

// ---------------------------------------------------------------------------
// AffinityHead — mma.sync fp16 split GEMM core, R17: 2-term split.
//   A = tok: fp16 hi+lo planes (error ~2^-22)
//   B = diag(a)W: single RN fp16 plane (error ~2^-12) -> 16 HMMA + 6 ldsm
//   per k-step (was 24 + 8), M-build halves, smem 207KB -> 142KB.
// Everything else (1-barrier pipeline, pipelined reduce, stream fork/join,
// R16 small kernels) unchanged.
// ---------------------------------------------------------------------------

__device__ __forceinline__ float silu_f(float v) { return v / (1.f + __expf(-v)); }

// ------------------------- scratch (static, no allocs) ---------------------
__device__ float g_tok[4 * 128 * 128];     // [n][j][h]
__device__ float g_S1[4 * 64 * 27];
__device__ float g_S0[4 * 32 * 27];
__device__ float g_p[4 * 256];
__device__ float g_pf[4 * 128];
__device__ float g_hpf[4 * 128];           // pf . Wb1_top (pre-activation)
__device__ float g_atoms[4 * 1024 * 128];  // [n][i][k]
__device__ float g_atom_e[4 * 1024];

// ------------------------------ PTX helpers --------------------------------
__device__ __forceinline__ uint32_t smem_to_u32(const void* p) {
    uint32_t a;
    asm("{ .reg .u64 t; cvta.to.shared.u64 t, %1; cvt.u32.u64 %0, t; }" : "=r"(a) : "l"(p));
    return a;
}

__device__ __forceinline__ void ldsm_x4(uint32_t* r, uint32_t addr) {
    asm volatile("ldmatrix.sync.aligned.m8n8.x4.shared.b16 {%0,%1,%2,%3}, [%4];"
                 : "=r"(r[0]), "=r"(r[1]), "=r"(r[2]), "=r"(r[3]) : "r"(addr));
}

__device__ __forceinline__ void ldsm_x4_t(uint32_t* r, uint32_t addr) {
    asm volatile("ldmatrix.sync.aligned.m8n8.x4.trans.shared.b16 {%0,%1,%2,%3}, [%4];"
                 : "=r"(r[0]), "=r"(r[1]), "=r"(r[2]), "=r"(r[3]) : "r"(addr));
}

__device__ __forceinline__ void mma_f16(float* d, const uint32_t* a, const uint32_t* b) {
    asm volatile(
        "mma.sync.aligned.m16n8k16.row.col.f32.f16.f16.f32 "
        "{%0,%1,%2,%3}, {%4,%5,%6,%7}, {%8,%9}, {%0,%1,%2,%3};"
        : "+f"(d[0]), "+f"(d[1]), "+f"(d[2]), "+f"(d[3])
        : "r"(a[0]), "r"(a[1]), "r"(a[2]), "r"(a[3]), "r"(b[0]), "r"(b[1]));
}

// SW128 blocked-atom swizzled byte offset for a [128 rows][128 halves] plane.
__device__ __forceinline__ uint32_t swz(int row, int k) {
    uint32_t off = (uint32_t)(((k >> 6) << 14) + ((row >> 3) << 10) +
                              ((row & 7) << 7) + ((k & 63) << 1));
    return off ^ (uint32_t)((row & 7) << 4);
}

// ------------------------------ k_tokatoms ----------------------------------
__global__ void k_tokatoms(const float* __restrict__ tf, const float* __restrict__ Wt,
                           const float* __restrict__ bt, const float* __restrict__ la,
                           const float* __restrict__ Wa, const float* __restrict__ ba) {
    __shared__ float s[2048];
    const int t = threadIdx.x;
    if (blockIdx.x < 64) {
        const int r0 = blockIdx.x * 8;
        for (int i = t; i < 2048; i += 128) s[i] = silu_f(tf[r0 * 256 + i]);
        __syncthreads();
        float b = bt[t];
        float acc[8];
#pragma unroll
        for (int r = 0; r < 8; r++) acc[r] = b;
        for (int c = 0; c < 256; c++) {
            float w = Wt[c * 128 + t];
#pragma unroll
            for (int r = 0; r < 8; r++) acc[r] += s[(r << 8) + c] * w;
        }
#pragma unroll
        for (int r = 0; r < 8; r++) g_tok[(r0 + r) * 128 + t] = acc[r];
    } else {
        const int r0 = (blockIdx.x - 64) * 8;
        for (int i = t; i < 512; i += 128) s[i] = la[r0 * 64 + i];
        __syncthreads();
        float b = ba[t];
        float acc[8];
#pragma unroll
        for (int r = 0; r < 8; r++) acc[r] = b;
        for (int c = 0; c < 64; c++) {
            float w = Wa[c * 128 + t];
#pragma unroll
            for (int r = 0; r < 8; r++) acc[r] += s[(r << 6) + c] * w;
        }
#pragma unroll
        for (int r = 0; r < 8; r++) g_atoms[(r0 + r) * 128 + t] = acc[r];
    }
}

// ------------------------------ k_ms (S1 + S0) ------------------------------
__global__ void __launch_bounds__(256, 8)
k_ms(const float* __restrict__ ms1, const float* __restrict__ ms0) {
    __shared__ float v[4096];
    const int t = threadIdx.x;
    const int w = t >> 5, lane = t & 31;
    const int b = blockIdx.x;
    if (b < 256) {
        for (int i = t; i < 512; i += 256) v[i] = silu_f(ms1[b * 512 + i]);
        __syncthreads();
        for (int k = w; k < 27; k += 8) {
            int kd = k / 9, kh = (k / 3) % 3, kw = k % 3;
            float s = 0.f;
            for (int i = lane; i < 216; i += 32) {
                int d = i / 36, r = i % 36, hh = r / 6, ww = r % 6;
                s += v[(d + kd) * 64 + (hh + kh) * 8 + (ww + kw)];
            }
#pragma unroll
            for (int off = 16; off > 0; off >>= 1)
                s += __shfl_down_sync(0xffffffffu, s, off);
            if (lane == 0) g_S1[b * 27 + k] = s;
        }
    } else {
        const int nc = b - 256;
        for (int i = t; i < 4096; i += 256) v[i] = silu_f(ms0[nc * 4096 + i]);
        __syncthreads();
        for (int k = w; k < 27; k += 8) {
            int kd = k / 9, kh = (k / 3) % 3, kw = k % 3;
            float s = 0.f;
            for (int i = lane; i < 2744; i += 32) {
                int d = i / 196, r = i % 196, hh = r / 14, ww = r % 14;
                s += v[(d + kd) * 256 + (hh + kh) * 16 + (ww + kw)];
            }
#pragma unroll
            for (int off = 16; off > 0; off >>= 1)
                s += __shfl_down_sync(0xffffffffu, s, off);
            if (lane == 0) g_S0[nc * 27 + k] = s;
        }
    }
}

// ------------------------------ k_pconv (warp-per-output) -------------------
__global__ void __launch_bounds__(256, 8)
k_pconv(const float* __restrict__ Wc0, const float* __restrict__ bc0,
        const float* __restrict__ Wc1, const float* __restrict__ bc1) {
    __shared__ float s[1728];
    const int t = threadIdx.x, w = t >> 5, lane = t & 31;
    int b = blockIdx.x;   // 128 blocks x 256 threads
    if (b < 64) {
        int n = b >> 4, o = (b & 15) * 8 + w;
        for (int i = t; i < 1728; i += 256) s[i] = g_S1[n * 1728 + i];
        __syncthreads();
        float a = 0.f;
        for (int x = lane; x < 1728; x += 32) a += s[x] * Wc0[o * 1728 + x];
#pragma unroll
        for (int off = 16; off > 0; off >>= 1)
            a += __shfl_down_sync(0xffffffffu, a, off);
        if (lane == 0) g_p[n * 256 + o] = a * (1.f / 216.f) + bc0[o];
    } else {
        b -= 64;
        int n = b >> 4, o = (b & 15) * 8 + w;
        for (int i = t; i < 864; i += 256) s[i] = g_S0[n * 864 + i];
        __syncthreads();
        float a = 0.f;
        for (int x = lane; x < 864; x += 32) a += s[x] * Wc1[o * 864 + x];
#pragma unroll
        for (int off = 16; off > 0; off >>= 1)
            a += __shfl_down_sync(0xffffffffu, a, off);
        if (lane == 0) g_p[n * 256 + 128 + o] = a * (1.f / 2744.f) + bc1[o];
    }
}

// ------------------------------ k_pf (per image, side stream) ---------------
__global__ void __launch_bounds__(128, 8)
k_pf(const float* __restrict__ Wp, const float* __restrict__ bp,
     const float* __restrict__ Wcat, const float* __restrict__ bcat,
     const float* __restrict__ Wgate, const float* __restrict__ bgate,
     const float* __restrict__ Wb1) {
    const int n = blockIdx.x, t = threadIdx.x;
    __shared__ float sp[256];
    __shared__ float pin[384];
    __shared__ float pfs[128];
    for (int c = t; c < 256; c += 128) sp[c] = silu_f(g_p[n * 256 + c]);
    float ts = 0.f;
    for (int j = 0; j < 128; j++) ts += g_tok[(n * 128 + j) * 128 + t];
    __syncthreads();
    float pk = bp[t];
#pragma unroll 4
    for (int c = 0; c < 256; c++) pk += sp[c] * Wp[c * 128 + t];
    pin[t] = pk;
    pin[128 + t] = ts;
    pin[256 + t] = ts * (1.f / 128.f);
    __syncthreads();
    float c1 = bcat[t], g1 = bgate[t];
#pragma unroll 4
    for (int c = 0; c < 384; c++) {
        float zz = pin[c];
        c1 += zz * Wcat[c * 128 + t];
        g1 += zz * Wgate[c * 128 + t];
    }
    float pf = c1 / (1.f + __expf(-g1));
    pfs[t] = pf;
    g_pf[n * 128 + t] = pf;
    __syncthreads();
    float hp = 0.f;
#pragma unroll 4
    for (int c = 0; c < 128; c++) hp += pfs[c] * Wb1[c * 128 + t];
    g_hpf[n * 128 + t] = hp;
}

// ------------------------------ k_inter (2-term) ----------------------------
// smem: A hi/lo (32768 each) | M buf0 (32768) | M buf1 (32768) | cv | pe/pg x2
//       | red x2 | sav x2
#define SA_HI 0
#define SA_LO 32768
#define SMB 65536
#define MBUF_STRIDE 32768     // single (hi-only) plane per buffer
#define SCV 131072            // wpe|wpg|bi : 1536
#define SPE 132608            // 2 x (peb[4][128] | pgb[4][128]) : 8192
#define SRED 140800           // [2][16] : 128
#define SSAV 140928           // [2][128] : 1024
#define SMEM_TC_BYTES 141952

#define SCALE_A 16.f
#define SCALE_B 256.f
#define SCALE_INV (1.f / 4096.f)

// Build one octet (8 h-values at one k) of M = diag(sav)*W, RN fp16 hi only.
__device__ __forceinline__ void build_oct_t(char* mb, const float* __restrict__ Wi,
                                            const float* __restrict__ sav, int p) {
    const int k = p >> 4, h0 = (p & 15) << 3;
    const float s = sav[k];
    const float4* wp = (const float4*)(Wi + k * 128 + h0);
    const float4 w0 = wp[0], w1 = wp[1];
    uint32_t hi[4];
    __half2 h01 = __float22half2_rn(make_float2(s * w0.x, s * w0.y));
    __half2 h23 = __float22half2_rn(make_float2(s * w0.z, s * w0.w));
    __half2 h45 = __float22half2_rn(make_float2(s * w1.x, s * w1.y));
    __half2 h67 = __float22half2_rn(make_float2(s * w1.z, s * w1.w));
    hi[0] = *(uint32_t*)&h01;
    hi[1] = *(uint32_t*)&h23;
    hi[2] = *(uint32_t*)&h45;
    hi[3] = *(uint32_t*)&h67;
    const uint32_t o = swz(k, h0);
    *(uint4*)(mb + o) = make_uint4(hi[0], hi[1], hi[2], hi[3]);
}

__global__ void __launch_bounds__(512, 1)
k_inter(const float* __restrict__ Wi, const float* __restrict__ bi,
        const float* __restrict__ wpe, const float* __restrict__ bpe,
        const float* __restrict__ wpg, const float* __restrict__ bpg) {
    extern __shared__ char smc[];
    const uint32_t sb = smem_to_u32(smc);
    float* cv = (float*)(smc + SCV);
    float* redb = (float*)(smc + SRED);      // [2][16]
    float* savbuf = (float*)(smc + SSAV);    // [2][128], pre-scaled by SCALE_B

    const int t = threadIdx.x;
    const int wid = t >> 5;
    const int lane = t & 31;

    const int n = blockIdx.x / 37;
    const int grp = blockIdx.x % 37;
    const int i0 = grp * 28;
    const int cnt = min(28, 1024 - i0);
    const float* atomBase = g_atoms + (n * 1024 + i0) * 128;
    const float bpe0 = bpe[0], bpg0 = bpg[0];

    if (t < 128) {
        cv[t] = wpe[t];
        cv[128 + t] = wpg[t];
        cv[256 + t] = bi[t];
        savbuf[t] = atomBase[t] * SCALE_B;
    } else if (t < 256) {
        savbuf[128 + (t - 128)] = atomBase[128 + (t - 128)] * SCALE_B;
    }
    __syncthreads();

    const float* tokn = g_tok + n * 16384;
    for (int p = t; p < 2048; p += 512) {
        int j = p >> 4, k0 = (p & 15) << 3;
        const float4* xp = (const float4*)(tokn + j * 128 + k0);
        float4 x0 = xp[0], x1 = xp[1];
        float v[8];
        v[0] = x0.x * SCALE_A; v[1] = x0.y * SCALE_A;
        v[2] = x0.z * SCALE_A; v[3] = x0.w * SCALE_A;
        v[4] = x1.x * SCALE_A; v[5] = x1.y * SCALE_A;
        v[6] = x1.z * SCALE_A; v[7] = x1.w * SCALE_A;
        uint32_t hi[4], lo[4];
#pragma unroll
        for (int q = 0; q < 4; q++) {
            __half2 hh = __float22half2_rn(make_float2(v[2 * q], v[2 * q + 1]));
            __half2 ll = __float22half2_rn(make_float2(v[2 * q] - __low2float(hh),
                                                       v[2 * q + 1] - __high2float(hh)));
            hi[q] = *(uint32_t*)&hh;
            lo[q] = *(uint32_t*)&ll;
        }
        uint32_t o = swz(j, k0);
        *(uint4*)(smc + SA_HI + o) = make_uint4(hi[0], hi[1], hi[2], hi[3]);
        *(uint4*)(smc + SA_LO + o) = make_uint4(lo[0], lo[1], lo[2], lo[3]);
    }
    for (int p = t; p < 2048; p += 512) build_oct_t(smc + SMB, Wi, savbuf, p);
    __syncthreads();

    const int j0 = (wid & 3) * 32;
    const int h0 = (wid >> 2) * 32;
    const int aRowG = j0 + (lane & 15);
    const uint32_t kbA = (uint32_t)(((lane >> 4) << 3) << 1);
    const uint32_t aXor = (uint32_t)((aRowG & 7) << 4);
    const uint32_t aBase = sb + (uint32_t)(((aRowG >> 3) << 10) + ((aRowG & 7) << 7));
    uint32_t alow[4];
#pragma unroll
    for (int c = 0; c < 4; c++) alow[c] = (((uint32_t)c << 5) + kbA) ^ aXor;
    const int bk = (lane & 7) + (((lane >> 3) & 1) << 3);
    const int bh = h0 + ((lane >> 4) << 3);
    const uint32_t bB0 = swz(bk, bh);
    const uint32_t bB1 = swz(bk, bh + 16);

    for (int a = 0; a < cnt; a++) {
        if (a >= 2 && wid == 0) {
            float v = (lane < 16) ? redb[((a - 2) & 1) * 16 + lane] : 0.f;
#pragma unroll
            for (int off = 8; off > 0; off >>= 1)
                v += __shfl_down_sync(0xffffffffu, v, off);
            if (lane == 0) g_atom_e[n * 1024 + i0 + a - 2] = v;
        }
        if (a >= 1 && lane < 8) {
            const int bsel = (a - 1) & 1;
            const float* pebR = (const float*)(smc + SPE + bsel * 4096);
            const float* pgbR = pebR + 512;
            const int j = (wid << 3) + lane;
            float spe = pebR[j] + pebR[128 + j] + pebR[256 + j] + pebR[384 + j] + bpe0;
            float spg = pgbR[j] + pgbR[128 + j] + pgbR[256 + j] + pgbR[384 + j] + bpg0;
            float sj = spe / (1.f + __expf(-spg));
#pragma unroll
            for (int off = 4; off > 0; off >>= 1)
                sj += __shfl_down_sync(0x000000ffu, sj, off);
            if (lane == 0) redb[bsel * 16 + wid] = sj;
        }

        const uint32_t mB = sb + (uint32_t)(SMB + (a & 1) * MBUF_STRIDE);
        char* mbN = smc + SMB + ((a + 1) & 1) * MBUF_STRIDE;
        const float* savN = savbuf + ((a + 1) & 1) * 128;
        const bool doBuild = (a + 1 < cnt);

        float acc[2][4][4];
#pragma unroll
        for (int mt = 0; mt < 2; mt++)
#pragma unroll
            for (int nt = 0; nt < 4; nt++)
#pragma unroll
                for (int e = 0; e < 4; e++) acc[mt][nt][e] = 0.f;

#pragma unroll
        for (int ks = 0; ks < 8; ks++) {
            const uint32_t pan = (uint32_t)((ks >> 2) << 14);
            const uint32_t ao = pan + alow[ks & 3];
            const uint32_t kstep = (uint32_t)(ks * 2048);
            uint32_t aH[2][4], aL[2][4], bH[2][4];
            ldsm_x4(aH[0], aBase + SA_HI + ao);
            ldsm_x4(aH[1], aBase + SA_HI + 2048 + ao);
            ldsm_x4(aL[0], aBase + SA_LO + ao);
            ldsm_x4(aL[1], aBase + SA_LO + 2048 + ao);
            ldsm_x4_t(bH[0], mB + bB0 + kstep);
            ldsm_x4_t(bH[1], mB + bB1 + kstep);
#pragma unroll
            for (int mt = 0; mt < 2; mt++) {
#pragma unroll
                for (int ng = 0; ng < 2; ng++) {
                    mma_f16(acc[mt][2 * ng], aH[mt], bH[ng]);
                    mma_f16(acc[mt][2 * ng + 1], aH[mt], bH[ng] + 2);
                    mma_f16(acc[mt][2 * ng], aL[mt], bH[ng]);
                    mma_f16(acc[mt][2 * ng + 1], aL[mt], bH[ng] + 2);
                }
            }
            if (doBuild && (ks & 1) == 0)
                build_oct_t(mbN, Wi, savN, t + ((ks >> 1) << 9));
        }

        float* pebB = (float*)(smc + SPE + (a & 1) * 4096);
        float* pgbB = pebB + 512;
        float pe[4] = {0.f, 0.f, 0.f, 0.f}, pg[4] = {0.f, 0.f, 0.f, 0.f};
#pragma unroll
        for (int nt = 0; nt < 4; nt++) {
#pragma unroll
            for (int c = 0; c < 2; c++) {
                const int h = h0 + 8 * nt + 2 * (lane & 3) + c;
                const float wpeh = cv[h];
                const float wpgh = cv[128 + h];
                const float bih = cv[256 + h];
#pragma unroll
                for (int mt = 0; mt < 2; mt++) {
#pragma unroll
                    for (int hf = 0; hf < 2; hf++) {
                        float v = acc[mt][nt][hf * 2 + c] * SCALE_INV + bih;
                        v = (v > 0.f) ? v : 0.01f * v;
                        pe[mt * 2 + hf] += v * wpeh;
                        pg[mt * 2 + hf] += v * wpgh;
                    }
                }
            }
        }
#pragma unroll
        for (int rs = 0; rs < 4; rs++) {
#pragma unroll
            for (int off = 1; off < 4; off <<= 1) {
                pe[rs] += __shfl_xor_sync(0xffffffffu, pe[rs], off);
                pg[rs] += __shfl_xor_sync(0xffffffffu, pg[rs], off);
            }
        }
        if ((lane & 3) == 0) {
            const int wx = wid >> 2;
#pragma unroll
            for (int mt = 0; mt < 2; mt++)
#pragma unroll
                for (int hf = 0; hf < 2; hf++) {
                    int j = j0 + 16 * mt + 8 * hf + (lane >> 2);
                    pebB[wx * 128 + j] = pe[mt * 2 + hf];
                    pgbB[wx * 128 + j] = pg[mt * 2 + hf];
                }
        }
        if (lane >= 24 && a + 2 < cnt) {
            const int idx = (wid << 3) + (lane - 24);
            savbuf[(a & 1) * 128 + idx] = atomBase[(a + 2) * 128 + idx] * SCALE_B;
        }
        __syncthreads();   // the ONLY barrier per atom
    }

    // ---- drain the reduction pipeline ----
    if (cnt >= 2 && wid == 0) {
        float v = (lane < 16) ? redb[((cnt - 2) & 1) * 16 + lane] : 0.f;
#pragma unroll
        for (int off = 8; off > 0; off >>= 1)
            v += __shfl_down_sync(0xffffffffu, v, off);
        if (lane == 0) g_atom_e[n * 1024 + i0 + cnt - 2] = v;
    }
    if (lane < 8) {
        const int bsel = (cnt - 1) & 1;
        const float* pebR = (const float*)(smc + SPE + bsel * 4096);
        const float* pgbR = pebR + 512;
        const int j = (wid << 3) + lane;
        float spe = pebR[j] + pebR[128 + j] + pebR[256 + j] + pebR[384 + j] + bpe0;
        float spg = pgbR[j] + pgbR[128 + j] + pgbR[256 + j] + pgbR[384 + j] + bpg0;
        float sj = spe / (1.f + __expf(-spg));
#pragma unroll
        for (int off = 4; off > 0; off >>= 1)
            sj += __shfl_down_sync(0x000000ffu, sj, off);
        if (lane == 0) redb[bsel * 16 + wid] = sj;
    }
    __syncthreads();
    if (wid == 0) {
        float v = (lane < 16) ? redb[((cnt - 1) & 1) * 16 + lane] : 0.f;
#pragma unroll
        for (int off = 8; off > 0; off >>= 1)
            v += __shfl_down_sync(0xffffffffu, v, off);
        if (lane == 0) g_atom_e[n * 1024 + i0 + cnt - 1] = v;
    }
}

// ------------------------------ k_final (light) -----------------------------
__global__ void k_final(const float* __restrict__ lgr, const int* __restrict__ lb,
                        const float* __restrict__ Wgr, const float* __restrict__ bgr,
                        const float* __restrict__ Wb1, const float* __restrict__ bb1,
                        const float* __restrict__ Wb2, const float* __restrict__ bb2,
                        float* __restrict__ out) {
    int n = blockIdx.x >> 6, g = blockIdx.x & 63, t = threadIdx.x;
    __shared__ float lg[64];
    __shared__ float gfs[128];
    __shared__ float red[8];
    if (t < 64) lg[t] = lgr[(n * 64 + g) * 64 + t];
    __syncthreads();
    float gf = bgr[t];
#pragma unroll 4
    for (int c = 0; c < 64; c++) gf += lg[c] * Wgr[c * 128 + t];
    gfs[t] = gf;
    __syncthreads();
    float h = g_hpf[n * 128 + t] + bb1[t];
    const float* Wb1b = Wb1 + 128 * 128;   // bottom half: rows 128..255
#pragma unroll 4
    for (int c = 0; c < 128; c++) h += gfs[c] * Wb1b[c * 128 + t];
    h = (h > 0.f) ? h : 0.01f * h;
    float part = h * Wb2[t];
    float seg = 0.f;
    for (int a = t; a < 1024; a += 128) {
        if (lb[a] == g) seg += g_atom_e[n * 1024 + a];
    }
#pragma unroll
    for (int off = 16; off > 0; off >>= 1) {
        part += __shfl_down_sync(0xffffffffu, part, off);
        seg += __shfl_down_sync(0xffffffffu, seg, off);
    }
    int wid = t >> 5;
    if ((t & 31) == 0) {
        red[wid] = part;
        red[4 + wid] = seg;
    }
    __syncthreads();
    if (t == 0) {
        float bias = red[0] + red[1] + red[2] + red[3] + bb2[0];
        float segs = red[4] + red[5] + red[6] + red[7];
        out[n * 64 + g] = segs + bias;
    }
}

// ------------------------------ launch --------------------------------------
extern "C" void kernel_launch(void* const* d_in, const int* in_sizes, int n_in,
                              void* d_out, int out_size) {
    const float* ms0 = (const float*)d_in[0];
    const float* ms1 = (const float*)d_in[1];
    const float* tf = (const float*)d_in[2];
    const float* lat = (const float*)d_in[3];
    const float* lgr = (const float*)d_in[4];
    const int* lb = (const int*)d_in[5];
    const float* Wt = (const float*)d_in[6];
    const float* bt = (const float*)d_in[7];
    const float* Wc0 = (const float*)d_in[8];
    const float* bc0 = (const float*)d_in[9];
    const float* Wc1 = (const float*)d_in[10];
    const float* bc1 = (const float*)d_in[11];
    const float* Wp = (const float*)d_in[12];
    const float* bp = (const float*)d_in[13];
    const float* Wcat = (const float*)d_in[14];
    const float* bcat = (const float*)d_in[15];
    const float* Wgate = (const float*)d_in[16];
    const float* bgate = (const float*)d_in[17];
    const float* Wa = (const float*)d_in[18];
    const float* ba = (const float*)d_in[19];
    const float* Wgr = (const float*)d_in[20];
    const float* bgr = (const float*)d_in[21];
    const float* Wb1 = (const float*)d_in[22];
    const float* bb1 = (const float*)d_in[23];
    const float* Wb2 = (const float*)d_in[24];
    const float* bb2 = (const float*)d_in[25];
    const float* Wi = (const float*)d_in[26];
    const float* bi = (const float*)d_in[27];
    const float* wpe = (const float*)d_in[28];
    const float* bpe = (const float*)d_in[29];
    const float* wpg = (const float*)d_in[30];
    const float* bpg = (const float*)d_in[31];
    float* out = (float*)d_out;

    static cudaStream_t s2 = nullptr;
    static cudaEvent_t evFork = nullptr, evTok = nullptr, evJoin = nullptr;
    if (s2 == nullptr) {
        cudaStreamCreateWithFlags(&s2, cudaStreamNonBlocking);
        cudaEventCreateWithFlags(&evFork, cudaEventDisableTiming);
        cudaEventCreateWithFlags(&evTok, cudaEventDisableTiming);
        cudaEventCreateWithFlags(&evJoin, cudaEventDisableTiming);
        cudaFuncSetAttribute(k_inter, cudaFuncAttributeMaxDynamicSharedMemorySize,
                             SMEM_TC_BYTES);
    }

    // fork: side stream does pocket branch (independent of tok/atoms)
    cudaEventRecord(evFork, 0);
    cudaStreamWaitEvent(s2, evFork, 0);
    k_ms<<<384, 256, 0, s2>>>(ms1, ms0);
    k_pconv<<<128, 256, 0, s2>>>(Wc0, bc0, Wc1, bc1);

    // main: tok+atoms, then signal tok availability for k_pf
    k_tokatoms<<<576, 128>>>(tf, Wt, bt, lat, Wa, ba);
    cudaEventRecord(evTok, 0);
    cudaStreamWaitEvent(s2, evTok, 0);
    // side: pf + hpf runs under k_inter
    k_pf<<<4, 128, 0, s2>>>(Wp, bp, Wcat, bcat, Wgate, bgate, Wb1);

    k_inter<<<148, 512, SMEM_TC_BYTES>>>(Wi, bi, wpe, bpe, wpg, bpg);

    // join, then the light output head
    cudaEventRecord(evJoin, s2);
    cudaStreamWaitEvent(0, evJoin, 0);
    k_final<<<256, 128>>>(lgr, lb, Wgr, bgr, Wb1, bb1, Wb2, bb2, out);
}